// round 1
// baseline (speedup 1.0000x reference)
#include <cuda_runtime.h>
#include <math.h>

#define SEQ   2048
#define HID   3584
#define NH    28
#define NKV   4
#define HD    128
#define KVDIM 512   // NKV * HD

// ---------------- scratch (no allocations allowed) ----------------
__device__ float g_q[SEQ * HID];
__device__ float g_k[SEQ * KVDIM];
__device__ float g_v[SEQ * KVDIM];
__device__ float g_ctx[SEQ * HID];

// ---------------- GEMM: C[M,N] = A[M,K] @ W[N,K]^T + bias ----------------
// BM=BN=128, BK=16, 256 threads, 8x8 per-thread register tile.
__global__ __launch_bounds__(256) void gemm_nt(
    const float* __restrict__ A, const float* __restrict__ W,
    const float* __restrict__ bias, float* __restrict__ C,
    int M, int N, int K)
{
    __shared__ float As[16][132];   // [k][m], padded
    __shared__ float Ws[16][132];   // [k][n], padded

    const int tid = threadIdx.x;
    const int bm = blockIdx.y * 128;
    const int bn = blockIdx.x * 128;

    // load mapping: each thread loads 2 float4 of A and 2 float4 of W per BK-step
    const int lr = tid >> 2;          // 0..63 (row within tile)
    const int lk = (tid & 3) << 2;    // 0,4,8,12 (k offset)

    // compute mapping
    const int ty = tid >> 4, tx = tid & 15;
    const int rm = ty * 8, rn = tx * 8;

    float acc[8][8];
    #pragma unroll
    for (int i = 0; i < 8; i++)
        #pragma unroll
        for (int j = 0; j < 8; j++) acc[i][j] = 0.f;

    const float* Ab = A + (size_t)(bm + lr) * K + lk;
    const float* Wb = W + (size_t)(bn + lr) * K + lk;

    for (int kt = 0; kt < K; kt += 16) {
        float4 a0 = *(const float4*)(Ab + kt);
        float4 a1 = *(const float4*)(Ab + (size_t)64 * K + kt);
        float4 w0 = *(const float4*)(Wb + kt);
        float4 w1 = *(const float4*)(Wb + (size_t)64 * K + kt);

        As[lk + 0][lr] = a0.x; As[lk + 1][lr] = a0.y;
        As[lk + 2][lr] = a0.z; As[lk + 3][lr] = a0.w;
        As[lk + 0][lr + 64] = a1.x; As[lk + 1][lr + 64] = a1.y;
        As[lk + 2][lr + 64] = a1.z; As[lk + 3][lr + 64] = a1.w;

        Ws[lk + 0][lr] = w0.x; Ws[lk + 1][lr] = w0.y;
        Ws[lk + 2][lr] = w0.z; Ws[lk + 3][lr] = w0.w;
        Ws[lk + 0][lr + 64] = w1.x; Ws[lk + 1][lr + 64] = w1.y;
        Ws[lk + 2][lr + 64] = w1.z; Ws[lk + 3][lr + 64] = w1.w;

        __syncthreads();

        #pragma unroll
        for (int kk = 0; kk < 16; kk++) {
            float4 x0 = *(const float4*)&As[kk][rm];
            float4 x1 = *(const float4*)&As[kk][rm + 4];
            float4 y0 = *(const float4*)&Ws[kk][rn];
            float4 y1 = *(const float4*)&Ws[kk][rn + 4];
            float a[8] = {x0.x, x0.y, x0.z, x0.w, x1.x, x1.y, x1.z, x1.w};
            float b[8] = {y0.x, y0.y, y0.z, y0.w, y1.x, y1.y, y1.z, y1.w};
            #pragma unroll
            for (int i = 0; i < 8; i++)
                #pragma unroll
                for (int j = 0; j < 8; j++)
                    acc[i][j] += a[i] * b[j];
        }
        __syncthreads();
    }

    #pragma unroll
    for (int i = 0; i < 8; i++) {
        float* Cr = C + (size_t)(bm + rm + i) * N + bn + rn;
        #pragma unroll
        for (int j = 0; j < 8; j++) {
            float c = acc[i][j];
            if (bias) c += bias[bn + rn + j];
            Cr[j] = c;
        }
    }
}

// ---------------- RoPE (in-place), angles in double ----------------
__global__ void rope_kernel(float* __restrict__ x, int nheads)
{
    int idx = blockIdx.x * blockDim.x + threadIdx.x;   // SEQ*nheads*64 threads
    int half = idx & 63;
    int h = (idx >> 6) % nheads;
    int s = idx / (64 * nheads);

    double inv = pow(1.0e6, -(double)(2 * half) / 128.0);
    double ang = (double)s * inv;
    float c = (float)cos(ang);
    float si = (float)sin(ang);

    float* base = x + (size_t)s * nheads * HD + h * HD;
    float x1 = base[half];
    float x2 = base[half + 64];
    base[half]      = x1 * c - x2 * si;
    base[half + 64] = x2 * c + x1 * si;
}

// ---------------- Flash attention: 64q x 64k tiles, D=128 ----------------
// smem: Qt[128][68] + Kt[128][68] + Vs[64][132] + S[64][65] + stats
#define ATTN_SMEM_FLOATS (128*68 + 128*68 + 64*132 + 64*65 + 192)

__global__ __launch_bounds__(256) void attn_kernel(
    const float* __restrict__ q, const float* __restrict__ k,
    const float* __restrict__ v, float* __restrict__ ctx)
{
    extern __shared__ float sm[];
    float* Qt   = sm;                 // [k][row], stride 68
    float* Kt   = Qt + 128 * 68;      // [k][col], stride 68
    float* Vs   = Kt + 128 * 68;      // [row][d], stride 132
    float* S    = Vs + 64 * 132;      // [row][col], stride 65
    float* mrow = S + 64 * 65;
    float* lrow = mrow + 64;
    float* arow = lrow + 64;

    const int qt = blockIdx.x;        // query tile (32)
    const int h  = blockIdx.y;        // head (28)
    const int kvh = h / 7;
    const int tid = threadIdx.x;
    const int ty = tid >> 4, tx = tid & 15;
    const int rm = ty * 4;            // 4 rows per thread
    const int cn = tx * 8;            // 8 output cols per thread

    // load Q tile transposed: Qt[d][r]
    const float* qbase = q + (size_t)(qt * 64) * HID + h * HD;
    #pragma unroll
    for (int i = 0; i < 8; i++) {
        int f = tid + i * 256;            // 0..2047
        int r = f >> 5;
        int d4 = (f & 31) << 2;
        float4 val = *(const float4*)(qbase + (size_t)r * HID + d4);
        Qt[(d4 + 0) * 68 + r] = val.x;
        Qt[(d4 + 1) * 68 + r] = val.y;
        Qt[(d4 + 2) * 68 + r] = val.z;
        Qt[(d4 + 3) * 68 + r] = val.w;
    }
    if (tid < 64) { mrow[tid] = -INFINITY; lrow[tid] = 0.f; }

    float acc[4][8];
    #pragma unroll
    for (int i = 0; i < 4; i++)
        #pragma unroll
        for (int j = 0; j < 8; j++) acc[i][j] = 0.f;

    const float scale = 0.08838834764831845f;   // 1/sqrt(128)

    for (int kt2 = 0; kt2 <= qt; kt2++) {
        const float* kb = k + (size_t)(kt2 * 64) * KVDIM + kvh * HD;
        const float* vb = v + (size_t)(kt2 * 64) * KVDIM + kvh * HD;
        #pragma unroll
        for (int i = 0; i < 8; i++) {
            int f = tid + i * 256;
            int r = f >> 5;
            int d4 = (f & 31) << 2;
            float4 kv4 = *(const float4*)(kb + (size_t)r * KVDIM + d4);
            Kt[(d4 + 0) * 68 + r] = kv4.x;
            Kt[(d4 + 1) * 68 + r] = kv4.y;
            Kt[(d4 + 2) * 68 + r] = kv4.z;
            Kt[(d4 + 3) * 68 + r] = kv4.w;
            float4 vv4 = *(const float4*)(vb + (size_t)r * KVDIM + d4);
            *(float4*)&Vs[r * 132 + d4] = vv4;
        }
        __syncthreads();

        // S = Q @ K^T : 4x4 per thread over d=128
        float sacc[4][4];
        #pragma unroll
        for (int i = 0; i < 4; i++)
            #pragma unroll
            for (int j = 0; j < 4; j++) sacc[i][j] = 0.f;

        #pragma unroll 4
        for (int kk = 0; kk < 128; kk++) {
            float4 qa = *(const float4*)&Qt[kk * 68 + rm];
            float4 kbv = *(const float4*)&Kt[kk * 68 + tx * 4];
            float a[4] = {qa.x, qa.y, qa.z, qa.w};
            float b[4] = {kbv.x, kbv.y, kbv.z, kbv.w};
            #pragma unroll
            for (int i = 0; i < 4; i++)
                #pragma unroll
                for (int j = 0; j < 4; j++)
                    sacc[i][j] += a[i] * b[j];
        }

        // scale + causal mask + write to smem
        #pragma unroll
        for (int i = 0; i < 4; i++) {
            int qr = qt * 64 + rm + i;
            #pragma unroll
            for (int j = 0; j < 4; j++) {
                int kc = kt2 * 64 + tx * 4 + j;
                float sv = sacc[i][j] * scale;
                if (kc > qr) sv += -1.0e9f;
                S[(rm + i) * 65 + tx * 4 + j] = sv;
            }
        }
        __syncthreads();

        // online softmax stats: one thread per row
        if (tid < 64) {
            int r = tid;
            float mo = mrow[r];
            float mx = mo;
            #pragma unroll 8
            for (int c = 0; c < 64; c++) mx = fmaxf(mx, S[r * 65 + c]);
            float al = __expf(mo - mx);      // 0 when mo = -inf
            float sum = 0.f;
            #pragma unroll 8
            for (int c = 0; c < 64; c++) {
                float p = __expf(S[r * 65 + c] - mx);
                S[r * 65 + c] = p;
                sum += p;
            }
            mrow[r] = mx;
            lrow[r] = lrow[r] * al + sum;
            arow[r] = al;
        }
        __syncthreads();

        // rescale accumulator, then O += P @ V
        float al[4];
        #pragma unroll
        for (int i = 0; i < 4; i++) al[i] = arow[rm + i];
        #pragma unroll
        for (int i = 0; i < 4; i++)
            #pragma unroll
            for (int j = 0; j < 8; j++) acc[i][j] *= al[i];

        #pragma unroll 4
        for (int kk = 0; kk < 64; kk++) {
            float4 v0 = *(const float4*)&Vs[kk * 132 + cn];
            float4 v1 = *(const float4*)&Vs[kk * 132 + cn + 4];
            float vv[8] = {v0.x, v0.y, v0.z, v0.w, v1.x, v1.y, v1.z, v1.w};
            #pragma unroll
            for (int i = 0; i < 4; i++) {
                float p = S[(rm + i) * 65 + kk];
                #pragma unroll
                for (int j = 0; j < 8; j++) acc[i][j] += p * vv[j];
            }
        }
        __syncthreads();   // protect Kt/Vs/S before next iteration
    }

    // epilogue: divide by l, write ctx (s, h*128 + d) layout
    #pragma unroll
    for (int i = 0; i < 4; i++) {
        float inv = 1.f / lrow[rm + i];
        float* crow = ctx + (size_t)(qt * 64 + rm + i) * HID + h * HD + cn;
        #pragma unroll
        for (int j = 0; j < 8; j++) crow[j] = acc[i][j] * inv;
    }
}

// ---------------- host launcher ----------------
extern "C" void kernel_launch(void* const* d_in, const int* in_sizes, int n_in,
                              void* d_out, int out_size)
{
    const float* hs = (const float*)d_in[0];
    // d_in[1] = attention_mask (pure causal; applied analytically)
    const float* wq = (const float*)d_in[2];
    const float* bq = (const float*)d_in[3];
    const float* wk = (const float*)d_in[4];
    const float* bk = (const float*)d_in[5];
    const float* wv = (const float*)d_in[6];
    const float* bv = (const float*)d_in[7];
    const float* wo = (const float*)d_in[8];
    float* out = (float*)d_out;

    float *q, *k, *v, *ctx;
    cudaGetSymbolAddress((void**)&q,   g_q);
    cudaGetSymbolAddress((void**)&k,   g_k);
    cudaGetSymbolAddress((void**)&v,   g_v);
    cudaGetSymbolAddress((void**)&ctx, g_ctx);

    dim3 blk(256);

    // projections
    gemm_nt<<<dim3(HID / 128,   SEQ / 128), blk>>>(hs, wq, bq, q, SEQ, HID,   HID);
    gemm_nt<<<dim3(KVDIM / 128, SEQ / 128), blk>>>(hs, wk, bk, k, SEQ, KVDIM, HID);
    gemm_nt<<<dim3(KVDIM / 128, SEQ / 128), blk>>>(hs, wv, bv, v, SEQ, KVDIM, HID);

    // rope
    rope_kernel<<<(SEQ * NH  * 64) / 256, 256>>>(q, NH);
    rope_kernel<<<(SEQ * NKV * 64) / 256, 256>>>(k, NKV);

    // attention
    size_t smem = ATTN_SMEM_FLOATS * sizeof(float);
    cudaFuncSetAttribute(attn_kernel, cudaFuncAttributeMaxDynamicSharedMemorySize, (int)smem);
    attn_kernel<<<dim3(SEQ / 64, NH), blk, smem>>>(q, k, v, ctx);

    // output projection (no bias)
    gemm_nt<<<dim3(HID / 128, SEQ / 128), blk>>>(ctx, wo, nullptr, out, SEQ, HID, HID);
}

// round 2
// speedup vs baseline: 2.8782x; 2.8782x over previous
#include <cuda_runtime.h>
#include <math.h>
#include <stdint.h>

#define SEQ   2048
#define HID   3584
#define NH    28
#define NKV   4
#define HD    128
#define KVDIM 512   // NKV * HD

// ---------------- scratch (no allocations allowed) ----------------
__device__ float g_q[SEQ * HID];
__device__ float g_k[SEQ * KVDIM];
__device__ float g_v[SEQ * KVDIM];
__device__ float g_ctx[SEQ * HID];

// ---------------- helpers ----------------
__device__ __forceinline__ float to_tf32(float x) {
    uint32_t u;
    asm("cvt.rna.tf32.f32 %0, %1;" : "=r"(u) : "f"(x));
    return __uint_as_float(u);
}

__device__ __forceinline__ void mma_tf32(float* c, const uint32_t* a, const uint32_t* b) {
    asm volatile(
        "mma.sync.aligned.m16n8k8.row.col.f32.tf32.tf32.f32 "
        "{%0,%1,%2,%3}, {%4,%5,%6,%7}, {%8,%9}, {%0,%1,%2,%3};\n"
        : "+f"(c[0]), "+f"(c[1]), "+f"(c[2]), "+f"(c[3])
        : "r"(a[0]), "r"(a[1]), "r"(a[2]), "r"(a[3]), "r"(b[0]), "r"(b[1]));
}

// ---------------- TF32 GEMM: C[M,N] = A[M,K] @ W[N,K]^T + bias ----------------
// Block tile 128x128, BK=16, 256 threads (8 warps, each 32x64 warp tile).
// Smem stride 20 (== 4 mod 32) makes all fragment loads bank-conflict-free.
__global__ __launch_bounds__(256, 2) void gemm_tf32(
    const float* __restrict__ A, const float* __restrict__ W,
    const float* __restrict__ bias, float* __restrict__ C,
    int M, int N, int K)
{
    __shared__ float As[128][20];
    __shared__ float Ws[128][20];

    const int tid  = threadIdx.x;
    const int lane = tid & 31;
    const int wid  = tid >> 5;
    const int bm = blockIdx.y * 128;
    const int bn = blockIdx.x * 128;

    const int warp_m = (wid >> 1) * 32;   // 0,32,64,96
    const int warp_n = (wid & 1) * 64;    // 0,64

    // global load mapping: 128 rows x 16 cols per tile = 512 float4; 2 per thread
    const int lrow = tid >> 2;            // 0..63
    const int lcol = (tid & 3) << 2;      // 0,4,8,12

    const float* Ag = A + (size_t)(bm + lrow) * K + lcol;
    const float* Wg = W + (size_t)(bn + lrow) * K + lcol;

    float acc[2][8][4];
    #pragma unroll
    for (int mi = 0; mi < 2; mi++)
        #pragma unroll
        for (int ni = 0; ni < 8; ni++)
            #pragma unroll
            for (int j = 0; j < 4; j++) acc[mi][ni][j] = 0.f;

    const int nk = K / 16;

    // preload tile 0
    float4 pa0 = *(const float4*)(Ag);
    float4 pa1 = *(const float4*)(Ag + (size_t)64 * K);
    float4 pw0 = *(const float4*)(Wg);
    float4 pw1 = *(const float4*)(Wg + (size_t)64 * K);

    As[lrow][lcol+0] = to_tf32(pa0.x); As[lrow][lcol+1] = to_tf32(pa0.y);
    As[lrow][lcol+2] = to_tf32(pa0.z); As[lrow][lcol+3] = to_tf32(pa0.w);
    As[lrow+64][lcol+0] = to_tf32(pa1.x); As[lrow+64][lcol+1] = to_tf32(pa1.y);
    As[lrow+64][lcol+2] = to_tf32(pa1.z); As[lrow+64][lcol+3] = to_tf32(pa1.w);
    Ws[lrow][lcol+0] = to_tf32(pw0.x); Ws[lrow][lcol+1] = to_tf32(pw0.y);
    Ws[lrow][lcol+2] = to_tf32(pw0.z); Ws[lrow][lcol+3] = to_tf32(pw0.w);
    Ws[lrow+64][lcol+0] = to_tf32(pw1.x); Ws[lrow+64][lcol+1] = to_tf32(pw1.y);
    Ws[lrow+64][lcol+2] = to_tf32(pw1.z); Ws[lrow+64][lcol+3] = to_tf32(pw1.w);
    __syncthreads();

    for (int kt = 0; kt < nk; kt++) {
        const bool has_next = (kt + 1) < nk;
        if (has_next) {
            const float* Ap = Ag + (size_t)(kt + 1) * 16;
            const float* Wp = Wg + (size_t)(kt + 1) * 16;
            pa0 = *(const float4*)(Ap);
            pa1 = *(const float4*)(Ap + (size_t)64 * K);
            pw0 = *(const float4*)(Wp);
            pw1 = *(const float4*)(Wp + (size_t)64 * K);
        }

        #pragma unroll
        for (int ks = 0; ks < 16; ks += 8) {
            const int kq = ks + (lane & 3);
            const int r0 = warp_m + (lane >> 2);
            uint32_t a[2][4], b[8][2];
            #pragma unroll
            for (int mi = 0; mi < 2; mi++) {
                const int r = r0 + mi * 16;
                a[mi][0] = __float_as_uint(As[r][kq]);
                a[mi][1] = __float_as_uint(As[r + 8][kq]);
                a[mi][2] = __float_as_uint(As[r][kq + 4]);
                a[mi][3] = __float_as_uint(As[r + 8][kq + 4]);
            }
            #pragma unroll
            for (int ni = 0; ni < 8; ni++) {
                const int cc = warp_n + ni * 8 + (lane >> 2);
                b[ni][0] = __float_as_uint(Ws[cc][kq]);
                b[ni][1] = __float_as_uint(Ws[cc][kq + 4]);
            }
            #pragma unroll
            for (int mi = 0; mi < 2; mi++)
                #pragma unroll
                for (int ni = 0; ni < 8; ni++)
                    mma_tf32(acc[mi][ni], a[mi], b[ni]);
        }
        __syncthreads();

        if (has_next) {
            As[lrow][lcol+0] = to_tf32(pa0.x); As[lrow][lcol+1] = to_tf32(pa0.y);
            As[lrow][lcol+2] = to_tf32(pa0.z); As[lrow][lcol+3] = to_tf32(pa0.w);
            As[lrow+64][lcol+0] = to_tf32(pa1.x); As[lrow+64][lcol+1] = to_tf32(pa1.y);
            As[lrow+64][lcol+2] = to_tf32(pa1.z); As[lrow+64][lcol+3] = to_tf32(pa1.w);
            Ws[lrow][lcol+0] = to_tf32(pw0.x); Ws[lrow][lcol+1] = to_tf32(pw0.y);
            Ws[lrow][lcol+2] = to_tf32(pw0.z); Ws[lrow][lcol+3] = to_tf32(pw0.w);
            Ws[lrow+64][lcol+0] = to_tf32(pw1.x); Ws[lrow+64][lcol+1] = to_tf32(pw1.y);
            Ws[lrow+64][lcol+2] = to_tf32(pw1.z); Ws[lrow+64][lcol+3] = to_tf32(pw1.w);
            __syncthreads();
        }
    }

    // epilogue
    #pragma unroll
    for (int ni = 0; ni < 8; ni++) {
        const int col = bn + warp_n + ni * 8 + (lane & 3) * 2;
        float b0 = 0.f, b1 = 0.f;
        if (bias) { b0 = bias[col]; b1 = bias[col + 1]; }
        #pragma unroll
        for (int mi = 0; mi < 2; mi++) {
            const int row = bm + warp_m + mi * 16 + (lane >> 2);
            float2 v0 = make_float2(acc[mi][ni][0] + b0, acc[mi][ni][1] + b1);
            float2 v1 = make_float2(acc[mi][ni][2] + b0, acc[mi][ni][3] + b1);
            *(float2*)(C + (size_t)row * N + col) = v0;
            *(float2*)(C + (size_t)(row + 8) * N + col) = v1;
        }
    }
}

// ---------------- RoPE (in-place), angles in double ----------------
__global__ void rope_kernel(float* __restrict__ x, int nheads)
{
    int idx = blockIdx.x * blockDim.x + threadIdx.x;
    int half = idx & 63;
    int h = (idx >> 6) % nheads;
    int s = idx / (64 * nheads);

    double inv = pow(1.0e6, -(double)(2 * half) / 128.0);
    double ang = (double)s * inv;
    float c = (float)cos(ang);
    float si = (float)sin(ang);

    float* base = x + (size_t)s * nheads * HD + h * HD;
    float x1 = base[half];
    float x2 = base[half + 64];
    base[half]      = x1 * c - x2 * si;
    base[half + 64] = x2 * c + x1 * si;
}

// ---------------- Flash attention, TF32 tensor cores ----------------
// 64 q-rows per block, 64-key tiles, D=128. 8 warps.
// Qs[64][132], Ks[64][132]: stride 132 == 4 mod 32 -> frag loads conflict-free.
// Vs[64][136]: stride 136 == 8 mod 32 -> transposed B-frag reads conflict-free.
// S/P[64][68]: stride 68 == 4 mod 32.
#define QS_STRIDE 132
#define VS_STRIDE 136
#define SS_STRIDE 68
#define ATTN_SMEM_FLOATS (64*QS_STRIDE + 64*QS_STRIDE + 64*VS_STRIDE + 64*SS_STRIDE + 192)

__global__ __launch_bounds__(256, 1) void attn_kernel(
    const float* __restrict__ q, const float* __restrict__ k,
    const float* __restrict__ v, float* __restrict__ ctx)
{
    extern __shared__ float sm[];
    float* Qs   = sm;                         // [64][132]
    float* Ks   = Qs + 64 * QS_STRIDE;        // [64][132]
    float* Vs   = Ks + 64 * QS_STRIDE;        // [64][136] (key row, d col)
    float* S    = Vs + 64 * VS_STRIDE;        // [64][68]
    float* mrow = S + 64 * SS_STRIDE;
    float* lrow = mrow + 64;
    float* arow = lrow + 64;

    const int qt  = gridDim.x - 1 - blockIdx.x;   // heavy tiles first
    const int h   = blockIdx.y;
    const int kvh = h / 7;
    const int tid  = threadIdx.x;
    const int lane = tid & 31;
    const int wid  = tid >> 5;

    // warp partitions
    const int wm  = (wid & 3) * 16;     // q-row base (both phases)
    const int wnS = (wid >> 2) * 32;    // key-col base for S (2 warps x 32)
    const int wnO = (wid >> 2) * 64;    // d-col base for O (2 warps x 64)

    // ---- load Q tile (cvt tf32) ----
    const float* qbase = q + (size_t)(qt * 64) * HID + h * HD;
    #pragma unroll
    for (int i = 0; i < 8; i++) {
        int f = tid + i * 256;            // 0..2047
        int r = f >> 5;
        int d4 = (f & 31) << 2;
        float4 val = *(const float4*)(qbase + (size_t)r * HID + d4);
        float* p = &Qs[r * QS_STRIDE + d4];
        p[0] = to_tf32(val.x); p[1] = to_tf32(val.y);
        p[2] = to_tf32(val.z); p[3] = to_tf32(val.w);
    }
    if (tid < 64) { mrow[tid] = -INFINITY; lrow[tid] = 0.f; }

    float out[8][4];
    #pragma unroll
    for (int ni = 0; ni < 8; ni++)
        #pragma unroll
        for (int j = 0; j < 4; j++) out[ni][j] = 0.f;

    const float scale = 0.08838834764831845f;   // 1/sqrt(128)

    for (int kt2 = 0; kt2 <= qt; kt2++) {
        if (kt2 > 0) __syncthreads();   // prev iter fully done before overwrite

        // ---- load K, V tiles ----
        const float* kb = k + (size_t)(kt2 * 64) * KVDIM + kvh * HD;
        const float* vb = v + (size_t)(kt2 * 64) * KVDIM + kvh * HD;
        #pragma unroll
        for (int i = 0; i < 8; i++) {
            int f = tid + i * 256;
            int r = f >> 5;
            int d4 = (f & 31) << 2;
            float4 kv = *(const float4*)(kb + (size_t)r * KVDIM + d4);
            float* pk = &Ks[r * QS_STRIDE + d4];
            pk[0] = to_tf32(kv.x); pk[1] = to_tf32(kv.y);
            pk[2] = to_tf32(kv.z); pk[3] = to_tf32(kv.w);
            float4 vv = *(const float4*)(vb + (size_t)r * KVDIM + d4);
            float* pv = &Vs[r * VS_STRIDE + d4];
            pv[0] = to_tf32(vv.x); pv[1] = to_tf32(vv.y);
            pv[2] = to_tf32(vv.z); pv[3] = to_tf32(vv.w);
        }
        __syncthreads();

        // ---- S = Q @ K^T (warp: 16 q x 32 keys) ----
        float sfrag[4][4];
        #pragma unroll
        for (int ni = 0; ni < 4; ni++)
            #pragma unroll
            for (int j = 0; j < 4; j++) sfrag[ni][j] = 0.f;

        #pragma unroll
        for (int ks = 0; ks < 128; ks += 8) {
            const int kq = ks + (lane & 3);
            const int r = wm + (lane >> 2);
            uint32_t a[4], b[4][2];
            a[0] = __float_as_uint(Qs[r * QS_STRIDE + kq]);
            a[1] = __float_as_uint(Qs[(r + 8) * QS_STRIDE + kq]);
            a[2] = __float_as_uint(Qs[r * QS_STRIDE + kq + 4]);
            a[3] = __float_as_uint(Qs[(r + 8) * QS_STRIDE + kq + 4]);
            #pragma unroll
            for (int ni = 0; ni < 4; ni++) {
                const int cc = wnS + ni * 8 + (lane >> 2);
                b[ni][0] = __float_as_uint(Ks[cc * QS_STRIDE + kq]);
                b[ni][1] = __float_as_uint(Ks[cc * QS_STRIDE + kq + 4]);
            }
            #pragma unroll
            for (int ni = 0; ni < 4; ni++)
                mma_tf32(sfrag[ni], a, b[ni]);
        }

        // scale + causal mask (diagonal tile only) + store S
        const bool diag = (kt2 == qt);
        #pragma unroll
        for (int ni = 0; ni < 4; ni++) {
            const int cl = wnS + ni * 8 + (lane & 3) * 2;
            #pragma unroll
            for (int rr = 0; rr < 2; rr++) {
                const int rl = wm + (lane >> 2) + rr * 8;
                float v0 = sfrag[ni][rr * 2 + 0] * scale;
                float v1 = sfrag[ni][rr * 2 + 1] * scale;
                if (diag) {
                    if (cl > rl)     v0 += -1.0e9f;
                    if (cl + 1 > rl) v1 += -1.0e9f;
                }
                S[rl * SS_STRIDE + cl]     = v0;
                S[rl * SS_STRIDE + cl + 1] = v1;
            }
        }
        __syncthreads();

        // ---- online softmax: 4 threads per row ----
        {
            const int r   = tid >> 2;
            const int sub = tid & 3;
            float* srow = &S[r * SS_STRIDE + sub * 16];
            float m_old = mrow[r];
            float mx = m_old;
            #pragma unroll
            for (int c = 0; c < 16; c++) mx = fmaxf(mx, srow[c]);
            mx = fmaxf(mx, __shfl_xor_sync(0xffffffffu, mx, 1));
            mx = fmaxf(mx, __shfl_xor_sync(0xffffffffu, mx, 2));
            float sum = 0.f;
            #pragma unroll
            for (int c = 0; c < 16; c++) {
                float p = __expf(srow[c] - mx);
                srow[c] = to_tf32(p);
                sum += p;
            }
            sum += __shfl_xor_sync(0xffffffffu, sum, 1);
            sum += __shfl_xor_sync(0xffffffffu, sum, 2);
            if (sub == 0) {
                float alpha = __expf(m_old - mx);
                mrow[r] = mx;
                lrow[r] = lrow[r] * alpha + sum;
                arow[r] = alpha;
            }
        }
        __syncthreads();

        // ---- rescale accumulators, O += P @ V (warp: 16 q x 64 d) ----
        {
            const float al0 = arow[wm + (lane >> 2)];
            const float al1 = arow[wm + 8 + (lane >> 2)];
            #pragma unroll
            for (int ni = 0; ni < 8; ni++) {
                out[ni][0] *= al0; out[ni][1] *= al0;
                out[ni][2] *= al1; out[ni][3] *= al1;
            }
        }
        #pragma unroll
        for (int ks = 0; ks < 64; ks += 8) {
            const int kq = ks + (lane & 3);
            const int r = wm + (lane >> 2);
            uint32_t a[4], b[8][2];
            a[0] = __float_as_uint(S[r * SS_STRIDE + kq]);
            a[1] = __float_as_uint(S[(r + 8) * SS_STRIDE + kq]);
            a[2] = __float_as_uint(S[r * SS_STRIDE + kq + 4]);
            a[3] = __float_as_uint(S[(r + 8) * SS_STRIDE + kq + 4]);
            #pragma unroll
            for (int ni = 0; ni < 8; ni++) {
                const int dn = wnO + ni * 8 + (lane >> 2);
                b[ni][0] = __float_as_uint(Vs[kq * VS_STRIDE + dn]);
                b[ni][1] = __float_as_uint(Vs[(kq + 4) * VS_STRIDE + dn]);
            }
            #pragma unroll
            for (int ni = 0; ni < 8; ni++)
                mma_tf32(out[ni], a, b[ni]);
        }
    }

    __syncthreads();
    // ---- epilogue: divide by l, write ctx ----
    {
        const float inv0 = 1.f / lrow[wm + (lane >> 2)];
        const float inv1 = 1.f / lrow[wm + 8 + (lane >> 2)];
        const int row0 = qt * 64 + wm + (lane >> 2);
        #pragma unroll
        for (int ni = 0; ni < 8; ni++) {
            const int col = h * HD + wnO + ni * 8 + (lane & 3) * 2;
            float2 v0 = make_float2(out[ni][0] * inv0, out[ni][1] * inv0);
            float2 v1 = make_float2(out[ni][2] * inv1, out[ni][3] * inv1);
            *(float2*)(ctx + (size_t)row0 * HID + col) = v0;
            *(float2*)(ctx + (size_t)(row0 + 8) * HID + col) = v1;
        }
    }
}

// ---------------- host launcher ----------------
extern "C" void kernel_launch(void* const* d_in, const int* in_sizes, int n_in,
                              void* d_out, int out_size)
{
    const float* hs = (const float*)d_in[0];
    // d_in[1] = attention_mask (pure causal; applied analytically)
    const float* wq = (const float*)d_in[2];
    const float* bq = (const float*)d_in[3];
    const float* wk = (const float*)d_in[4];
    const float* bk = (const float*)d_in[5];
    const float* wv = (const float*)d_in[6];
    const float* bv = (const float*)d_in[7];
    const float* wo = (const float*)d_in[8];
    float* out = (float*)d_out;

    float *q, *k, *v, *ctx;
    cudaGetSymbolAddress((void**)&q,   g_q);
    cudaGetSymbolAddress((void**)&k,   g_k);
    cudaGetSymbolAddress((void**)&v,   g_v);
    cudaGetSymbolAddress((void**)&ctx, g_ctx);

    dim3 blk(256);

    // projections (TF32 tensor cores)
    gemm_tf32<<<dim3(HID / 128,   SEQ / 128), blk>>>(hs, wq, bq, q, SEQ, HID,   HID);
    gemm_tf32<<<dim3(KVDIM / 128, SEQ / 128), blk>>>(hs, wk, bk, k, SEQ, KVDIM, HID);
    gemm_tf32<<<dim3(KVDIM / 128, SEQ / 128), blk>>>(hs, wv, bv, v, SEQ, KVDIM, HID);

    // rope
    rope_kernel<<<(SEQ * NH  * 64) / 256, 256>>>(q, NH);
    rope_kernel<<<(SEQ * NKV * 64) / 256, 256>>>(k, NKV);

    // attention (TF32 tensor cores)
    size_t smem = ATTN_SMEM_FLOATS * sizeof(float);
    cudaFuncSetAttribute(attn_kernel, cudaFuncAttributeMaxDynamicSharedMemorySize, (int)smem);
    attn_kernel<<<dim3(SEQ / 64, NH), blk, smem>>>(q, k, v, ctx);

    // output projection
    gemm_tf32<<<dim3(HID / 128, SEQ / 128), blk>>>(ctx, wo, nullptr, out, SEQ, HID, HID);
}

// round 4
// speedup vs baseline: 4.9345x; 1.7144x over previous
#include <cuda_runtime.h>
#include <cuda_fp16.h>
#include <math.h>
#include <stdint.h>

#define SEQ   2048
#define HID   3584
#define NH    28
#define NKV   4
#define HD    128
#define KVDIM 512   // NKV * HD

// ---------------- scratch (no allocations allowed) ----------------
__device__ float  g_q[SEQ * HID];
__device__ float  g_k[SEQ * KVDIM];
__device__ float  g_v[SEQ * KVDIM];
__device__ __half g_ctx_h[SEQ * HID];
__device__ __half g_hs_h[SEQ * HID];
__device__ __half g_wq_h[(size_t)HID * HID];
__device__ __half g_wk_h[(size_t)KVDIM * HID];
__device__ __half g_wv_h[(size_t)KVDIM * HID];
__device__ __half g_wo_h[(size_t)HID * HID];

// ---------------- helpers ----------------
__device__ __forceinline__ float to_tf32(float x) {
    uint32_t u;
    asm("cvt.rna.tf32.f32 %0, %1;" : "=r"(u) : "f"(x));
    return __uint_as_float(u);
}

__device__ __forceinline__ uint32_t smem_u32(const void* p) {
    uint32_t a;
    asm("{ .reg .u64 t; cvta.to.shared.u64 t, %1; cvt.u32.u64 %0, t; }" : "=r"(a) : "l"(p));
    return a;
}

__device__ __forceinline__ void mma_tf32(float* c, const uint32_t* a, const uint32_t* b) {
    asm volatile(
        "mma.sync.aligned.m16n8k8.row.col.f32.tf32.tf32.f32 "
        "{%0,%1,%2,%3}, {%4,%5,%6,%7}, {%8,%9}, {%0,%1,%2,%3};\n"
        : "+f"(c[0]), "+f"(c[1]), "+f"(c[2]), "+f"(c[3])
        : "r"(a[0]), "r"(a[1]), "r"(a[2]), "r"(a[3]), "r"(b[0]), "r"(b[1]));
}

__device__ __forceinline__ void mma_f16(float* c, const uint32_t* a, const uint32_t* b) {
    asm volatile(
        "mma.sync.aligned.m16n8k16.row.col.f32.f16.f16.f32 "
        "{%0,%1,%2,%3}, {%4,%5,%6,%7}, {%8,%9}, {%0,%1,%2,%3};\n"
        : "+f"(c[0]), "+f"(c[1]), "+f"(c[2]), "+f"(c[3])
        : "r"(a[0]), "r"(a[1]), "r"(a[2]), "r"(a[3]), "r"(b[0]), "r"(b[1]));
}

__device__ __forceinline__ void ldm_x4(uint32_t* r, uint32_t addr) {
    asm volatile("ldmatrix.sync.aligned.m8n8.x4.shared.b16 {%0,%1,%2,%3}, [%4];"
                 : "=r"(r[0]), "=r"(r[1]), "=r"(r[2]), "=r"(r[3]) : "r"(addr));
}

// ---------------- fp32 -> fp16 conversion pass ----------------
__global__ void cvt_half(const float* __restrict__ in, __half* __restrict__ out, int n4) {
    int i = blockIdx.x * blockDim.x + threadIdx.x;
    if (i < n4) {
        float4 v = ((const float4*)in)[i];
        __half2 h0 = __floats2half2_rn(v.x, v.y);
        __half2 h1 = __floats2half2_rn(v.z, v.w);
        ((__half2*)out)[i * 2 + 0] = h0;
        ((__half2*)out)[i * 2 + 1] = h1;
    }
}

// ---------------- FP16 GEMM: C[M,N] = A[M,K] @ W[N,K]^T + bias (fp32 out) ----
// Block 128x128, BK=32 halves, 2-stage cp.async, ldmatrix fragments.
// Smem tiles [128 rows][40 halves] (stride 80B = 5 x 16B, odd -> ldmatrix
// phases conflict-free). 8 warps: 4 m-partitions x 2 n-partitions (32x64 each).
#define GTILE_H 5120   // 128 * 40 halves per buffer

__global__ __launch_bounds__(256, 2) void gemm_f16(
    const __half* __restrict__ A, const __half* __restrict__ W,
    const float* __restrict__ bias, float* __restrict__ C,
    int M, int N, int K)
{
    __shared__ __align__(16) __half As[2][GTILE_H];
    __shared__ __align__(16) __half Bs[2][GTILE_H];

    const int tid  = threadIdx.x;
    const int lane = tid & 31;
    const int wid  = tid >> 5;
    const int bm = blockIdx.y * 128;
    const int bn = blockIdx.x * 128;

    const int warp_m = (wid >> 1) * 32;
    const int warp_n = (wid & 1) * 64;

    const uint32_t sbA = smem_u32(&As[0][0]);
    const uint32_t sbB = smem_u32(&Bs[0][0]);

    // cp.async mapping: 2 x 16B per operand per thread per tile
    int lrow[2], lch[2];
    #pragma unroll
    for (int p = 0; p < 2; p++) {
        int f = tid + p * 256;
        lrow[p] = f >> 2;
        lch[p]  = f & 3;
    }

    const int nt = K / 32;

    // prologue: tile 0 -> buf 0
    #pragma unroll
    for (int p = 0; p < 2; p++) {
        uint32_t so = (uint32_t)lrow[p] * 80u + (uint32_t)lch[p] * 16u;
        const __half* ga = A + (size_t)(bm + lrow[p]) * K + lch[p] * 8;
        const __half* gb = W + (size_t)(bn + lrow[p]) * K + lch[p] * 8;
        asm volatile("cp.async.cg.shared.global [%0], [%1], 16;" :: "r"(sbA + so), "l"(ga) : "memory");
        asm volatile("cp.async.cg.shared.global [%0], [%1], 16;" :: "r"(sbB + so), "l"(gb) : "memory");
    }
    asm volatile("cp.async.commit_group;" ::: "memory");

    float acc[2][8][4];
    #pragma unroll
    for (int mi = 0; mi < 2; mi++)
        #pragma unroll
        for (int ni = 0; ni < 8; ni++)
            #pragma unroll
            for (int j = 0; j < 4; j++) acc[mi][ni][j] = 0.f;

    // ldmatrix lane roles
    const int lg = lane >> 3;        // 0..3 (matrix group)
    const int lr = lane & 7;         // row within matrix

    for (int i = 0; i < nt; i++) {
        const int cur = i & 1;
        if (i + 1 < nt) {
            const uint32_t ab = sbA + (uint32_t)((i + 1) & 1) * (GTILE_H * 2);
            const uint32_t bb = sbB + (uint32_t)((i + 1) & 1) * (GTILE_H * 2);
            #pragma unroll
            for (int p = 0; p < 2; p++) {
                uint32_t so = (uint32_t)lrow[p] * 80u + (uint32_t)lch[p] * 16u;
                const __half* ga = A + (size_t)(bm + lrow[p]) * K + (size_t)(i + 1) * 32 + lch[p] * 8;
                const __half* gb = W + (size_t)(bn + lrow[p]) * K + (size_t)(i + 1) * 32 + lch[p] * 8;
                asm volatile("cp.async.cg.shared.global [%0], [%1], 16;" :: "r"(ab + so), "l"(ga) : "memory");
                asm volatile("cp.async.cg.shared.global [%0], [%1], 16;" :: "r"(bb + so), "l"(gb) : "memory");
            }
            asm volatile("cp.async.commit_group;" ::: "memory");
            asm volatile("cp.async.wait_group 1;" ::: "memory");
        } else {
            asm volatile("cp.async.wait_group 0;" ::: "memory");
        }
        __syncthreads();

        const uint32_t abuf = sbA + (uint32_t)cur * (GTILE_H * 2);
        const uint32_t bbuf = sbB + (uint32_t)cur * (GTILE_H * 2);

        #pragma unroll
        for (int s = 0; s < 2; s++) {        // two k16 steps per 32-half buffer
            uint32_t a[2][4], bq[4][4];
            #pragma unroll
            for (int mi = 0; mi < 2; mi++) {
                // a0: m0-7/k0-7, a1: m8-15/k0-7, a2: m0-7/k8-15, a3: m8-15/k8-15
                int row = warp_m + mi * 16 + lr + (lg & 1) * 8;
                int ch  = s * 2 + (lg >> 1);
                ldm_x4(a[mi], abuf + (uint32_t)row * 80u + (uint32_t)ch * 16u);
            }
            #pragma unroll
            for (int pr = 0; pr < 4; pr++) {
                // q0: n0-7/k0-7, q1: n0-7/k8-15, q2: n8-15/k0-7, q3: n8-15/k8-15
                int row = warp_n + pr * 16 + lr + (lg >> 1) * 8;
                int ch  = s * 2 + (lg & 1);
                ldm_x4(bq[pr], bbuf + (uint32_t)row * 80u + (uint32_t)ch * 16u);
            }
            #pragma unroll
            for (int mi = 0; mi < 2; mi++)
                #pragma unroll
                for (int pr = 0; pr < 4; pr++) {
                    mma_f16(acc[mi][pr * 2 + 0], a[mi], &bq[pr][0]);
                    mma_f16(acc[mi][pr * 2 + 1], a[mi], &bq[pr][2]);
                }
        }
        __syncthreads();
    }

    // epilogue (fp32 + bias)
    #pragma unroll
    for (int ni = 0; ni < 8; ni++) {
        const int col = bn + warp_n + ni * 8 + (lane & 3) * 2;
        float b0 = 0.f, b1 = 0.f;
        if (bias) { b0 = bias[col]; b1 = bias[col + 1]; }
        #pragma unroll
        for (int mi = 0; mi < 2; mi++) {
            const int row = bm + warp_m + mi * 16 + (lane >> 2);
            float2 v0 = make_float2(acc[mi][ni][0] + b0, acc[mi][ni][1] + b1);
            float2 v1 = make_float2(acc[mi][ni][2] + b0, acc[mi][ni][3] + b1);
            *(float2*)(C + (size_t)row * N + col) = v0;
            *(float2*)(C + (size_t)(row + 8) * N + col) = v1;
        }
    }
}

// ---------------- RoPE (in-place), angles in double ----------------
__global__ void rope_kernel(float* __restrict__ x, int nheads)
{
    int idx = blockIdx.x * blockDim.x + threadIdx.x;
    int half = idx & 63;
    int h = (idx >> 6) % nheads;
    int s = idx / (64 * nheads);

    double inv = pow(1.0e6, -(double)(2 * half) / 128.0);
    double ang = (double)s * inv;
    float c = (float)cos(ang);
    float si = (float)sin(ang);

    float* base = x + (size_t)s * nheads * HD + h * HD;
    float x1 = base[half];
    float x2 = base[half + 64];
    base[half]      = x1 * c - x2 * si;
    base[half + 64] = x2 * c + x1 * si;
}

// ---------------- Flash attention, TF32 mma.sync (round-2 proven) ----------
#define QS_STRIDE 132
#define VS_STRIDE 136
#define SS_STRIDE 68
#define ATTN_SMEM_FLOATS (64*QS_STRIDE + 64*QS_STRIDE + 64*VS_STRIDE + 64*SS_STRIDE + 192)

__global__ __launch_bounds__(256, 1) void attn_kernel(
    const float* __restrict__ q, const float* __restrict__ k,
    const float* __restrict__ v, __half* __restrict__ ctx)
{
    extern __shared__ float sm[];
    float* Qs   = sm;
    float* Ks   = Qs + 64 * QS_STRIDE;
    float* Vs   = Ks + 64 * QS_STRIDE;
    float* S    = Vs + 64 * VS_STRIDE;
    float* mrow = S + 64 * SS_STRIDE;
    float* lrow = mrow + 64;
    float* arow = lrow + 64;

    const int qt  = gridDim.x - 1 - blockIdx.x;
    const int h   = blockIdx.y;
    const int kvh = h / 7;
    const int tid  = threadIdx.x;
    const int lane = tid & 31;
    const int wid  = tid >> 5;

    const int wm  = (wid & 3) * 16;
    const int wnS = (wid >> 2) * 32;
    const int wnO = (wid >> 2) * 64;

    const float* qbase = q + (size_t)(qt * 64) * HID + h * HD;
    #pragma unroll
    for (int i = 0; i < 8; i++) {
        int f = tid + i * 256;
        int r = f >> 5;
        int d4 = (f & 31) << 2;
        float4 val = *(const float4*)(qbase + (size_t)r * HID + d4);
        float* p = &Qs[r * QS_STRIDE + d4];
        p[0] = to_tf32(val.x); p[1] = to_tf32(val.y);
        p[2] = to_tf32(val.z); p[3] = to_tf32(val.w);
    }
    if (tid < 64) { mrow[tid] = -INFINITY; lrow[tid] = 0.f; }

    float out[8][4];
    #pragma unroll
    for (int ni = 0; ni < 8; ni++)
        #pragma unroll
        for (int j = 0; j < 4; j++) out[ni][j] = 0.f;

    const float scale = 0.08838834764831845f;

    for (int kt2 = 0; kt2 <= qt; kt2++) {
        if (kt2 > 0) __syncthreads();

        const float* kb = k + (size_t)(kt2 * 64) * KVDIM + kvh * HD;
        const float* vb = v + (size_t)(kt2 * 64) * KVDIM + kvh * HD;
        #pragma unroll
        for (int i = 0; i < 8; i++) {
            int f = tid + i * 256;
            int r = f >> 5;
            int d4 = (f & 31) << 2;
            float4 kv = *(const float4*)(kb + (size_t)r * KVDIM + d4);
            float* pk = &Ks[r * QS_STRIDE + d4];
            pk[0] = to_tf32(kv.x); pk[1] = to_tf32(kv.y);
            pk[2] = to_tf32(kv.z); pk[3] = to_tf32(kv.w);
            float4 vv = *(const float4*)(vb + (size_t)r * KVDIM + d4);
            float* pv = &Vs[r * VS_STRIDE + d4];
            pv[0] = to_tf32(vv.x); pv[1] = to_tf32(vv.y);
            pv[2] = to_tf32(vv.z); pv[3] = to_tf32(vv.w);
        }
        __syncthreads();

        float sfrag[4][4];
        #pragma unroll
        for (int ni = 0; ni < 4; ni++)
            #pragma unroll
            for (int j = 0; j < 4; j++) sfrag[ni][j] = 0.f;

        #pragma unroll
        for (int ks = 0; ks < 128; ks += 8) {
            const int kq = ks + (lane & 3);
            const int r = wm + (lane >> 2);
            uint32_t a[4], b[4][2];
            a[0] = __float_as_uint(Qs[r * QS_STRIDE + kq]);
            a[1] = __float_as_uint(Qs[(r + 8) * QS_STRIDE + kq]);
            a[2] = __float_as_uint(Qs[r * QS_STRIDE + kq + 4]);
            a[3] = __float_as_uint(Qs[(r + 8) * QS_STRIDE + kq + 4]);
            #pragma unroll
            for (int ni = 0; ni < 4; ni++) {
                const int cc = wnS + ni * 8 + (lane >> 2);
                b[ni][0] = __float_as_uint(Ks[cc * QS_STRIDE + kq]);
                b[ni][1] = __float_as_uint(Ks[cc * QS_STRIDE + kq + 4]);
            }
            #pragma unroll
            for (int ni = 0; ni < 4; ni++)
                mma_tf32(sfrag[ni], a, b[ni]);
        }

        const bool diag = (kt2 == qt);
        #pragma unroll
        for (int ni = 0; ni < 4; ni++) {
            const int cl = wnS + ni * 8 + (lane & 3) * 2;
            #pragma unroll
            for (int rr = 0; rr < 2; rr++) {
                const int rl = wm + (lane >> 2) + rr * 8;
                float v0 = sfrag[ni][rr * 2 + 0] * scale;
                float v1 = sfrag[ni][rr * 2 + 1] * scale;
                if (diag) {
                    if (cl > rl)     v0 += -1.0e9f;
                    if (cl + 1 > rl) v1 += -1.0e9f;
                }
                S[rl * SS_STRIDE + cl]     = v0;
                S[rl * SS_STRIDE + cl + 1] = v1;
            }
        }
        __syncthreads();

        {
            const int r   = tid >> 2;
            const int sub = tid & 3;
            float* srow = &S[r * SS_STRIDE + sub * 16];
            float m_old = mrow[r];
            float mx = m_old;
            #pragma unroll
            for (int c = 0; c < 16; c++) mx = fmaxf(mx, srow[c]);
            mx = fmaxf(mx, __shfl_xor_sync(0xffffffffu, mx, 1));
            mx = fmaxf(mx, __shfl_xor_sync(0xffffffffu, mx, 2));
            float sum = 0.f;
            #pragma unroll
            for (int c = 0; c < 16; c++) {
                float p = __expf(srow[c] - mx);
                srow[c] = to_tf32(p);
                sum += p;
            }
            sum += __shfl_xor_sync(0xffffffffu, sum, 1);
            sum += __shfl_xor_sync(0xffffffffu, sum, 2);
            if (sub == 0) {
                float alpha = __expf(m_old - mx);
                mrow[r] = mx;
                lrow[r] = lrow[r] * alpha + sum;
                arow[r] = alpha;
            }
        }
        __syncthreads();

        {
            const float al0 = arow[wm + (lane >> 2)];
            const float al1 = arow[wm + 8 + (lane >> 2)];
            #pragma unroll
            for (int ni = 0; ni < 8; ni++) {
                out[ni][0] *= al0; out[ni][1] *= al0;
                out[ni][2] *= al1; out[ni][3] *= al1;
            }
        }
        #pragma unroll
        for (int ks = 0; ks < 64; ks += 8) {
            const int kq = ks + (lane & 3);
            const int r = wm + (lane >> 2);
            uint32_t a[4], b[8][2];
            a[0] = __float_as_uint(S[r * SS_STRIDE + kq]);
            a[1] = __float_as_uint(S[(r + 8) * SS_STRIDE + kq]);
            a[2] = __float_as_uint(S[r * SS_STRIDE + kq + 4]);
            a[3] = __float_as_uint(S[(r + 8) * SS_STRIDE + kq + 4]);
            #pragma unroll
            for (int ni = 0; ni < 8; ni++) {
                const int dn = wnO + ni * 8 + (lane >> 2);
                b[ni][0] = __float_as_uint(Vs[kq * VS_STRIDE + dn]);
                b[ni][1] = __float_as_uint(Vs[(kq + 4) * VS_STRIDE + dn]);
            }
            #pragma unroll
            for (int ni = 0; ni < 8; ni++)
                mma_f16_dummy:;
            #pragma unroll
            for (int ni = 0; ni < 8; ni++)
                mma_tf32(out[ni], a, b[ni]);
        }
    }

    __syncthreads();
    // epilogue: divide by l, write ctx as fp16 (feeds fp16 O-projection)
    {
        const float inv0 = 1.f / lrow[wm + (lane >> 2)];
        const float inv1 = 1.f / lrow[wm + 8 + (lane >> 2)];
        const int row0 = qt * 64 + wm + (lane >> 2);
        #pragma unroll
        for (int ni = 0; ni < 8; ni++) {
            const int col = h * HD + wnO + ni * 8 + (lane & 3) * 2;
            __half2 h0 = __floats2half2_rn(out[ni][0] * inv0, out[ni][1] * inv0);
            __half2 h1 = __floats2half2_rn(out[ni][2] * inv1, out[ni][3] * inv1);
            *(__half2*)(ctx + (size_t)row0 * HID + col) = h0;
            *(__half2*)(ctx + (size_t)(row0 + 8) * HID + col) = h1;
        }
    }
}

// ---------------- host launcher ----------------
extern "C" void kernel_launch(void* const* d_in, const int* in_sizes, int n_in,
                              void* d_out, int out_size)
{
    const float* hs = (const float*)d_in[0];
    const float* wq = (const float*)d_in[2];
    const float* bq = (const float*)d_in[3];
    const float* wk = (const float*)d_in[4];
    const float* bk = (const float*)d_in[5];
    const float* wv = (const float*)d_in[6];
    const float* bv = (const float*)d_in[7];
    const float* wo = (const float*)d_in[8];
    float* out = (float*)d_out;

    float *q, *k, *v;
    __half *ctx_h, *hs_h, *wq_h, *wk_h, *wv_h, *wo_h;
    cudaGetSymbolAddress((void**)&q,     g_q);
    cudaGetSymbolAddress((void**)&k,     g_k);
    cudaGetSymbolAddress((void**)&v,     g_v);
    cudaGetSymbolAddress((void**)&ctx_h, g_ctx_h);
    cudaGetSymbolAddress((void**)&hs_h,  g_hs_h);
    cudaGetSymbolAddress((void**)&wq_h,  g_wq_h);
    cudaGetSymbolAddress((void**)&wk_h,  g_wk_h);
    cudaGetSymbolAddress((void**)&wv_h,  g_wv_h);
    cudaGetSymbolAddress((void**)&wo_h,  g_wo_h);

    // fp16 operand conversion (RN)
    cvt_half<<<(SEQ * HID / 4 + 255) / 256, 256>>>(hs, hs_h, SEQ * HID / 4);
    cvt_half<<<(HID * HID / 4 + 255) / 256, 256>>>(wq, wq_h, HID * HID / 4);
    cvt_half<<<(KVDIM * HID / 4 + 255) / 256, 256>>>(wk, wk_h, KVDIM * HID / 4);
    cvt_half<<<(KVDIM * HID / 4 + 255) / 256, 256>>>(wv, wv_h, KVDIM * HID / 4);
    cvt_half<<<(HID * HID / 4 + 255) / 256, 256>>>(wo, wo_h, HID * HID / 4);

    // projections (fp16 tensor cores, fp32 accumulate)
    gemm_f16<<<dim3(HID / 128,   SEQ / 128), 256>>>(hs_h, wq_h, bq, q, SEQ, HID,   HID);
    gemm_f16<<<dim3(KVDIM / 128, SEQ / 128), 256>>>(hs_h, wk_h, bk, k, SEQ, KVDIM, HID);
    gemm_f16<<<dim3(KVDIM / 128, SEQ / 128), 256>>>(hs_h, wv_h, bv, v, SEQ, KVDIM, HID);

    // rope
    rope_kernel<<<(SEQ * NH  * 64) / 256, 256>>>(q, NH);
    rope_kernel<<<(SEQ * NKV * 64) / 256, 256>>>(k, NKV);

    // attention (tf32 mma, fp32 in, fp16 ctx out)
    size_t smem = ATTN_SMEM_FLOATS * sizeof(float);
    cudaFuncSetAttribute(attn_kernel, cudaFuncAttributeMaxDynamicSharedMemorySize, (int)smem);
    attn_kernel<<<dim3(SEQ / 64, NH), 256, smem>>>(q, k, v, ctx_h);

    // output projection (fp16 tensor cores)
    gemm_f16<<<dim3(HID / 128, SEQ / 128), 256>>>(ctx_h, wo_h, nullptr, out, SEQ, HID, HID);
}

// round 5
// speedup vs baseline: 5.9074x; 1.1972x over previous
#include <cuda_runtime.h>
#include <cuda_fp16.h>
#include <math.h>
#include <stdint.h>

#define SEQ   2048
#define HID   3584
#define NH    28
#define NKV   4
#define HD    128
#define KVDIM 512   // NKV * HD

// ---------------- scratch (no allocations allowed) ----------------
__device__ float  g_q[SEQ * HID];
__device__ float  g_k[SEQ * KVDIM];
__device__ float  g_v[SEQ * KVDIM];
__device__ __half g_qh[SEQ * HID];
__device__ __half g_kh[SEQ * KVDIM];
__device__ __half g_vh[SEQ * KVDIM];
__device__ __half g_ctx_h[SEQ * HID];
__device__ __half g_hs_h[SEQ * HID];
__device__ __half g_wq_h[(size_t)HID * HID];
__device__ __half g_wk_h[(size_t)KVDIM * HID];
__device__ __half g_wv_h[(size_t)KVDIM * HID];
__device__ __half g_wo_h[(size_t)HID * HID];
__device__ float  g_cos[SEQ * 64];
__device__ float  g_sin[SEQ * 64];

// ---------------- helpers ----------------
__device__ __forceinline__ uint32_t smem_u32(const void* p) {
    uint32_t a;
    asm("{ .reg .u64 t; cvta.to.shared.u64 t, %1; cvt.u32.u64 %0, t; }" : "=r"(a) : "l"(p));
    return a;
}

__device__ __forceinline__ void mma_f16(float* c, const uint32_t* a, const uint32_t* b) {
    asm volatile(
        "mma.sync.aligned.m16n8k16.row.col.f32.f16.f16.f32 "
        "{%0,%1,%2,%3}, {%4,%5,%6,%7}, {%8,%9}, {%0,%1,%2,%3};\n"
        : "+f"(c[0]), "+f"(c[1]), "+f"(c[2]), "+f"(c[3])
        : "r"(a[0]), "r"(a[1]), "r"(a[2]), "r"(a[3]), "r"(b[0]), "r"(b[1]));
}

__device__ __forceinline__ void ldm_x4(uint32_t* r, uint32_t addr) {
    asm volatile("ldmatrix.sync.aligned.m8n8.x4.shared.b16 {%0,%1,%2,%3}, [%4];"
                 : "=r"(r[0]), "=r"(r[1]), "=r"(r[2]), "=r"(r[3]) : "r"(addr));
}

__device__ __forceinline__ void ldm_x4_t(uint32_t* r, uint32_t addr) {
    asm volatile("ldmatrix.sync.aligned.m8n8.x4.trans.shared.b16 {%0,%1,%2,%3}, [%4];"
                 : "=r"(r[0]), "=r"(r[1]), "=r"(r[2]), "=r"(r[3]) : "r"(addr));
}

// ---------------- fp32 -> fp16 conversion pass ----------------
__global__ void cvt_half(const float* __restrict__ in, __half* __restrict__ out, int n4) {
    int i = blockIdx.x * blockDim.x + threadIdx.x;
    if (i < n4) {
        float4 v = ((const float4*)in)[i];
        ((__half2*)out)[i * 2 + 0] = __floats2half2_rn(v.x, v.y);
        ((__half2*)out)[i * 2 + 1] = __floats2half2_rn(v.z, v.w);
    }
}

// ---------------- FP16 GEMM: C[M,N] = A[M,K] @ W[N,K]^T + bias (fp32 out) ----
#define GTILE_H 5120   // 128 * 40 halves per buffer

__global__ __launch_bounds__(256, 2) void gemm_f16(
    const __half* __restrict__ A, const __half* __restrict__ W,
    const float* __restrict__ bias, float* __restrict__ C,
    int M, int N, int K)
{
    __shared__ __align__(16) __half As[2][GTILE_H];
    __shared__ __align__(16) __half Bs[2][GTILE_H];

    const int tid  = threadIdx.x;
    const int lane = tid & 31;
    const int wid  = tid >> 5;
    const int bm = blockIdx.y * 128;
    const int bn = blockIdx.x * 128;

    const int warp_m = (wid >> 1) * 32;
    const int warp_n = (wid & 1) * 64;

    const uint32_t sbA = smem_u32(&As[0][0]);
    const uint32_t sbB = smem_u32(&Bs[0][0]);

    int lrow[2], lch[2];
    #pragma unroll
    for (int p = 0; p < 2; p++) {
        int f = tid + p * 256;
        lrow[p] = f >> 2;
        lch[p]  = f & 3;
    }

    const int nt = K / 32;

    #pragma unroll
    for (int p = 0; p < 2; p++) {
        uint32_t so = (uint32_t)lrow[p] * 80u + (uint32_t)lch[p] * 16u;
        const __half* ga = A + (size_t)(bm + lrow[p]) * K + lch[p] * 8;
        const __half* gb = W + (size_t)(bn + lrow[p]) * K + lch[p] * 8;
        asm volatile("cp.async.cg.shared.global [%0], [%1], 16;" :: "r"(sbA + so), "l"(ga) : "memory");
        asm volatile("cp.async.cg.shared.global [%0], [%1], 16;" :: "r"(sbB + so), "l"(gb) : "memory");
    }
    asm volatile("cp.async.commit_group;" ::: "memory");

    float acc[2][8][4];
    #pragma unroll
    for (int mi = 0; mi < 2; mi++)
        #pragma unroll
        for (int ni = 0; ni < 8; ni++)
            #pragma unroll
            for (int j = 0; j < 4; j++) acc[mi][ni][j] = 0.f;

    const int lg = lane >> 3;
    const int lr = lane & 7;

    for (int i = 0; i < nt; i++) {
        const int cur = i & 1;
        if (i + 1 < nt) {
            const uint32_t ab = sbA + (uint32_t)((i + 1) & 1) * (GTILE_H * 2);
            const uint32_t bb = sbB + (uint32_t)((i + 1) & 1) * (GTILE_H * 2);
            #pragma unroll
            for (int p = 0; p < 2; p++) {
                uint32_t so = (uint32_t)lrow[p] * 80u + (uint32_t)lch[p] * 16u;
                const __half* ga = A + (size_t)(bm + lrow[p]) * K + (size_t)(i + 1) * 32 + lch[p] * 8;
                const __half* gb = W + (size_t)(bn + lrow[p]) * K + (size_t)(i + 1) * 32 + lch[p] * 8;
                asm volatile("cp.async.cg.shared.global [%0], [%1], 16;" :: "r"(ab + so), "l"(ga) : "memory");
                asm volatile("cp.async.cg.shared.global [%0], [%1], 16;" :: "r"(bb + so), "l"(gb) : "memory");
            }
            asm volatile("cp.async.commit_group;" ::: "memory");
            asm volatile("cp.async.wait_group 1;" ::: "memory");
        } else {
            asm volatile("cp.async.wait_group 0;" ::: "memory");
        }
        __syncthreads();

        const uint32_t abuf = sbA + (uint32_t)cur * (GTILE_H * 2);
        const uint32_t bbuf = sbB + (uint32_t)cur * (GTILE_H * 2);

        #pragma unroll
        for (int s = 0; s < 2; s++) {
            uint32_t a[2][4], bq[4][4];
            #pragma unroll
            for (int mi = 0; mi < 2; mi++) {
                int row = warp_m + mi * 16 + lr + (lg & 1) * 8;
                int ch  = s * 2 + (lg >> 1);
                ldm_x4(a[mi], abuf + (uint32_t)row * 80u + (uint32_t)ch * 16u);
            }
            #pragma unroll
            for (int pr = 0; pr < 4; pr++) {
                int row = warp_n + pr * 16 + lr + (lg >> 1) * 8;
                int ch  = s * 2 + (lg & 1);
                ldm_x4(bq[pr], bbuf + (uint32_t)row * 80u + (uint32_t)ch * 16u);
            }
            #pragma unroll
            for (int mi = 0; mi < 2; mi++)
                #pragma unroll
                for (int pr = 0; pr < 4; pr++) {
                    mma_f16(acc[mi][pr * 2 + 0], a[mi], &bq[pr][0]);
                    mma_f16(acc[mi][pr * 2 + 1], a[mi], &bq[pr][2]);
                }
        }
        __syncthreads();
    }

    #pragma unroll
    for (int ni = 0; ni < 8; ni++) {
        const int col = bn + warp_n + ni * 8 + (lane & 3) * 2;
        float b0 = 0.f, b1 = 0.f;
        if (bias) { b0 = bias[col]; b1 = bias[col + 1]; }
        #pragma unroll
        for (int mi = 0; mi < 2; mi++) {
            const int row = bm + warp_m + mi * 16 + (lane >> 2);
            float2 v0 = make_float2(acc[mi][ni][0] + b0, acc[mi][ni][1] + b1);
            float2 v1 = make_float2(acc[mi][ni][2] + b0, acc[mi][ni][3] + b1);
            *(float2*)(C + (size_t)row * N + col) = v0;
            *(float2*)(C + (size_t)(row + 8) * N + col) = v1;
        }
    }
}

// ---------------- RoPE tables (double precision, once per replay) ----------
__global__ void rope_tables(float* __restrict__ cosd, float* __restrict__ sind) {
    int i = blockIdx.x * blockDim.x + threadIdx.x;   // SEQ * 64
    int half = i & 63;
    int s = i >> 6;
    double inv = exp(-log(1.0e6) * (double)(2 * half) / 128.0);
    double ang = (double)s * inv;
    cosd[i] = (float)cos(ang);
    sind[i] = (float)sin(ang);
}

// rope in fp32 from fp32 projection output, single rounding to half
__global__ void rope_apply(const float* __restrict__ x, __half* __restrict__ xh,
                           const float* __restrict__ cosd, const float* __restrict__ sind,
                           int nheads)
{
    int idx = blockIdx.x * blockDim.x + threadIdx.x;
    int half = idx & 63;
    int h = (idx >> 6) % nheads;
    int s = idx / (64 * nheads);

    float c  = cosd[s * 64 + half];
    float si = sind[s * 64 + half];

    const float* base = x + (size_t)s * nheads * HD + h * HD;
    __half* baseh = xh + (size_t)s * nheads * HD + h * HD;
    float x1 = base[half];
    float x2 = base[half + 64];
    baseh[half]      = __float2half_rn(x1 * c - x2 * si);
    baseh[half + 64] = __float2half_rn(x2 * c + x1 * si);
}

// ---------------- Flash attention, FP16 mma + ldmatrix ----------------
// 64 q-rows/block, 64-key tiles, D=128. 8 warps, 2 CTAs/SM.
// Qh/Kh/Vh: [64][136] halves (272B row = 17x16B, odd -> ldmatrix conflict-free)
// Ph: [64][72] halves (144B = 9x16B, odd). S: [64][68] fp32.
#define AQ_STR 136
#define AP_STR 72
#define AS_STR 68
#define ATTN_SMEM_BYTES ((3 * 64 * AQ_STR + 64 * AP_STR) * 2 + (64 * AS_STR + 192) * 4)

__global__ __launch_bounds__(256, 2) void attn_f16(
    const __half* __restrict__ q, const __half* __restrict__ k,
    const __half* __restrict__ v, __half* __restrict__ ctx)
{
    extern __shared__ __align__(16) char smraw[];
    __half* Qh = (__half*)smraw;
    __half* Kh = Qh + 64 * AQ_STR;
    __half* Vh = Kh + 64 * AQ_STR;
    __half* Ph = Vh + 64 * AQ_STR;
    float*  S  = (float*)(Ph + 64 * AP_STR);
    float* mrow = S + 64 * AS_STR;
    float* lrow = mrow + 64;
    float* arow = lrow + 64;

    const int qt  = gridDim.x - 1 - blockIdx.x;   // heavy tiles first
    const int h   = blockIdx.y;
    const int kvh = h / 7;
    const int tid  = threadIdx.x;
    const int lane = tid & 31;
    const int wid  = tid >> 5;

    const int wm  = (wid & 3) * 16;     // q-row base
    const int wnS = (wid >> 2) * 32;    // key-col base (S phase)
    const int wnO = (wid >> 2) * 64;    // d-col base (O phase)

    const int lg = lane >> 3;           // ldmatrix matrix index
    const int lr = lane & 7;

    const uint32_t sQ = smem_u32(Qh);
    const uint32_t sK = smem_u32(Kh);
    const uint32_t sV = smem_u32(Vh);
    const uint32_t sP = smem_u32(Ph);

    // ---- load Q tile ----
    const __half* qbase = q + (size_t)(qt * 64) * HID + h * HD;
    #pragma unroll
    for (int i = 0; i < 4; i++) {
        int f = tid + i * 256;          // 0..1023
        int r = f >> 4;
        int c = (f & 15) * 8;
        *(uint4*)&Qh[r * AQ_STR + c] = *(const uint4*)(qbase + (size_t)r * HID + c);
    }
    if (tid < 64) { mrow[tid] = -INFINITY; lrow[tid] = 0.f; }

    float out[8][4];
    #pragma unroll
    for (int ni = 0; ni < 8; ni++)
        #pragma unroll
        for (int j = 0; j < 4; j++) out[ni][j] = 0.f;

    const float scale = 0.08838834764831845f;   // 1/sqrt(128)

    for (int kt2 = 0; kt2 <= qt; kt2++) {
        if (kt2 > 0) __syncthreads();   // previous iter done before overwrite

        const __half* kb = k + (size_t)(kt2 * 64) * KVDIM + kvh * HD;
        const __half* vb = v + (size_t)(kt2 * 64) * KVDIM + kvh * HD;
        #pragma unroll
        for (int i = 0; i < 4; i++) {
            int f = tid + i * 256;
            int r = f >> 4;
            int c = (f & 15) * 8;
            *(uint4*)&Kh[r * AQ_STR + c] = *(const uint4*)(kb + (size_t)r * KVDIM + c);
            *(uint4*)&Vh[r * AQ_STR + c] = *(const uint4*)(vb + (size_t)r * KVDIM + c);
        }
        __syncthreads();

        // ---- S = Q @ K^T (warp: 16 q x 32 keys, fp16 mma) ----
        float sfrag[4][4];
        #pragma unroll
        for (int ni = 0; ni < 4; ni++)
            #pragma unroll
            for (int j = 0; j < 4; j++) sfrag[ni][j] = 0.f;

        #pragma unroll
        for (int s = 0; s < 8; s++) {   // 8 x k16 over d=128
            uint32_t a[4], bq[2][4];
            {
                int row = wm + lr + (lg & 1) * 8;
                int ch  = s * 2 + (lg >> 1);
                ldm_x4(a, sQ + ((uint32_t)row * AQ_STR + (uint32_t)ch * 8) * 2u);
            }
            #pragma unroll
            for (int pr = 0; pr < 2; pr++) {
                int row = wnS + pr * 16 + lr + (lg >> 1) * 8;
                int ch  = s * 2 + (lg & 1);
                ldm_x4(bq[pr], sK + ((uint32_t)row * AQ_STR + (uint32_t)ch * 8) * 2u);
            }
            #pragma unroll
            for (int pr = 0; pr < 2; pr++) {
                mma_f16(sfrag[pr * 2 + 0], a, &bq[pr][0]);
                mma_f16(sfrag[pr * 2 + 1], a, &bq[pr][2]);
            }
        }

        // scale + causal mask (diagonal tile only) + store S (fp32)
        const bool diag = (kt2 == qt);
        #pragma unroll
        for (int ni = 0; ni < 4; ni++) {
            const int cl = wnS + ni * 8 + (lane & 3) * 2;
            #pragma unroll
            for (int rr = 0; rr < 2; rr++) {
                const int rl = wm + (lane >> 2) + rr * 8;
                float v0 = sfrag[ni][rr * 2 + 0] * scale;
                float v1 = sfrag[ni][rr * 2 + 1] * scale;
                if (diag) {
                    if (cl > rl)     v0 += -1.0e9f;
                    if (cl + 1 > rl) v1 += -1.0e9f;
                }
                S[rl * AS_STR + cl]     = v0;
                S[rl * AS_STR + cl + 1] = v1;
            }
        }
        __syncthreads();

        // ---- online softmax: 4 threads per row; write P as half ----
        {
            const int r   = tid >> 2;
            const int sub = tid & 3;
            float* srow = &S[r * AS_STR + sub * 16];
            __half* prow = &Ph[r * AP_STR + sub * 16];
            float m_old = mrow[r];
            float mx = m_old;
            #pragma unroll
            for (int c = 0; c < 16; c++) mx = fmaxf(mx, srow[c]);
            mx = fmaxf(mx, __shfl_xor_sync(0xffffffffu, mx, 1));
            mx = fmaxf(mx, __shfl_xor_sync(0xffffffffu, mx, 2));
            float sum = 0.f;
            #pragma unroll
            for (int c = 0; c < 16; c += 2) {
                float p0 = __expf(srow[c] - mx);
                float p1 = __expf(srow[c + 1] - mx);
                *(__half2*)&prow[c] = __floats2half2_rn(p0, p1);
                sum += p0 + p1;
            }
            sum += __shfl_xor_sync(0xffffffffu, sum, 1);
            sum += __shfl_xor_sync(0xffffffffu, sum, 2);
            if (sub == 0) {
                float alpha = __expf(m_old - mx);
                mrow[r] = mx;
                lrow[r] = lrow[r] * alpha + sum;
                arow[r] = alpha;
            }
        }
        __syncthreads();

        // ---- rescale accumulators, O += P @ V (warp: 16 q x 64 d) ----
        {
            const float al0 = arow[wm + (lane >> 2)];
            const float al1 = arow[wm + 8 + (lane >> 2)];
            #pragma unroll
            for (int ni = 0; ni < 8; ni++) {
                out[ni][0] *= al0; out[ni][1] *= al0;
                out[ni][2] *= al1; out[ni][3] *= al1;
            }
        }
        #pragma unroll
        for (int s = 0; s < 4; s++) {   // 4 x k16 over 64 keys
            uint32_t a[4];
            {
                int row = wm + lr + (lg & 1) * 8;
                int ch  = s * 2 + (lg >> 1);
                ldm_x4(a, sP + ((uint32_t)row * AP_STR + (uint32_t)ch * 8) * 2u);
            }
            #pragma unroll
            for (int nb = 0; nb < 4; nb++) {
                uint32_t bv[4];
                int row = s * 16 + (lg & 1) * 8 + lr;            // key row
                int col = wnO + nb * 16 + (lg >> 1) * 8;         // d col
                ldm_x4_t(bv, sV + ((uint32_t)row * AQ_STR + (uint32_t)col) * 2u);
                mma_f16(out[nb * 2 + 0], a, &bv[0]);
                mma_f16(out[nb * 2 + 1], a, &bv[2]);
            }
        }
    }

    __syncthreads();
    // ---- epilogue: divide by l, write ctx as fp16 ----
    {
        const float inv0 = 1.f / lrow[wm + (lane >> 2)];
        const float inv1 = 1.f / lrow[wm + 8 + (lane >> 2)];
        const int row0 = qt * 64 + wm + (lane >> 2);
        #pragma unroll
        for (int ni = 0; ni < 8; ni++) {
            const int col = h * HD + wnO + ni * 8 + (lane & 3) * 2;
            __half2 h0 = __floats2half2_rn(out[ni][0] * inv0, out[ni][1] * inv0);
            __half2 h1 = __floats2half2_rn(out[ni][2] * inv1, out[ni][3] * inv1);
            *(__half2*)(ctx + (size_t)row0 * HID + col) = h0;
            *(__half2*)(ctx + (size_t)(row0 + 8) * HID + col) = h1;
        }
    }
}

// ---------------- host launcher ----------------
extern "C" void kernel_launch(void* const* d_in, const int* in_sizes, int n_in,
                              void* d_out, int out_size)
{
    const float* hs = (const float*)d_in[0];
    const float* wq = (const float*)d_in[2];
    const float* bq = (const float*)d_in[3];
    const float* wk = (const float*)d_in[4];
    const float* bk = (const float*)d_in[5];
    const float* wv = (const float*)d_in[6];
    const float* bv = (const float*)d_in[7];
    const float* wo = (const float*)d_in[8];
    float* out = (float*)d_out;

    float *q, *k, *v, *cosd, *sind;
    __half *qh, *kh, *vh, *ctx_h, *hs_h, *wq_h, *wk_h, *wv_h, *wo_h;
    cudaGetSymbolAddress((void**)&q,     g_q);
    cudaGetSymbolAddress((void**)&k,     g_k);
    cudaGetSymbolAddress((void**)&v,     g_v);
    cudaGetSymbolAddress((void**)&qh,    g_qh);
    cudaGetSymbolAddress((void**)&kh,    g_kh);
    cudaGetSymbolAddress((void**)&vh,    g_vh);
    cudaGetSymbolAddress((void**)&ctx_h, g_ctx_h);
    cudaGetSymbolAddress((void**)&hs_h,  g_hs_h);
    cudaGetSymbolAddress((void**)&wq_h,  g_wq_h);
    cudaGetSymbolAddress((void**)&wk_h,  g_wk_h);
    cudaGetSymbolAddress((void**)&wv_h,  g_wv_h);
    cudaGetSymbolAddress((void**)&wo_h,  g_wo_h);
    cudaGetSymbolAddress((void**)&cosd,  g_cos);
    cudaGetSymbolAddress((void**)&sind,  g_sin);

    // fp16 operand conversion
    cvt_half<<<(SEQ * HID / 4 + 255) / 256, 256>>>(hs, hs_h, SEQ * HID / 4);
    cvt_half<<<(HID * HID / 4 + 255) / 256, 256>>>(wq, wq_h, HID * HID / 4);
    cvt_half<<<(KVDIM * HID / 4 + 255) / 256, 256>>>(wk, wk_h, KVDIM * HID / 4);
    cvt_half<<<(KVDIM * HID / 4 + 255) / 256, 256>>>(wv, wv_h, KVDIM * HID / 4);
    cvt_half<<<(HID * HID / 4 + 255) / 256, 256>>>(wo, wo_h, HID * HID / 4);
    rope_tables<<<(SEQ * 64) / 256, 256>>>(cosd, sind);

    // projections (fp16 mma, fp32 out)
    gemm_f16<<<dim3(HID / 128,   SEQ / 128), 256>>>(hs_h, wq_h, bq, q, SEQ, HID,   HID);
    gemm_f16<<<dim3(KVDIM / 128, SEQ / 128), 256>>>(hs_h, wk_h, bk, k, SEQ, KVDIM, HID);
    gemm_f16<<<dim3(KVDIM / 128, SEQ / 128), 256>>>(hs_h, wv_h, bv, v, SEQ, KVDIM, HID);

    // rope (fp32 math, single rounding to half) + v fp32->half
    rope_apply<<<(SEQ * NH  * 64) / 256, 256>>>(q, qh, cosd, sind, NH);
    rope_apply<<<(SEQ * NKV * 64) / 256, 256>>>(k, kh, cosd, sind, NKV);
    cvt_half<<<(SEQ * KVDIM / 4 + 255) / 256, 256>>>(v, vh, SEQ * KVDIM / 4);

    // attention (fp16 mma + ldmatrix)
    cudaFuncSetAttribute(attn_f16, cudaFuncAttributeMaxDynamicSharedMemorySize, ATTN_SMEM_BYTES);
    attn_f16<<<dim3(SEQ / 64, NH), 256, ATTN_SMEM_BYTES>>>(qh, kh, vh, ctx_h);

    // output projection (fp16 mma, fp32 out)
    gemm_f16<<<dim3(HID / 128, SEQ / 128), 256>>>(ctx_h, wo_h, nullptr, out, SEQ, HID, HID);
}

// round 7
// speedup vs baseline: 7.1918x; 1.2174x over previous
#include <cuda_runtime.h>
#include <cuda_fp16.h>
#include <math.h>
#include <stdint.h>

#define SEQ   2048
#define HID   3584
#define NH    28
#define NKV   4
#define HD    128
#define KVDIM 512   // NKV * HD

// ---------------- scratch (no allocations allowed) ----------------
__device__ float  g_q[SEQ * HID];
__device__ float  g_k[SEQ * KVDIM];
__device__ float  g_v[SEQ * KVDIM];
__device__ __half g_qh[SEQ * HID];
__device__ __half g_kh[SEQ * KVDIM];
__device__ __half g_vh[SEQ * KVDIM];
__device__ __half g_ctx_h[SEQ * HID];
__device__ __half g_hs_h[SEQ * HID];
__device__ __half g_wq_h[(size_t)HID * HID];
__device__ __half g_wk_h[(size_t)KVDIM * HID];
__device__ __half g_wv_h[(size_t)KVDIM * HID];
__device__ __half g_wo_h[(size_t)HID * HID];
__device__ float  g_cos[SEQ * 64];
__device__ float  g_sin[SEQ * 64];

// ---------------- helpers ----------------
__device__ __forceinline__ uint32_t smem_u32(const void* p) {
    uint32_t a;
    asm("{ .reg .u64 t; cvta.to.shared.u64 t, %1; cvt.u32.u64 %0, t; }" : "=r"(a) : "l"(p));
    return a;
}

__device__ __forceinline__ void mma_f16(float* c, const uint32_t* a, const uint32_t* b) {
    asm volatile(
        "mma.sync.aligned.m16n8k16.row.col.f32.f16.f16.f32 "
        "{%0,%1,%2,%3}, {%4,%5,%6,%7}, {%8,%9}, {%0,%1,%2,%3};\n"
        : "+f"(c[0]), "+f"(c[1]), "+f"(c[2]), "+f"(c[3])
        : "r"(a[0]), "r"(a[1]), "r"(a[2]), "r"(a[3]), "r"(b[0]), "r"(b[1]));
}

__device__ __forceinline__ void ldm_x4(uint32_t* r, uint32_t addr) {
    asm volatile("ldmatrix.sync.aligned.m8n8.x4.shared.b16 {%0,%1,%2,%3}, [%4];"
                 : "=r"(r[0]), "=r"(r[1]), "=r"(r[2]), "=r"(r[3]) : "r"(addr));
}

__device__ __forceinline__ void ldm_x4_t(uint32_t* r, uint32_t addr) {
    asm volatile("ldmatrix.sync.aligned.m8n8.x4.trans.shared.b16 {%0,%1,%2,%3}, [%4];"
                 : "=r"(r[0]), "=r"(r[1]), "=r"(r[2]), "=r"(r[3]) : "r"(addr));
}

// ---------------- fp32 -> fp16 conversion pass ----------------
__global__ void cvt_half(const float* __restrict__ in, __half* __restrict__ out, int n4) {
    int i = blockIdx.x * blockDim.x + threadIdx.x;
    if (i < n4) {
        float4 v = ((const float4*)in)[i];
        ((__half2*)out)[i * 2 + 0] = __floats2half2_rn(v.x, v.y);
        ((__half2*)out)[i * 2 + 1] = __floats2half2_rn(v.z, v.w);
    }
}

// ---------------- FP16 GEMM body: 3-stage cp.async, 1 sync/iter ------------
#define GTILE_H 5120        // 128 rows * 40 halves per stage
#define GSTAGES 3
#define GEMM_SMEM_BYTES (2 * GSTAGES * GTILE_H * 2)

__device__ __forceinline__ void gemm_body(
    const __half* __restrict__ A, const __half* __restrict__ W,
    const float* __restrict__ bias, float* __restrict__ C,
    int N, int K, int bm, int bn, __half* As, __half* Bs)
{
    const int tid  = threadIdx.x;
    const int lane = tid & 31;
    const int wid  = tid >> 5;

    const int warp_m = (wid >> 1) * 32;
    const int warp_n = (wid & 1) * 64;

    const uint32_t sbA = smem_u32(As);
    const uint32_t sbB = smem_u32(Bs);

    int lrow[2], lch[2];
    #pragma unroll
    for (int p = 0; p < 2; p++) {
        int f = tid + p * 256;
        lrow[p] = f >> 2;
        lch[p]  = f & 3;
    }

    const int nt = K / 32;

    // prologue: stages 0 and 1
    #pragma unroll
    for (int st = 0; st < 2; st++) {
        const uint32_t ab = sbA + (uint32_t)st * (GTILE_H * 2);
        const uint32_t bb = sbB + (uint32_t)st * (GTILE_H * 2);
        #pragma unroll
        for (int p = 0; p < 2; p++) {
            uint32_t so = (uint32_t)lrow[p] * 80u + (uint32_t)lch[p] * 16u;
            const __half* ga = A + (size_t)(bm + lrow[p]) * K + (size_t)st * 32 + lch[p] * 8;
            const __half* gb = W + (size_t)(bn + lrow[p]) * K + (size_t)st * 32 + lch[p] * 8;
            asm volatile("cp.async.cg.shared.global [%0], [%1], 16;" :: "r"(ab + so), "l"(ga) : "memory");
            asm volatile("cp.async.cg.shared.global [%0], [%1], 16;" :: "r"(bb + so), "l"(gb) : "memory");
        }
        asm volatile("cp.async.commit_group;" ::: "memory");
    }

    float acc[2][8][4];
    #pragma unroll
    for (int mi = 0; mi < 2; mi++)
        #pragma unroll
        for (int ni = 0; ni < 8; ni++)
            #pragma unroll
            for (int j = 0; j < 4; j++) acc[mi][ni][j] = 0.f;

    const int lg = lane >> 3;
    const int lr = lane & 7;

    int cur = 0, nxt = 2;
    for (int i = 0; i < nt; i++) {
        if (i < nt - 1) asm volatile("cp.async.wait_group 1;" ::: "memory");
        else            asm volatile("cp.async.wait_group 0;" ::: "memory");
        __syncthreads();

        // issue stage i+2 (targets the buffer last read at iter i-1; safe post-sync)
        if (i + 2 < nt) {
            const uint32_t ab = sbA + (uint32_t)nxt * (GTILE_H * 2);
            const uint32_t bb = sbB + (uint32_t)nxt * (GTILE_H * 2);
            #pragma unroll
            for (int p = 0; p < 2; p++) {
                uint32_t so = (uint32_t)lrow[p] * 80u + (uint32_t)lch[p] * 16u;
                const __half* ga = A + (size_t)(bm + lrow[p]) * K + (size_t)(i + 2) * 32 + lch[p] * 8;
                const __half* gb = W + (size_t)(bn + lrow[p]) * K + (size_t)(i + 2) * 32 + lch[p] * 8;
                asm volatile("cp.async.cg.shared.global [%0], [%1], 16;" :: "r"(ab + so), "l"(ga) : "memory");
                asm volatile("cp.async.cg.shared.global [%0], [%1], 16;" :: "r"(bb + so), "l"(gb) : "memory");
            }
            asm volatile("cp.async.commit_group;" ::: "memory");
        }

        const uint32_t abuf = sbA + (uint32_t)cur * (GTILE_H * 2);
        const uint32_t bbuf = sbB + (uint32_t)cur * (GTILE_H * 2);

        #pragma unroll
        for (int s = 0; s < 2; s++) {
            uint32_t a[2][4], bq[4][4];
            #pragma unroll
            for (int mi = 0; mi < 2; mi++) {
                int row = warp_m + mi * 16 + lr + (lg & 1) * 8;
                int ch  = s * 2 + (lg >> 1);
                ldm_x4(a[mi], abuf + (uint32_t)row * 80u + (uint32_t)ch * 16u);
            }
            #pragma unroll
            for (int pr = 0; pr < 4; pr++) {
                int row = warp_n + pr * 16 + lr + (lg >> 1) * 8;
                int ch  = s * 2 + (lg & 1);
                ldm_x4(bq[pr], bbuf + (uint32_t)row * 80u + (uint32_t)ch * 16u);
            }
            #pragma unroll
            for (int mi = 0; mi < 2; mi++)
                #pragma unroll
                for (int pr = 0; pr < 4; pr++) {
                    mma_f16(acc[mi][pr * 2 + 0], a[mi], &bq[pr][0]);
                    mma_f16(acc[mi][pr * 2 + 1], a[mi], &bq[pr][2]);
                }
        }

        cur = (cur + 1 == GSTAGES) ? 0 : cur + 1;
        nxt = (nxt + 1 == GSTAGES) ? 0 : nxt + 1;
    }

    #pragma unroll
    for (int ni = 0; ni < 8; ni++) {
        const int col = bn + warp_n + ni * 8 + (lane & 3) * 2;
        float b0 = 0.f, b1 = 0.f;
        if (bias) { b0 = bias[col]; b1 = bias[col + 1]; }
        #pragma unroll
        for (int mi = 0; mi < 2; mi++) {
            const int row = bm + warp_m + mi * 16 + (lane >> 2);
            float2 v0 = make_float2(acc[mi][ni][0] + b0, acc[mi][ni][1] + b1);
            float2 v1 = make_float2(acc[mi][ni][2] + b0, acc[mi][ni][3] + b1);
            *(float2*)(C + (size_t)row * N + col) = v0;
            *(float2*)(C + (size_t)(row + 8) * N + col) = v1;
        }
    }
}

// generic GEMM (O-projection)
__global__ __launch_bounds__(256, 2) void gemm_f16(
    const __half* __restrict__ A, const __half* __restrict__ W,
    const float* __restrict__ bias, float* __restrict__ C,
    int M, int N, int K)
{
    extern __shared__ __align__(16) __half gsh[];
    gemm_body(A, W, bias, C, N, K, blockIdx.y * 128, blockIdx.x * 128,
              gsh, gsh + GSTAGES * GTILE_H);
}

// fused Q/K/V projection: 36 block-cols (28 Q + 4 K + 4 V)
__global__ __launch_bounds__(256, 2) void gemm_qkv(
    const __half* __restrict__ A,
    const __half* __restrict__ wq, const __half* __restrict__ wk, const __half* __restrict__ wv,
    const float* __restrict__ bq, const float* __restrict__ bk, const float* __restrict__ bv,
    float* __restrict__ q, float* __restrict__ k, float* __restrict__ v)
{
    extern __shared__ __align__(16) __half gsh[];
    const int bx = blockIdx.x;
    const __half* W; const float* bias; float* C; int N, bn;
    if (bx < HID / 128)                    { W = wq; bias = bq; C = q; N = HID;   bn = bx * 128; }
    else if (bx < HID / 128 + KVDIM / 128) { W = wk; bias = bk; C = k; N = KVDIM; bn = (bx - HID / 128) * 128; }
    else                                   { W = wv; bias = bv; C = v; N = KVDIM; bn = (bx - HID / 128 - KVDIM / 128) * 128; }
    gemm_body(A, W, bias, C, N, HID, blockIdx.y * 128, bn,
              gsh, gsh + GSTAGES * GTILE_H);
}

// ---------------- RoPE tables + apply ----------------
__global__ void rope_tables(float* __restrict__ cosd, float* __restrict__ sind) {
    int i = blockIdx.x * blockDim.x + threadIdx.x;
    int half = i & 63;
    int s = i >> 6;
    double inv = exp(-log(1.0e6) * (double)(2 * half) / 128.0);
    double ang = (double)s * inv;
    cosd[i] = (float)cos(ang);
    sind[i] = (float)sin(ang);
}

__global__ void rope_apply(const float* __restrict__ x, __half* __restrict__ xh,
                           const float* __restrict__ cosd, const float* __restrict__ sind,
                           int nheads)
{
    int idx = blockIdx.x * blockDim.x + threadIdx.x;
    int half = idx & 63;
    int h = (idx >> 6) % nheads;
    int s = idx / (64 * nheads);

    float c  = cosd[s * 64 + half];
    float si = sind[s * 64 + half];

    const float* base = x + (size_t)s * nheads * HD + h * HD;
    __half* baseh = xh + (size_t)s * nheads * HD + h * HD;
    float x1 = base[half];
    float x2 = base[half + 64];
    baseh[half]      = __float2half_rn(x1 * c - x2 * si);
    baseh[half + 64] = __float2half_rn(x2 * c + x1 * si);
}

// ---------------- Flash attention, FP16 mma + ldmatrix + reg prefetch ------
#define AQ_STR 136
#define AP_STR 72
#define AS_STR 68
#define ATTN_SMEM_BYTES ((3 * 64 * AQ_STR + 64 * AP_STR) * 2 + (64 * AS_STR + 192) * 4)

__global__ __launch_bounds__(256, 2) void attn_f16(
    const __half* __restrict__ q, const __half* __restrict__ k,
    const __half* __restrict__ v, __half* __restrict__ ctx)
{
    extern __shared__ __align__(16) char smraw[];
    __half* Qh = (__half*)smraw;
    __half* Kh = Qh + 64 * AQ_STR;
    __half* Vh = Kh + 64 * AQ_STR;
    __half* Ph = Vh + 64 * AQ_STR;
    float*  S  = (float*)(Ph + 64 * AP_STR);
    float* mrow = S + 64 * AS_STR;
    float* lrow = mrow + 64;
    float* arow = lrow + 64;

    const int qt  = gridDim.x - 1 - blockIdx.x;   // heavy tiles first
    const int h   = blockIdx.y;
    const int kvh = h / 7;
    const int tid  = threadIdx.x;
    const int lane = tid & 31;
    const int wid  = tid >> 5;

    const int wm  = (wid & 3) * 16;
    const int wnS = (wid >> 2) * 32;
    const int wnO = (wid >> 2) * 64;

    const int lg = lane >> 3;
    const int lr = lane & 7;

    const uint32_t sQ = smem_u32(Qh);
    const uint32_t sK = smem_u32(Kh);
    const uint32_t sV = smem_u32(Vh);
    const uint32_t sP = smem_u32(Ph);

    // per-thread K/V tile slice addressing (4 x uint4 each)
    int trow[4], tcol[4];
    #pragma unroll
    for (int i = 0; i < 4; i++) {
        int f = tid + i * 256;
        trow[i] = f >> 4;
        tcol[i] = (f & 15) * 8;
    }

    // ---- load Q tile ----
    const __half* qbase = q + (size_t)(qt * 64) * HID + h * HD;
    #pragma unroll
    for (int i = 0; i < 4; i++)
        *(uint4*)&Qh[trow[i] * AQ_STR + tcol[i]] =
            *(const uint4*)(qbase + (size_t)trow[i] * HID + tcol[i]);
    if (tid < 64) { mrow[tid] = -INFINITY; lrow[tid] = 0.f; }

    float out[8][4];
    #pragma unroll
    for (int ni = 0; ni < 8; ni++)
        #pragma unroll
        for (int j = 0; j < 4; j++) out[ni][j] = 0.f;

    const float scale = 0.08838834764831845f;

    // ---- prefetch K/V tile 0 into registers ----
    uint4 rk[4], rv[4];
    {
        const __half* kb = k + kvh * HD;
        const __half* vb = v + kvh * HD;
        #pragma unroll
        for (int i = 0; i < 4; i++) {
            rk[i] = *(const uint4*)(kb + (size_t)trow[i] * KVDIM + tcol[i]);
            rv[i] = *(const uint4*)(vb + (size_t)trow[i] * KVDIM + tcol[i]);
        }
    }

    for (int kt2 = 0; kt2 <= qt; kt2++) {
        if (kt2 > 0) __syncthreads();   // prev iter fully done before overwrite

        // store prefetched tile to smem
        #pragma unroll
        for (int i = 0; i < 4; i++) {
            *(uint4*)&Kh[trow[i] * AQ_STR + tcol[i]] = rk[i];
            *(uint4*)&Vh[trow[i] * AQ_STR + tcol[i]] = rv[i];
        }
        // issue next tile's loads (overlap with compute below)
        if (kt2 < qt) {
            const __half* kb = k + (size_t)((kt2 + 1) * 64) * KVDIM + kvh * HD;
            const __half* vb = v + (size_t)((kt2 + 1) * 64) * KVDIM + kvh * HD;
            #pragma unroll
            for (int i = 0; i < 4; i++) {
                rk[i] = *(const uint4*)(kb + (size_t)trow[i] * KVDIM + tcol[i]);
                rv[i] = *(const uint4*)(vb + (size_t)trow[i] * KVDIM + tcol[i]);
            }
        }
        __syncthreads();

        // ---- S = Q @ K^T ----
        float sfrag[4][4];
        #pragma unroll
        for (int ni = 0; ni < 4; ni++)
            #pragma unroll
            for (int j = 0; j < 4; j++) sfrag[ni][j] = 0.f;

        #pragma unroll
        for (int s = 0; s < 8; s++) {
            uint32_t a[4], bq[2][4];
            {
                int row = wm + lr + (lg & 1) * 8;
                int ch  = s * 2 + (lg >> 1);
                ldm_x4(a, sQ + ((uint32_t)row * AQ_STR + (uint32_t)ch * 8) * 2u);
            }
            #pragma unroll
            for (int pr = 0; pr < 2; pr++) {
                int row = wnS + pr * 16 + lr + (lg >> 1) * 8;
                int ch  = s * 2 + (lg & 1);
                ldm_x4(bq[pr], sK + ((uint32_t)row * AQ_STR + (uint32_t)ch * 8) * 2u);
            }
            #pragma unroll
            for (int pr = 0; pr < 2; pr++) {
                mma_f16(sfrag[pr * 2 + 0], a, &bq[pr][0]);
                mma_f16(sfrag[pr * 2 + 1], a, &bq[pr][2]);
            }
        }

        const bool diag = (kt2 == qt);
        #pragma unroll
        for (int ni = 0; ni < 4; ni++) {
            const int cl = wnS + ni * 8 + (lane & 3) * 2;
            #pragma unroll
            for (int rr = 0; rr < 2; rr++) {
                const int rl = wm + (lane >> 2) + rr * 8;
                float v0 = sfrag[ni][rr * 2 + 0] * scale;
                float v1 = sfrag[ni][rr * 2 + 1] * scale;
                if (diag) {
                    if (cl > rl)     v0 += -1.0e9f;
                    if (cl + 1 > rl) v1 += -1.0e9f;
                }
                S[rl * AS_STR + cl]     = v0;
                S[rl * AS_STR + cl + 1] = v1;
            }
        }
        __syncthreads();

        // ---- online softmax: 4 threads per row; write P as half ----
        {
            const int r   = tid >> 2;
            const int sub = tid & 3;
            float* srow = &S[r * AS_STR + sub * 16];
            __half* prow = &Ph[r * AP_STR + sub * 16];
            float m_old = mrow[r];
            float mx = m_old;
            #pragma unroll
            for (int c = 0; c < 16; c++) mx = fmaxf(mx, srow[c]);
            mx = fmaxf(mx, __shfl_xor_sync(0xffffffffu, mx, 1));
            mx = fmaxf(mx, __shfl_xor_sync(0xffffffffu, mx, 2));
            float sum = 0.f;
            #pragma unroll
            for (int c = 0; c < 16; c += 2) {
                float p0 = __expf(srow[c] - mx);
                float p1 = __expf(srow[c + 1] - mx);
                *(__half2*)&prow[c] = __floats2half2_rn(p0, p1);
                sum += p0 + p1;
            }
            sum += __shfl_xor_sync(0xffffffffu, sum, 1);
            sum += __shfl_xor_sync(0xffffffffu, sum, 2);
            if (sub == 0) {
                float alpha = __expf(m_old - mx);
                mrow[r] = mx;
                lrow[r] = lrow[r] * alpha + sum;
                arow[r] = alpha;
            }
        }
        __syncthreads();

        // ---- rescale accumulators, O += P @ V ----
        {
            const float al0 = arow[wm + (lane >> 2)];
            const float al1 = arow[wm + 8 + (lane >> 2)];
            #pragma unroll
            for (int ni = 0; ni < 8; ni++) {
                out[ni][0] *= al0; out[ni][1] *= al0;
                out[ni][2] *= al1; out[ni][3] *= al1;
            }
        }
        #pragma unroll
        for (int s = 0; s < 4; s++) {
            uint32_t a[4];
            {
                int row = wm + lr + (lg & 1) * 8;
                int ch  = s * 2 + (lg >> 1);
                ldm_x4(a, sP + ((uint32_t)row * AP_STR + (uint32_t)ch * 8) * 2u);
            }
            #pragma unroll
            for (int nb = 0; nb < 4; nb++) {
                uint32_t bv2[4];
                int row = s * 16 + (lg & 1) * 8 + lr;
                int col = wnO + nb * 16 + (lg >> 1) * 8;
                ldm_x4_t(bv2, sV + ((uint32_t)row * AQ_STR + (uint32_t)col) * 2u);
                mma_f16(out[nb * 2 + 0], a, &bv2[0]);
                mma_f16(out[nb * 2 + 1], a, &bv2[2]);
            }
        }
    }

    __syncthreads();
    // ---- epilogue ----
    {
        const float inv0 = 1.f / lrow[wm + (lane >> 2)];
        const float inv1 = 1.f / lrow[wm + 8 + (lane >> 2)];
        const int row0 = qt * 64 + wm + (lane >> 2);
        #pragma unroll
        for (int ni = 0; ni < 8; ni++) {
            const int col = h * HD + wnO + ni * 8 + (lane & 3) * 2;
            __half2 h0 = __floats2half2_rn(out[ni][0] * inv0, out[ni][1] * inv0);
            __half2 h1 = __floats2half2_rn(out[ni][2] * inv1, out[ni][3] * inv1);
            *(__half2*)(ctx + (size_t)row0 * HID + col) = h0;
            *(__half2*)(ctx + (size_t)(row0 + 8) * HID + col) = h1;
        }
    }
}

// ---------------- host launcher ----------------
extern "C" void kernel_launch(void* const* d_in, const int* in_sizes, int n_in,
                              void* d_out, int out_size)
{
    const float* hs = (const float*)d_in[0];
    const float* wq = (const float*)d_in[2];
    const float* bq = (const float*)d_in[3];
    const float* wk = (const float*)d_in[4];
    const float* bk = (const float*)d_in[5];
    const float* wv = (const float*)d_in[6];
    const float* bv = (const float*)d_in[7];
    const float* wo = (const float*)d_in[8];
    float* out = (float*)d_out;

    float *q, *k, *v, *cosd, *sind;
    __half *qh, *kh, *vh, *ctx_h, *hs_h, *wq_h, *wk_h, *wv_h, *wo_h;
    cudaGetSymbolAddress((void**)&q,     g_q);
    cudaGetSymbolAddress((void**)&k,     g_k);
    cudaGetSymbolAddress((void**)&v,     g_v);
    cudaGetSymbolAddress((void**)&qh,    g_qh);
    cudaGetSymbolAddress((void**)&kh,    g_kh);
    cudaGetSymbolAddress((void**)&vh,    g_vh);
    cudaGetSymbolAddress((void**)&ctx_h, g_ctx_h);
    cudaGetSymbolAddress((void**)&hs_h,  g_hs_h);
    cudaGetSymbolAddress((void**)&wq_h,  g_wq_h);
    cudaGetSymbolAddress((void**)&wk_h,  g_wk_h);
    cudaGetSymbolAddress((void**)&wv_h,  g_wv_h);
    cudaGetSymbolAddress((void**)&wo_h,  g_wo_h);
    cudaGetSymbolAddress((void**)&cosd,  g_cos);
    cudaGetSymbolAddress((void**)&sind,  g_sin);

    // fp16 operand conversion + rope tables
    cvt_half<<<(SEQ * HID / 4 + 255) / 256, 256>>>(hs, hs_h, SEQ * HID / 4);
    cvt_half<<<(HID * HID / 4 + 255) / 256, 256>>>(wq, wq_h, HID * HID / 4);
    cvt_half<<<(KVDIM * HID / 4 + 255) / 256, 256>>>(wk, wk_h, KVDIM * HID / 4);
    cvt_half<<<(KVDIM * HID / 4 + 255) / 256, 256>>>(wv, wv_h, KVDIM * HID / 4);
    cvt_half<<<(HID * HID / 4 + 255) / 256, 256>>>(wo, wo_h, HID * HID / 4);
    rope_tables<<<(SEQ * 64) / 256, 256>>>(cosd, sind);

    cudaFuncSetAttribute(gemm_qkv, cudaFuncAttributeMaxDynamicSharedMemorySize, GEMM_SMEM_BYTES);
    cudaFuncSetAttribute(gemm_f16, cudaFuncAttributeMaxDynamicSharedMemorySize, GEMM_SMEM_BYTES);

    // fused Q/K/V projection
    gemm_qkv<<<dim3((HID + 2 * KVDIM) / 128, SEQ / 128), 256, GEMM_SMEM_BYTES>>>(
        hs_h, wq_h, wk_h, wv_h, bq, bk, bv, q, k, v);

    // rope + v conversion
    rope_apply<<<(SEQ * NH  * 64) / 256, 256>>>(q, qh, cosd, sind, NH);
    rope_apply<<<(SEQ * NKV * 64) / 256, 256>>>(k, kh, cosd, sind, NKV);
    cvt_half<<<(SEQ * KVDIM / 4 + 255) / 256, 256>>>(v, vh, SEQ * KVDIM / 4);

    // attention
    cudaFuncSetAttribute(attn_f16, cudaFuncAttributeMaxDynamicSharedMemorySize, ATTN_SMEM_BYTES);
    attn_f16<<<dim3(SEQ / 64, NH), 256, ATTN_SMEM_BYTES>>>(qh, kh, vh, ctx_h);

    // output projection
    gemm_f16<<<dim3(HID / 128, SEQ / 128), 256, GEMM_SMEM_BYTES>>>(
        ctx_h, wo_h, nullptr, out, SEQ, HID, HID);
}

// round 9
// speedup vs baseline: 7.9131x; 1.1003x over previous
#include <cuda_runtime.h>
#include <cuda_fp16.h>
#include <math.h>
#include <stdint.h>

#define SEQ   2048
#define HID   3584
#define NH    28
#define NKV   4
#define HD    128
#define KVDIM 512   // NKV * HD

// ---------------- scratch (no allocations allowed) ----------------
__device__ float  g_q[SEQ * HID];
__device__ float  g_k[SEQ * KVDIM];
__device__ __half g_qh[SEQ * HID];
__device__ __half g_kh[SEQ * KVDIM];
__device__ __half g_vh[SEQ * KVDIM];
__device__ __half g_ctx_h[SEQ * HID];
__device__ __half g_hs_h[SEQ * HID];
__device__ __half g_wq_h[(size_t)HID * HID];
__device__ __half g_wk_h[(size_t)KVDIM * HID];
__device__ __half g_wv_h[(size_t)KVDIM * HID];
__device__ __half g_wo_h[(size_t)HID * HID];
__device__ float  g_cos[SEQ * 64];
__device__ float  g_sin[SEQ * 64];

// ---------------- helpers ----------------
__device__ __forceinline__ uint32_t smem_u32(const void* p) {
    uint32_t a;
    asm("{ .reg .u64 t; cvta.to.shared.u64 t, %1; cvt.u32.u64 %0, t; }" : "=r"(a) : "l"(p));
    return a;
}

__device__ __forceinline__ uint32_t h2_as_u32(__half2 h) {
    return *reinterpret_cast<uint32_t*>(&h);
}

__device__ __forceinline__ void mma_f16(float* c, const uint32_t* a, const uint32_t* b) {
    asm volatile(
        "mma.sync.aligned.m16n8k16.row.col.f32.f16.f16.f32 "
        "{%0,%1,%2,%3}, {%4,%5,%6,%7}, {%8,%9}, {%0,%1,%2,%3};\n"
        : "+f"(c[0]), "+f"(c[1]), "+f"(c[2]), "+f"(c[3])
        : "r"(a[0]), "r"(a[1]), "r"(a[2]), "r"(a[3]), "r"(b[0]), "r"(b[1]));
}

__device__ __forceinline__ void ldm_x4(uint32_t* r, uint32_t addr) {
    asm volatile("ldmatrix.sync.aligned.m8n8.x4.shared.b16 {%0,%1,%2,%3}, [%4];"
                 : "=r"(r[0]), "=r"(r[1]), "=r"(r[2]), "=r"(r[3]) : "r"(addr));
}

__device__ __forceinline__ void ldm_x4_t(uint32_t* r, uint32_t addr) {
    asm volatile("ldmatrix.sync.aligned.m8n8.x4.trans.shared.b16 {%0,%1,%2,%3}, [%4];"
                 : "=r"(r[0]), "=r"(r[1]), "=r"(r[2]), "=r"(r[3]) : "r"(addr));
}

// ---------------- fp32 -> fp16 conversion pass ----------------
__global__ void cvt_half(const float* __restrict__ in, __half* __restrict__ out, int n4) {
    int i = blockIdx.x * blockDim.x + threadIdx.x;
    if (i < n4) {
        float4 v = ((const float4*)in)[i];
        ((__half2*)out)[i * 2 + 0] = __floats2half2_rn(v.x, v.y);
        ((__half2*)out)[i * 2 + 1] = __floats2half2_rn(v.z, v.w);
    }
}

// ---------------- FP16 GEMM body: 3-stage cp.async, 1 sync/iter ------------
#define GTILE_H 5120        // 128 rows * 40 halves per stage
#define GSTAGES 3
#define GEMM_SMEM_BYTES (2 * GSTAGES * GTILE_H * 2)

__device__ __forceinline__ void gemm_body(
    const __half* __restrict__ A, const __half* __restrict__ W,
    const float* __restrict__ bias, float* __restrict__ Cf, __half* __restrict__ Ch,
    int N, int K, int bm, int bn, __half* As, __half* Bs)
{
    const int tid  = threadIdx.x;
    const int lane = tid & 31;
    const int wid  = tid >> 5;

    const int warp_m = (wid >> 1) * 32;
    const int warp_n = (wid & 1) * 64;

    const uint32_t sbA = smem_u32(As);
    const uint32_t sbB = smem_u32(Bs);

    int lrow[2], lch[2];
    #pragma unroll
    for (int p = 0; p < 2; p++) {
        int f = tid + p * 256;
        lrow[p] = f >> 2;
        lch[p]  = f & 3;
    }

    const int nt = K / 32;

    #pragma unroll
    for (int st = 0; st < 2; st++) {
        const uint32_t ab = sbA + (uint32_t)st * (GTILE_H * 2);
        const uint32_t bb = sbB + (uint32_t)st * (GTILE_H * 2);
        #pragma unroll
        for (int p = 0; p < 2; p++) {
            uint32_t so = (uint32_t)lrow[p] * 80u + (uint32_t)lch[p] * 16u;
            const __half* ga = A + (size_t)(bm + lrow[p]) * K + (size_t)st * 32 + lch[p] * 8;
            const __half* gb = W + (size_t)(bn + lrow[p]) * K + (size_t)st * 32 + lch[p] * 8;
            asm volatile("cp.async.cg.shared.global [%0], [%1], 16;" :: "r"(ab + so), "l"(ga) : "memory");
            asm volatile("cp.async.cg.shared.global [%0], [%1], 16;" :: "r"(bb + so), "l"(gb) : "memory");
        }
        asm volatile("cp.async.commit_group;" ::: "memory");
    }

    float acc[2][8][4];
    #pragma unroll
    for (int mi = 0; mi < 2; mi++)
        #pragma unroll
        for (int ni = 0; ni < 8; ni++)
            #pragma unroll
            for (int j = 0; j < 4; j++) acc[mi][ni][j] = 0.f;

    const int lg = lane >> 3;
    const int lr = lane & 7;

    int cur = 0, nxt = 2;
    for (int i = 0; i < nt; i++) {
        if (i < nt - 1) asm volatile("cp.async.wait_group 1;" ::: "memory");
        else            asm volatile("cp.async.wait_group 0;" ::: "memory");
        __syncthreads();

        if (i + 2 < nt) {
            const uint32_t ab = sbA + (uint32_t)nxt * (GTILE_H * 2);
            const uint32_t bb = sbB + (uint32_t)nxt * (GTILE_H * 2);
            #pragma unroll
            for (int p = 0; p < 2; p++) {
                uint32_t so = (uint32_t)lrow[p] * 80u + (uint32_t)lch[p] * 16u;
                const __half* ga = A + (size_t)(bm + lrow[p]) * K + (size_t)(i + 2) * 32 + lch[p] * 8;
                const __half* gb = W + (size_t)(bn + lrow[p]) * K + (size_t)(i + 2) * 32 + lch[p] * 8;
                asm volatile("cp.async.cg.shared.global [%0], [%1], 16;" :: "r"(ab + so), "l"(ga) : "memory");
                asm volatile("cp.async.cg.shared.global [%0], [%1], 16;" :: "r"(bb + so), "l"(gb) : "memory");
            }
            asm volatile("cp.async.commit_group;" ::: "memory");
        }

        const uint32_t abuf = sbA + (uint32_t)cur * (GTILE_H * 2);
        const uint32_t bbuf = sbB + (uint32_t)cur * (GTILE_H * 2);

        #pragma unroll
        for (int s = 0; s < 2; s++) {
            uint32_t a[2][4], bq[4][4];
            #pragma unroll
            for (int mi = 0; mi < 2; mi++) {
                int row = warp_m + mi * 16 + lr + (lg & 1) * 8;
                int ch  = s * 2 + (lg >> 1);
                ldm_x4(a[mi], abuf + (uint32_t)row * 80u + (uint32_t)ch * 16u);
            }
            #pragma unroll
            for (int pr = 0; pr < 4; pr++) {
                int row = warp_n + pr * 16 + lr + (lg >> 1) * 8;
                int ch  = s * 2 + (lg & 1);
                ldm_x4(bq[pr], bbuf + (uint32_t)row * 80u + (uint32_t)ch * 16u);
            }
            #pragma unroll
            for (int mi = 0; mi < 2; mi++)
                #pragma unroll
                for (int pr = 0; pr < 4; pr++) {
                    mma_f16(acc[mi][pr * 2 + 0], a[mi], &bq[pr][0]);
                    mma_f16(acc[mi][pr * 2 + 1], a[mi], &bq[pr][2]);
                }
        }

        cur = (cur + 1 == GSTAGES) ? 0 : cur + 1;
        nxt = (nxt + 1 == GSTAGES) ? 0 : nxt + 1;
    }

    #pragma unroll
    for (int ni = 0; ni < 8; ni++) {
        const int col = bn + warp_n + ni * 8 + (lane & 3) * 2;
        float b0 = 0.f, b1 = 0.f;
        if (bias) { b0 = bias[col]; b1 = bias[col + 1]; }
        #pragma unroll
        for (int mi = 0; mi < 2; mi++) {
            const int row = bm + warp_m + mi * 16 + (lane >> 2);
            if (Ch) {
                *(__half2*)(Ch + (size_t)row * N + col) =
                    __floats2half2_rn(acc[mi][ni][0] + b0, acc[mi][ni][1] + b1);
                *(__half2*)(Ch + (size_t)(row + 8) * N + col) =
                    __floats2half2_rn(acc[mi][ni][2] + b0, acc[mi][ni][3] + b1);
            } else {
                float2 v0 = make_float2(acc[mi][ni][0] + b0, acc[mi][ni][1] + b1);
                float2 v1 = make_float2(acc[mi][ni][2] + b0, acc[mi][ni][3] + b1);
                *(float2*)(Cf + (size_t)row * N + col) = v0;
                *(float2*)(Cf + (size_t)(row + 8) * N + col) = v1;
            }
        }
    }
}

// generic GEMM (O-projection, fp32 out)
__global__ __launch_bounds__(256, 2) void gemm_f16(
    const __half* __restrict__ A, const __half* __restrict__ W,
    const float* __restrict__ bias, float* __restrict__ C,
    int M, int N, int K)
{
    extern __shared__ __align__(16) __half gsh[];
    gemm_body(A, W, bias, C, (__half*)0, N, K, blockIdx.y * 128, blockIdx.x * 128,
              gsh, gsh + GSTAGES * GTILE_H);
}

// fused Q/K/V projection: 36 block-cols; V written directly as fp16
__global__ __launch_bounds__(256, 2) void gemm_qkv(
    const __half* __restrict__ A,
    const __half* __restrict__ wq, const __half* __restrict__ wk, const __half* __restrict__ wv,
    const float* __restrict__ bq, const float* __restrict__ bk, const float* __restrict__ bv,
    float* __restrict__ q, float* __restrict__ k, __half* __restrict__ vh)
{
    extern __shared__ __align__(16) __half gsh[];
    const int bx = blockIdx.x;
    const __half* W; const float* bias; float* Cf; __half* Ch; int N, bn;
    if (bx < HID / 128) {
        W = wq; bias = bq; Cf = q; Ch = 0; N = HID; bn = bx * 128;
    } else if (bx < HID / 128 + KVDIM / 128) {
        W = wk; bias = bk; Cf = k; Ch = 0; N = KVDIM; bn = (bx - HID / 128) * 128;
    } else {
        W = wv; bias = bv; Cf = 0; Ch = vh; N = KVDIM; bn = (bx - HID / 128 - KVDIM / 128) * 128;
    }
    gemm_body(A, W, bias, Cf, Ch, N, HID, blockIdx.y * 128, bn,
              gsh, gsh + GSTAGES * GTILE_H);
}

// ---------------- RoPE tables + apply ----------------
__global__ void rope_tables(float* __restrict__ cosd, float* __restrict__ sind) {
    int i = blockIdx.x * blockDim.x + threadIdx.x;
    int half = i & 63;
    int s = i >> 6;
    double inv = exp(-log(1.0e6) * (double)(2 * half) / 128.0);
    double ang = (double)s * inv;
    cosd[i] = (float)cos(ang);
    sind[i] = (float)sin(ang);
}

__global__ void rope_apply(const float* __restrict__ x, __half* __restrict__ xh,
                           const float* __restrict__ cosd, const float* __restrict__ sind,
                           int nheads)
{
    int idx = blockIdx.x * blockDim.x + threadIdx.x;
    int half = idx & 63;
    int h = (idx >> 6) % nheads;
    int s = idx / (64 * nheads);

    float c  = cosd[s * 64 + half];
    float si = sind[s * 64 + half];

    const float* base = x + (size_t)s * nheads * HD + h * HD;
    __half* baseh = xh + (size_t)s * nheads * HD + h * HD;
    float x1 = base[half];
    float x2 = base[half + 64];
    baseh[half]      = __float2half_rn(x1 * c - x2 * si);
    baseh[half + 64] = __float2half_rn(x2 * c + x1 * si);
}

// ---------------- Flash attention (FA2): 128q block, warp = 16q x 64k ------
// Smem: Q[128][136], K[2][64][136], V[2][64][136]. Softmax fully in registers.
#define AQ_STR 136
#define ATTN_SMEM_BYTES ((128 * AQ_STR + 4 * 64 * AQ_STR) * 2)

__global__ __launch_bounds__(256, 2) void attn_f16(
    const __half* __restrict__ q, const __half* __restrict__ k,
    const __half* __restrict__ v, __half* __restrict__ ctx)
{
    extern __shared__ __align__(16) char smraw[];
    __half* Qh = (__half*)smraw;                    // [128][136]
    __half* Kh = Qh + 128 * AQ_STR;                 // [2][64][136]
    __half* Vh = Kh + 2 * 64 * AQ_STR;              // [2][64][136]

    const int qt  = gridDim.x - 1 - blockIdx.x;     // heavy tiles first
    const int h   = blockIdx.y;
    const int kvh = h / 7;
    const int tid  = threadIdx.x;
    const int lane = tid & 31;
    const int wid  = tid >> 5;

    const int wm = wid * 16;                        // warp's q-row base
    const int lg = lane >> 3;
    const int lr = lane & 7;
    const int qr = lane >> 2;                       // row-in-slab (0..7)
    const int qc = lane & 3;

    const uint32_t sQ = smem_u32(Qh);
    const uint32_t sK = smem_u32(Kh);
    const uint32_t sV = smem_u32(Vh);

    // K/V cp.async mapping: 64 rows x 128 cols = 1024 uint4; 4 per thread
    int trow[4], tcol[4];
    #pragma unroll
    for (int i = 0; i < 4; i++) {
        int f = tid + i * 256;
        trow[i] = f >> 4;
        tcol[i] = (f & 15) * 8;
    }

    const int nkt = 2 * qt + 2;

    // prologue: cp.async tile 0 into stage 0
    {
        const __half* kb = k + kvh * HD;
        const __half* vb = v + kvh * HD;
        #pragma unroll
        for (int i = 0; i < 4; i++) {
            uint32_t so = (uint32_t)trow[i] * (AQ_STR * 2) + (uint32_t)tcol[i] * 2;
            asm volatile("cp.async.cg.shared.global [%0], [%1], 16;"
                         :: "r"(sK + so), "l"(kb + (size_t)trow[i] * KVDIM + tcol[i]) : "memory");
            asm volatile("cp.async.cg.shared.global [%0], [%1], 16;"
                         :: "r"(sV + so), "l"(vb + (size_t)trow[i] * KVDIM + tcol[i]) : "memory");
        }
        asm volatile("cp.async.commit_group;" ::: "memory");
    }

    // load Q tile (128 rows)
    {
        const __half* qbase = q + (size_t)(qt * 128) * HID + h * HD;
        #pragma unroll
        for (int i = 0; i < 8; i++) {
            int f = tid + i * 256;
            int r = f >> 4;
            int c = (f & 15) * 8;
            *(uint4*)&Qh[r * AQ_STR + c] = *(const uint4*)(qbase + (size_t)r * HID + c);
        }
    }

    float out[16][4];
    #pragma unroll
    for (int ni = 0; ni < 16; ni++)
        #pragma unroll
        for (int j = 0; j < 4; j++) out[ni][j] = 0.f;
    float m0 = -INFINITY, m1 = -INFINITY, l0 = 0.f, l1 = 0.f;

    const float scale = 0.08838834764831845f;       // 1/sqrt(128)

    for (int kt = 0; kt < nkt; kt++) {
        asm volatile("cp.async.wait_group 0;" ::: "memory");
        __syncthreads();

        // issue next tile into the other stage (overlaps compute below)
        if (kt + 1 < nkt) {
            const uint32_t stoff = (uint32_t)((kt + 1) & 1) * (64 * AQ_STR * 2);
            const __half* kb = k + (size_t)((kt + 1) * 64) * KVDIM + kvh * HD;
            const __half* vb = v + (size_t)((kt + 1) * 64) * KVDIM + kvh * HD;
            #pragma unroll
            for (int i = 0; i < 4; i++) {
                uint32_t so = (uint32_t)trow[i] * (AQ_STR * 2) + (uint32_t)tcol[i] * 2 + stoff;
                asm volatile("cp.async.cg.shared.global [%0], [%1], 16;"
                             :: "r"(sK + so), "l"(kb + (size_t)trow[i] * KVDIM + tcol[i]) : "memory");
                asm volatile("cp.async.cg.shared.global [%0], [%1], 16;"
                             :: "r"(sV + so), "l"(vb + (size_t)trow[i] * KVDIM + tcol[i]) : "memory");
            }
            asm volatile("cp.async.commit_group;" ::: "memory");
        }

        const uint32_t kbuf = sK + (uint32_t)(kt & 1) * (64 * AQ_STR * 2);
        const uint32_t vbuf = sV + (uint32_t)(kt & 1) * (64 * AQ_STR * 2);

        // ---- S = Q @ K^T : sfrag[8] covers 64 keys ----
        float sfrag[8][4];
        #pragma unroll
        for (int ni = 0; ni < 8; ni++)
            #pragma unroll
            for (int j = 0; j < 4; j++) sfrag[ni][j] = 0.f;

        #pragma unroll
        for (int s = 0; s < 8; s++) {
            uint32_t a[4];
            {
                int row = wm + lr + (lg & 1) * 8;
                int ch  = s * 2 + (lg >> 1);
                ldm_x4(a, sQ + ((uint32_t)row * AQ_STR + (uint32_t)ch * 8) * 2u);
            }
            #pragma unroll
            for (int pr = 0; pr < 4; pr++) {
                uint32_t bq[4];
                int row = pr * 16 + lr + (lg >> 1) * 8;
                int ch  = s * 2 + (lg & 1);
                ldm_x4(bq, kbuf + ((uint32_t)row * AQ_STR + (uint32_t)ch * 8) * 2u);
                mma_f16(sfrag[pr * 2 + 0], a, &bq[0]);
                mma_f16(sfrag[pr * 2 + 1], a, &bq[2]);
            }
        }

        // ---- scale + causal mask ----
        const bool diag = (kt >= 2 * qt);
        const int qr0 = qt * 128 + wm + qr;
        #pragma unroll
        for (int ni = 0; ni < 8; ni++) {
            const int kc = kt * 64 + ni * 8 + qc * 2;
            sfrag[ni][0] *= scale; sfrag[ni][1] *= scale;
            sfrag[ni][2] *= scale; sfrag[ni][3] *= scale;
            if (diag) {
                if (kc > qr0)         sfrag[ni][0] += -1.0e9f;
                if (kc + 1 > qr0)     sfrag[ni][1] += -1.0e9f;
                if (kc > qr0 + 8)     sfrag[ni][2] += -1.0e9f;
                if (kc + 1 > qr0 + 8) sfrag[ni][3] += -1.0e9f;
            }
        }

        // ---- row max (quad reduce) + rescale ----
        float mx0 = m0, mx1 = m1;
        #pragma unroll
        for (int ni = 0; ni < 8; ni++) {
            mx0 = fmaxf(mx0, fmaxf(sfrag[ni][0], sfrag[ni][1]));
            mx1 = fmaxf(mx1, fmaxf(sfrag[ni][2], sfrag[ni][3]));
        }
        mx0 = fmaxf(mx0, __shfl_xor_sync(0xffffffffu, mx0, 1));
        mx0 = fmaxf(mx0, __shfl_xor_sync(0xffffffffu, mx0, 2));
        mx1 = fmaxf(mx1, __shfl_xor_sync(0xffffffffu, mx1, 1));
        mx1 = fmaxf(mx1, __shfl_xor_sync(0xffffffffu, mx1, 2));
        const float al0 = __expf(m0 - mx0);
        const float al1 = __expf(m1 - mx1);
        m0 = mx0; m1 = mx1;
        #pragma unroll
        for (int ni = 0; ni < 16; ni++) {
            out[ni][0] *= al0; out[ni][1] *= al0;
            out[ni][2] *= al1; out[ni][3] *= al1;
        }

        // ---- exp -> P frags; PV interleaved per k16-step ----
        float sum0 = 0.f, sum1 = 0.f;
        #pragma unroll
        for (int s = 0; s < 4; s++) {
            float p00 = __expf(sfrag[2*s][0]   - mx0), p01 = __expf(sfrag[2*s][1]   - mx0);
            float p10 = __expf(sfrag[2*s][2]   - mx1), p11 = __expf(sfrag[2*s][3]   - mx1);
            float p20 = __expf(sfrag[2*s+1][0] - mx0), p21 = __expf(sfrag[2*s+1][1] - mx0);
            float p30 = __expf(sfrag[2*s+1][2] - mx1), p31 = __expf(sfrag[2*s+1][3] - mx1);
            sum0 += p00 + p01 + p20 + p21;
            sum1 += p10 + p11 + p30 + p31;
            uint32_t pf[4];
            pf[0] = h2_as_u32(__floats2half2_rn(p00, p01));
            pf[1] = h2_as_u32(__floats2half2_rn(p10, p11));
            pf[2] = h2_as_u32(__floats2half2_rn(p20, p21));
            pf[3] = h2_as_u32(__floats2half2_rn(p30, p31));
            #pragma unroll
            for (int nb = 0; nb < 8; nb++) {
                uint32_t bv[4];
                int row = s * 16 + (lg & 1) * 8 + lr;        // key row
                int col = nb * 16 + (lg >> 1) * 8;           // d col
                ldm_x4_t(bv, vbuf + ((uint32_t)row * AQ_STR + (uint32_t)col) * 2u);
                mma_f16(out[nb * 2 + 0], pf, &bv[0]);
                mma_f16(out[nb * 2 + 1], pf, &bv[2]);
            }
        }
        sum0 += __shfl_xor_sync(0xffffffffu, sum0, 1);
        sum0 += __shfl_xor_sync(0xffffffffu, sum0, 2);
        sum1 += __shfl_xor_sync(0xffffffffu, sum1, 1);
        sum1 += __shfl_xor_sync(0xffffffffu, sum1, 2);
        l0 = l0 * al0 + sum0;
        l1 = l1 * al1 + sum1;
    }

    // ---- epilogue ----
    {
        const float inv0 = 1.f / l0;
        const float inv1 = 1.f / l1;
        const int row0 = qt * 128 + wm + qr;
        #pragma unroll
        for (int ni = 0; ni < 16; ni++) {
            const int col = h * HD + ni * 8 + qc * 2;
            *(__half2*)(ctx + (size_t)row0 * HID + col) =
                __floats2half2_rn(out[ni][0] * inv0, out[ni][1] * inv0);
            *(__half2*)(ctx + (size_t)(row0 + 8) * HID + col) =
                __floats2half2_rn(out[ni][2] * inv1, out[ni][3] * inv1);
        }
    }
}

// ---------------- host launcher ----------------
extern "C" void kernel_launch(void* const* d_in, const int* in_sizes, int n_in,
                              void* d_out, int out_size)
{
    const float* hs = (const float*)d_in[0];
    const float* wq = (const float*)d_in[2];
    const float* bq = (const float*)d_in[3];
    const float* wk = (const float*)d_in[4];
    const float* bk = (const float*)d_in[5];
    const float* wv = (const float*)d_in[6];
    const float* bv = (const float*)d_in[7];
    const float* wo = (const float*)d_in[8];
    float* out = (float*)d_out;

    float *q, *k, *cosd, *sind;
    __half *qh, *kh, *vh, *ctx_h, *hs_h, *wq_h, *wk_h, *wv_h, *wo_h;
    cudaGetSymbolAddress((void**)&q,     g_q);
    cudaGetSymbolAddress((void**)&k,     g_k);
    cudaGetSymbolAddress((void**)&qh,    g_qh);
    cudaGetSymbolAddress((void**)&kh,    g_kh);
    cudaGetSymbolAddress((void**)&vh,    g_vh);
    cudaGetSymbolAddress((void**)&ctx_h, g_ctx_h);
    cudaGetSymbolAddress((void**)&hs_h,  g_hs_h);
    cudaGetSymbolAddress((void**)&wq_h,  g_wq_h);
    cudaGetSymbolAddress((void**)&wk_h,  g_wk_h);
    cudaGetSymbolAddress((void**)&wv_h,  g_wv_h);
    cudaGetSymbolAddress((void**)&wo_h,  g_wo_h);
    cudaGetSymbolAddress((void**)&cosd,  g_cos);
    cudaGetSymbolAddress((void**)&sind,  g_sin);

    // fp16 operand conversion + rope tables
    cvt_half<<<(SEQ * HID / 4 + 255) / 256, 256>>>(hs, hs_h, SEQ * HID / 4);
    cvt_half<<<(HID * HID / 4 + 255) / 256, 256>>>(wq, wq_h, HID * HID / 4);
    cvt_half<<<(KVDIM * HID / 4 + 255) / 256, 256>>>(wk, wk_h, KVDIM * HID / 4);
    cvt_half<<<(KVDIM * HID / 4 + 255) / 256, 256>>>(wv, wv_h, KVDIM * HID / 4);
    cvt_half<<<(HID * HID / 4 + 255) / 256, 256>>>(wo, wo_h, HID * HID / 4);
    rope_tables<<<(SEQ * 64) / 256, 256>>>(cosd, sind);

    cudaFuncSetAttribute(gemm_qkv, cudaFuncAttributeMaxDynamicSharedMemorySize, GEMM_SMEM_BYTES);
    cudaFuncSetAttribute(gemm_f16, cudaFuncAttributeMaxDynamicSharedMemorySize, GEMM_SMEM_BYTES);

    // fused Q/K/V projection (V written directly as fp16)
    gemm_qkv<<<dim3((HID + 2 * KVDIM) / 128, SEQ / 128), 256, GEMM_SMEM_BYTES>>>(
        hs_h, wq_h, wk_h, wv_h, bq, bk, bv, q, k, vh);

    // rope (fp32 math, single rounding to half)
    rope_apply<<<(SEQ * NH  * 64) / 256, 256>>>(q, qh, cosd, sind, NH);
    rope_apply<<<(SEQ * NKV * 64) / 256, 256>>>(k, kh, cosd, sind, NKV);

    // attention (FA2, in-register softmax)
    cudaFuncSetAttribute(attn_f16, cudaFuncAttributeMaxDynamicSharedMemorySize, ATTN_SMEM_BYTES);
    attn_f16<<<dim3(SEQ / 128, NH), 256, ATTN_SMEM_BYTES>>>(qh, kh, vh, ctx_h);

    // output projection
    gemm_f16<<<dim3(HID / 128, SEQ / 128), 256, GEMM_SMEM_BYTES>>>(
        ctx_h, wo_h, nullptr, out, SEQ, HID, HID);
}

// round 10
// speedup vs baseline: 8.6797x; 1.0969x over previous
#include <cuda_runtime.h>
#include <cuda_fp16.h>
#include <math.h>
#include <stdint.h>

#define SEQ   2048
#define HID   3584
#define NH    28
#define NKV   4
#define HD    128
#define KVDIM 512   // NKV * HD

// ---------------- scratch (no allocations allowed) ----------------
__device__ float  g_q[SEQ * HID];
__device__ float  g_k[SEQ * KVDIM];
__device__ __half g_qh[SEQ * HID];
__device__ __half g_kh[SEQ * KVDIM];
__device__ __half g_vh[SEQ * KVDIM];
__device__ __half g_ctx_h[SEQ * HID];
__device__ __half g_hs_h[SEQ * HID];
__device__ __half g_wq_h[(size_t)HID * HID];
__device__ __half g_wk_h[(size_t)KVDIM * HID];
__device__ __half g_wv_h[(size_t)KVDIM * HID];
__device__ __half g_wo_h[(size_t)HID * HID];
__device__ float  g_cos[SEQ * 64];
__device__ float  g_sin[SEQ * 64];

// ---------------- helpers ----------------
__device__ __forceinline__ uint32_t smem_u32(const void* p) {
    uint32_t a;
    asm("{ .reg .u64 t; cvta.to.shared.u64 t, %1; cvt.u32.u64 %0, t; }" : "=r"(a) : "l"(p));
    return a;
}

__device__ __forceinline__ uint32_t h2_as_u32(__half2 h) {
    return *reinterpret_cast<uint32_t*>(&h);
}

__device__ __forceinline__ void mma_f16(float* c, const uint32_t* a, const uint32_t* b) {
    asm volatile(
        "mma.sync.aligned.m16n8k16.row.col.f32.f16.f16.f32 "
        "{%0,%1,%2,%3}, {%4,%5,%6,%7}, {%8,%9}, {%0,%1,%2,%3};\n"
        : "+f"(c[0]), "+f"(c[1]), "+f"(c[2]), "+f"(c[3])
        : "r"(a[0]), "r"(a[1]), "r"(a[2]), "r"(a[3]), "r"(b[0]), "r"(b[1]));
}

__device__ __forceinline__ void ldm_x4(uint32_t* r, uint32_t addr) {
    asm volatile("ldmatrix.sync.aligned.m8n8.x4.shared.b16 {%0,%1,%2,%3}, [%4];"
                 : "=r"(r[0]), "=r"(r[1]), "=r"(r[2]), "=r"(r[3]) : "r"(addr));
}

__device__ __forceinline__ void ldm_x4_t(uint32_t* r, uint32_t addr) {
    asm volatile("ldmatrix.sync.aligned.m8n8.x4.trans.shared.b16 {%0,%1,%2,%3}, [%4];"
                 : "=r"(r[0]), "=r"(r[1]), "=r"(r[2]), "=r"(r[3]) : "r"(addr));
}

// ---------------- fp32 -> fp16 conversion, 4 float4/thread (MLP=4) --------
// n4 MUST be a multiple of 1024 (all call sites are).
__global__ void cvt_half(const float* __restrict__ in, __half* __restrict__ out, int n4) {
    const int i0 = blockIdx.x * 1024 + threadIdx.x;
    float4 v[4];
    #pragma unroll
    for (int j = 0; j < 4; j++) v[j] = ((const float4*)in)[i0 + j * 256];
    #pragma unroll
    for (int j = 0; j < 4; j++) {
        const int i = i0 + j * 256;
        ((__half2*)out)[i * 2 + 0] = __floats2half2_rn(v[j].x, v[j].y);
        ((__half2*)out)[i * 2 + 1] = __floats2half2_rn(v[j].z, v[j].w);
    }
}

// ---------------- FP16 GEMM body: 3-stage cp.async, 1 sync/iter ------------
#define GTILE_H 5120        // 128 rows * 40 halves per stage
#define GSTAGES 3
#define GEMM_SMEM_BYTES (2 * GSTAGES * GTILE_H * 2)

__device__ __forceinline__ void gemm_body(
    const __half* __restrict__ A, const __half* __restrict__ W,
    const float* __restrict__ bias, float* __restrict__ Cf, __half* __restrict__ Ch,
    int N, int K, int bm, int bn, __half* As, __half* Bs)
{
    const int tid  = threadIdx.x;
    const int lane = tid & 31;
    const int wid  = tid >> 5;

    const int warp_m = (wid >> 1) * 32;
    const int warp_n = (wid & 1) * 64;

    const uint32_t sbA = smem_u32(As);
    const uint32_t sbB = smem_u32(Bs);

    int lrow[2], lch[2];
    #pragma unroll
    for (int p = 0; p < 2; p++) {
        int f = tid + p * 256;
        lrow[p] = f >> 2;
        lch[p]  = f & 3;
    }

    const int nt = K / 32;

    #pragma unroll
    for (int st = 0; st < 2; st++) {
        const uint32_t ab = sbA + (uint32_t)st * (GTILE_H * 2);
        const uint32_t bb = sbB + (uint32_t)st * (GTILE_H * 2);
        #pragma unroll
        for (int p = 0; p < 2; p++) {
            uint32_t so = (uint32_t)lrow[p] * 80u + (uint32_t)lch[p] * 16u;
            const __half* ga = A + (size_t)(bm + lrow[p]) * K + (size_t)st * 32 + lch[p] * 8;
            const __half* gb = W + (size_t)(bn + lrow[p]) * K + (size_t)st * 32 + lch[p] * 8;
            asm volatile("cp.async.cg.shared.global [%0], [%1], 16;" :: "r"(ab + so), "l"(ga) : "memory");
            asm volatile("cp.async.cg.shared.global [%0], [%1], 16;" :: "r"(bb + so), "l"(gb) : "memory");
        }
        asm volatile("cp.async.commit_group;" ::: "memory");
    }

    float acc[2][8][4];
    #pragma unroll
    for (int mi = 0; mi < 2; mi++)
        #pragma unroll
        for (int ni = 0; ni < 8; ni++)
            #pragma unroll
            for (int j = 0; j < 4; j++) acc[mi][ni][j] = 0.f;

    const int lg = lane >> 3;
    const int lr = lane & 7;

    int cur = 0, nxt = 2;
    for (int i = 0; i < nt; i++) {
        if (i < nt - 1) asm volatile("cp.async.wait_group 1;" ::: "memory");
        else            asm volatile("cp.async.wait_group 0;" ::: "memory");
        __syncthreads();

        if (i + 2 < nt) {
            const uint32_t ab = sbA + (uint32_t)nxt * (GTILE_H * 2);
            const uint32_t bb = sbB + (uint32_t)nxt * (GTILE_H * 2);
            #pragma unroll
            for (int p = 0; p < 2; p++) {
                uint32_t so = (uint32_t)lrow[p] * 80u + (uint32_t)lch[p] * 16u;
                const __half* ga = A + (size_t)(bm + lrow[p]) * K + (size_t)(i + 2) * 32 + lch[p] * 8;
                const __half* gb = W + (size_t)(bn + lrow[p]) * K + (size_t)(i + 2) * 32 + lch[p] * 8;
                asm volatile("cp.async.cg.shared.global [%0], [%1], 16;" :: "r"(ab + so), "l"(ga) : "memory");
                asm volatile("cp.async.cg.shared.global [%0], [%1], 16;" :: "r"(bb + so), "l"(gb) : "memory");
            }
            asm volatile("cp.async.commit_group;" ::: "memory");
        }

        const uint32_t abuf = sbA + (uint32_t)cur * (GTILE_H * 2);
        const uint32_t bbuf = sbB + (uint32_t)cur * (GTILE_H * 2);

        #pragma unroll
        for (int s = 0; s < 2; s++) {
            uint32_t a[2][4], bq[4][4];
            #pragma unroll
            for (int mi = 0; mi < 2; mi++) {
                int row = warp_m + mi * 16 + lr + (lg & 1) * 8;
                int ch  = s * 2 + (lg >> 1);
                ldm_x4(a[mi], abuf + (uint32_t)row * 80u + (uint32_t)ch * 16u);
            }
            #pragma unroll
            for (int pr = 0; pr < 4; pr++) {
                int row = warp_n + pr * 16 + lr + (lg >> 1) * 8;
                int ch  = s * 2 + (lg & 1);
                ldm_x4(bq[pr], bbuf + (uint32_t)row * 80u + (uint32_t)ch * 16u);
            }
            #pragma unroll
            for (int mi = 0; mi < 2; mi++)
                #pragma unroll
                for (int pr = 0; pr < 4; pr++) {
                    mma_f16(acc[mi][pr * 2 + 0], a[mi], &bq[pr][0]);
                    mma_f16(acc[mi][pr * 2 + 1], a[mi], &bq[pr][2]);
                }
        }

        cur = (cur + 1 == GSTAGES) ? 0 : cur + 1;
        nxt = (nxt + 1 == GSTAGES) ? 0 : nxt + 1;
    }

    #pragma unroll
    for (int ni = 0; ni < 8; ni++) {
        const int col = bn + warp_n + ni * 8 + (lane & 3) * 2;
        float b0 = 0.f, b1 = 0.f;
        if (bias) { b0 = bias[col]; b1 = bias[col + 1]; }
        #pragma unroll
        for (int mi = 0; mi < 2; mi++) {
            const int row = bm + warp_m + mi * 16 + (lane >> 2);
            if (Ch) {
                *(__half2*)(Ch + (size_t)row * N + col) =
                    __floats2half2_rn(acc[mi][ni][0] + b0, acc[mi][ni][1] + b1);
                *(__half2*)(Ch + (size_t)(row + 8) * N + col) =
                    __floats2half2_rn(acc[mi][ni][2] + b0, acc[mi][ni][3] + b1);
            } else {
                float2 v0 = make_float2(acc[mi][ni][0] + b0, acc[mi][ni][1] + b1);
                float2 v1 = make_float2(acc[mi][ni][2] + b0, acc[mi][ni][3] + b1);
                *(float2*)(Cf + (size_t)row * N + col) = v0;
                *(float2*)(Cf + (size_t)(row + 8) * N + col) = v1;
            }
        }
    }
}

// generic GEMM (O-projection, fp32 out)
__global__ __launch_bounds__(256, 2) void gemm_f16(
    const __half* __restrict__ A, const __half* __restrict__ W,
    const float* __restrict__ bias, float* __restrict__ C,
    int M, int N, int K)
{
    extern __shared__ __align__(16) __half gsh[];
    gemm_body(A, W, bias, C, (__half*)0, N, K, blockIdx.y * 128, blockIdx.x * 128,
              gsh, gsh + GSTAGES * GTILE_H);
}

// fused Q/K/V projection: 36 block-cols; V written directly as fp16
__global__ __launch_bounds__(256, 2) void gemm_qkv(
    const __half* __restrict__ A,
    const __half* __restrict__ wq, const __half* __restrict__ wk, const __half* __restrict__ wv,
    const float* __restrict__ bq, const float* __restrict__ bk, const float* __restrict__ bv,
    float* __restrict__ q, float* __restrict__ k, __half* __restrict__ vh)
{
    extern __shared__ __align__(16) __half gsh[];
    const int bx = blockIdx.x;
    const __half* W; const float* bias; float* Cf; __half* Ch; int N, bn;
    if (bx < HID / 128) {
        W = wq; bias = bq; Cf = q; Ch = 0; N = HID; bn = bx * 128;
    } else if (bx < HID / 128 + KVDIM / 128) {
        W = wk; bias = bk; Cf = k; Ch = 0; N = KVDIM; bn = (bx - HID / 128) * 128;
    } else {
        W = wv; bias = bv; Cf = 0; Ch = vh; N = KVDIM; bn = (bx - HID / 128 - KVDIM / 128) * 128;
    }
    gemm_body(A, W, bias, Cf, Ch, N, HID, blockIdx.y * 128, bn,
              gsh, gsh + GSTAGES * GTILE_H);
}

// ---------------- RoPE tables + apply ----------------
__global__ void rope_tables(float* __restrict__ cosd, float* __restrict__ sind) {
    int i = blockIdx.x * blockDim.x + threadIdx.x;
    int half = i & 63;
    int s = i >> 6;
    double inv = exp(-log(1.0e6) * (double)(2 * half) / 128.0);
    double ang = (double)s * inv;
    cosd[i] = (float)cos(ang);
    sind[i] = (float)sin(ang);
}

__global__ void rope_apply(const float* __restrict__ x, __half* __restrict__ xh,
                           const float* __restrict__ cosd, const float* __restrict__ sind,
                           int nheads)
{
    int idx = blockIdx.x * blockDim.x + threadIdx.x;
    int half = idx & 63;
    int h = (idx >> 6) % nheads;
    int s = idx / (64 * nheads);

    float c  = cosd[s * 64 + half];
    float si = sind[s * 64 + half];

    const float* base = x + (size_t)s * nheads * HD + h * HD;
    __half* baseh = xh + (size_t)s * nheads * HD + h * HD;
    float x1 = base[half];
    float x2 = base[half + 64];
    baseh[half]      = __float2half_rn(x1 * c - x2 * si);
    baseh[half + 64] = __float2half_rn(x2 * c + x1 * si);
}

// ---------------- Flash attention (FA2): 128q block, warp = 16q x 64k ------
// 1-D grid in strict LPT order (heaviest q-tiles of all heads first).
#define AQ_STR 136
#define ATTN_SMEM_BYTES ((128 * AQ_STR + 4 * 64 * AQ_STR) * 2)

__global__ __launch_bounds__(256, 2) void attn_f16(
    const __half* __restrict__ q, const __half* __restrict__ k,
    const __half* __restrict__ v, __half* __restrict__ ctx)
{
    extern __shared__ __align__(16) char smraw[];
    __half* Qh = (__half*)smraw;                    // [128][136]
    __half* Kh = Qh + 128 * AQ_STR;                 // [2][64][136]
    __half* Vh = Kh + 2 * 64 * AQ_STR;              // [2][64][136]

    const int b   = blockIdx.x;                     // 0..447, LPT order
    const int qt  = (SEQ / 128 - 1) - (b / NH);     // heaviest first across ALL heads
    const int h   = b % NH;
    const int kvh = h / 7;
    const int tid  = threadIdx.x;
    const int lane = tid & 31;
    const int wid  = tid >> 5;

    const int wm = wid * 16;                        // warp's q-row base
    const int lg = lane >> 3;
    const int lr = lane & 7;
    const int qr = lane >> 2;                       // row-in-slab (0..7)
    const int qc = lane & 3;

    const uint32_t sQ = smem_u32(Qh);
    const uint32_t sK = smem_u32(Kh);
    const uint32_t sV = smem_u32(Vh);

    // K/V cp.async mapping: 64 rows x 128 cols = 1024 uint4; 4 per thread
    int trow[4], tcol[4];
    #pragma unroll
    for (int i = 0; i < 4; i++) {
        int f = tid + i * 256;
        trow[i] = f >> 4;
        tcol[i] = (f & 15) * 8;
    }

    const int nkt = 2 * qt + 2;

    // prologue: cp.async tile 0 into stage 0
    {
        const __half* kb = k + kvh * HD;
        const __half* vb = v + kvh * HD;
        #pragma unroll
        for (int i = 0; i < 4; i++) {
            uint32_t so = (uint32_t)trow[i] * (AQ_STR * 2) + (uint32_t)tcol[i] * 2;
            asm volatile("cp.async.cg.shared.global [%0], [%1], 16;"
                         :: "r"(sK + so), "l"(kb + (size_t)trow[i] * KVDIM + tcol[i]) : "memory");
            asm volatile("cp.async.cg.shared.global [%0], [%1], 16;"
                         :: "r"(sV + so), "l"(vb + (size_t)trow[i] * KVDIM + tcol[i]) : "memory");
        }
        asm volatile("cp.async.commit_group;" ::: "memory");
    }

    // load Q tile (128 rows)
    {
        const __half* qbase = q + (size_t)(qt * 128) * HID + h * HD;
        #pragma unroll
        for (int i = 0; i < 8; i++) {
            int f = tid + i * 256;
            int r = f >> 4;
            int c = (f & 15) * 8;
            *(uint4*)&Qh[r * AQ_STR + c] = *(const uint4*)(qbase + (size_t)r * HID + c);
        }
    }

    float out[16][4];
    #pragma unroll
    for (int ni = 0; ni < 16; ni++)
        #pragma unroll
        for (int j = 0; j < 4; j++) out[ni][j] = 0.f;
    float m0 = -INFINITY, m1 = -INFINITY, l0 = 0.f, l1 = 0.f;

    const float scale = 0.08838834764831845f;       // 1/sqrt(128)

    for (int kt = 0; kt < nkt; kt++) {
        asm volatile("cp.async.wait_group 0;" ::: "memory");
        __syncthreads();

        // issue next tile into the other stage (overlaps compute below)
        if (kt + 1 < nkt) {
            const uint32_t stoff = (uint32_t)((kt + 1) & 1) * (64 * AQ_STR * 2);
            const __half* kb = k + (size_t)((kt + 1) * 64) * KVDIM + kvh * HD;
            const __half* vb = v + (size_t)((kt + 1) * 64) * KVDIM + kvh * HD;
            #pragma unroll
            for (int i = 0; i < 4; i++) {
                uint32_t so = (uint32_t)trow[i] * (AQ_STR * 2) + (uint32_t)tcol[i] * 2 + stoff;
                asm volatile("cp.async.cg.shared.global [%0], [%1], 16;"
                             :: "r"(sK + so), "l"(kb + (size_t)trow[i] * KVDIM + tcol[i]) : "memory");
                asm volatile("cp.async.cg.shared.global [%0], [%1], 16;"
                             :: "r"(sV + so), "l"(vb + (size_t)trow[i] * KVDIM + tcol[i]) : "memory");
            }
            asm volatile("cp.async.commit_group;" ::: "memory");
        }

        const uint32_t kbuf = sK + (uint32_t)(kt & 1) * (64 * AQ_STR * 2);
        const uint32_t vbuf = sV + (uint32_t)(kt & 1) * (64 * AQ_STR * 2);

        // ---- S = Q @ K^T : sfrag[8] covers 64 keys ----
        float sfrag[8][4];
        #pragma unroll
        for (int ni = 0; ni < 8; ni++)
            #pragma unroll
            for (int j = 0; j < 4; j++) sfrag[ni][j] = 0.f;

        #pragma unroll
        for (int s = 0; s < 8; s++) {
            uint32_t a[4];
            {
                int row = wm + lr + (lg & 1) * 8;
                int ch  = s * 2 + (lg >> 1);
                ldm_x4(a, sQ + ((uint32_t)row * AQ_STR + (uint32_t)ch * 8) * 2u);
            }
            #pragma unroll
            for (int pr = 0; pr < 4; pr++) {
                uint32_t bq[4];
                int row = pr * 16 + lr + (lg >> 1) * 8;
                int ch  = s * 2 + (lg & 1);
                ldm_x4(bq, kbuf + ((uint32_t)row * AQ_STR + (uint32_t)ch * 8) * 2u);
                mma_f16(sfrag[pr * 2 + 0], a, &bq[0]);
                mma_f16(sfrag[pr * 2 + 1], a, &bq[2]);
            }
        }

        // ---- scale + causal mask ----
        const bool diag = (kt >= 2 * qt);
        const int qr0 = qt * 128 + wm + qr;
        #pragma unroll
        for (int ni = 0; ni < 8; ni++) {
            const int kc = kt * 64 + ni * 8 + qc * 2;
            sfrag[ni][0] *= scale; sfrag[ni][1] *= scale;
            sfrag[ni][2] *= scale; sfrag[ni][3] *= scale;
            if (diag) {
                if (kc > qr0)         sfrag[ni][0] += -1.0e9f;
                if (kc + 1 > qr0)     sfrag[ni][1] += -1.0e9f;
                if (kc > qr0 + 8)     sfrag[ni][2] += -1.0e9f;
                if (kc + 1 > qr0 + 8) sfrag[ni][3] += -1.0e9f;
            }
        }

        // ---- row max (quad reduce) + rescale ----
        float mx0 = m0, mx1 = m1;
        #pragma unroll
        for (int ni = 0; ni < 8; ni++) {
            mx0 = fmaxf(mx0, fmaxf(sfrag[ni][0], sfrag[ni][1]));
            mx1 = fmaxf(mx1, fmaxf(sfrag[ni][2], sfrag[ni][3]));
        }
        mx0 = fmaxf(mx0, __shfl_xor_sync(0xffffffffu, mx0, 1));
        mx0 = fmaxf(mx0, __shfl_xor_sync(0xffffffffu, mx0, 2));
        mx1 = fmaxf(mx1, __shfl_xor_sync(0xffffffffu, mx1, 1));
        mx1 = fmaxf(mx1, __shfl_xor_sync(0xffffffffu, mx1, 2));
        const float al0 = __expf(m0 - mx0);
        const float al1 = __expf(m1 - mx1);
        m0 = mx0; m1 = mx1;
        #pragma unroll
        for (int ni = 0; ni < 16; ni++) {
            out[ni][0] *= al0; out[ni][1] *= al0;
            out[ni][2] *= al1; out[ni][3] *= al1;
        }

        // ---- exp -> P frags; PV interleaved per k16-step ----
        float sum0 = 0.f, sum1 = 0.f;
        #pragma unroll
        for (int s = 0; s < 4; s++) {
            float p00 = __expf(sfrag[2*s][0]   - mx0), p01 = __expf(sfrag[2*s][1]   - mx0);
            float p10 = __expf(sfrag[2*s][2]   - mx1), p11 = __expf(sfrag[2*s][3]   - mx1);
            float p20 = __expf(sfrag[2*s+1][0] - mx0), p21 = __expf(sfrag[2*s+1][1] - mx0);
            float p30 = __expf(sfrag[2*s+1][2] - mx1), p31 = __expf(sfrag[2*s+1][3] - mx1);
            sum0 += p00 + p01 + p20 + p21;
            sum1 += p10 + p11 + p30 + p31;
            uint32_t pf[4];
            pf[0] = h2_as_u32(__floats2half2_rn(p00, p01));
            pf[1] = h2_as_u32(__floats2half2_rn(p10, p11));
            pf[2] = h2_as_u32(__floats2half2_rn(p20, p21));
            pf[3] = h2_as_u32(__floats2half2_rn(p30, p31));
            #pragma unroll
            for (int nb = 0; nb < 8; nb++) {
                uint32_t bv[4];
                int row = s * 16 + (lg & 1) * 8 + lr;        // key row
                int col = nb * 16 + (lg >> 1) * 8;           // d col
                ldm_x4_t(bv, vbuf + ((uint32_t)row * AQ_STR + (uint32_t)col) * 2u);
                mma_f16(out[nb * 2 + 0], pf, &bv[0]);
                mma_f16(out[nb * 2 + 1], pf, &bv[2]);
            }
        }
        sum0 += __shfl_xor_sync(0xffffffffu, sum0, 1);
        sum0 += __shfl_xor_sync(0xffffffffu, sum0, 2);
        sum1 += __shfl_xor_sync(0xffffffffu, sum1, 1);
        sum1 += __shfl_xor_sync(0xffffffffu, sum1, 2);
        l0 = l0 * al0 + sum0;
        l1 = l1 * al1 + sum1;
    }

    // ---- epilogue ----
    {
        const float inv0 = 1.f / l0;
        const float inv1 = 1.f / l1;
        const int row0 = qt * 128 + wm + qr;
        #pragma unroll
        for (int ni = 0; ni < 16; ni++) {
            const int col = h * HD + ni * 8 + qc * 2;
            *(__half2*)(ctx + (size_t)row0 * HID + col) =
                __floats2half2_rn(out[ni][0] * inv0, out[ni][1] * inv0);
            *(__half2*)(ctx + (size_t)(row0 + 8) * HID + col) =
                __floats2half2_rn(out[ni][2] * inv1, out[ni][3] * inv1);
        }
    }
}

// ---------------- host launcher ----------------
extern "C" void kernel_launch(void* const* d_in, const int* in_sizes, int n_in,
                              void* d_out, int out_size)
{
    const float* hs = (const float*)d_in[0];
    const float* wq = (const float*)d_in[2];
    const float* bq = (const float*)d_in[3];
    const float* wk = (const float*)d_in[4];
    const float* bk = (const float*)d_in[5];
    const float* wv = (const float*)d_in[6];
    const float* bv = (const float*)d_in[7];
    const float* wo = (const float*)d_in[8];
    float* out = (float*)d_out;

    float *q, *k, *cosd, *sind;
    __half *qh, *kh, *vh, *ctx_h, *hs_h, *wq_h, *wk_h, *wv_h, *wo_h;
    cudaGetSymbolAddress((void**)&q,     g_q);
    cudaGetSymbolAddress((void**)&k,     g_k);
    cudaGetSymbolAddress((void**)&qh,    g_qh);
    cudaGetSymbolAddress((void**)&kh,    g_kh);
    cudaGetSymbolAddress((void**)&vh,    g_vh);
    cudaGetSymbolAddress((void**)&ctx_h, g_ctx_h);
    cudaGetSymbolAddress((void**)&hs_h,  g_hs_h);
    cudaGetSymbolAddress((void**)&wq_h,  g_wq_h);
    cudaGetSymbolAddress((void**)&wk_h,  g_wk_h);
    cudaGetSymbolAddress((void**)&wv_h,  g_wv_h);
    cudaGetSymbolAddress((void**)&wo_h,  g_wo_h);
    cudaGetSymbolAddress((void**)&cosd,  g_cos);
    cudaGetSymbolAddress((void**)&sind,  g_sin);

    // fp16 operand conversion (4 float4/thread) + rope tables
    cvt_half<<<SEQ * HID / 4 / 1024,   256>>>(hs, hs_h, SEQ * HID / 4);
    cvt_half<<<HID * HID / 4 / 1024,   256>>>(wq, wq_h, HID * HID / 4);
    cvt_half<<<KVDIM * HID / 4 / 1024, 256>>>(wk, wk_h, KVDIM * HID / 4);
    cvt_half<<<KVDIM * HID / 4 / 1024, 256>>>(wv, wv_h, KVDIM * HID / 4);
    cvt_half<<<HID * HID / 4 / 1024,   256>>>(wo, wo_h, HID * HID / 4);
    rope_tables<<<(SEQ * 64) / 256, 256>>>(cosd, sind);

    cudaFuncSetAttribute(gemm_qkv, cudaFuncAttributeMaxDynamicSharedMemorySize, GEMM_SMEM_BYTES);
    cudaFuncSetAttribute(gemm_f16, cudaFuncAttributeMaxDynamicSharedMemorySize, GEMM_SMEM_BYTES);

    // fused Q/K/V projection (V written directly as fp16)
    gemm_qkv<<<dim3((HID + 2 * KVDIM) / 128, SEQ / 128), 256, GEMM_SMEM_BYTES>>>(
        hs_h, wq_h, wk_h, wv_h, bq, bk, bv, q, k, vh);

    // rope (fp32 math, single rounding to half)
    rope_apply<<<(SEQ * NH  * 64) / 256, 256>>>(q, qh, cosd, sind, NH);
    rope_apply<<<(SEQ * NKV * 64) / 256, 256>>>(k, kh, cosd, sind, NKV);

    // attention (FA2, in-register softmax, LPT block order)
    cudaFuncSetAttribute(attn_f16, cudaFuncAttributeMaxDynamicSharedMemorySize, ATTN_SMEM_BYTES);
    attn_f16<<<(SEQ / 128) * NH, 256, ATTN_SMEM_BYTES>>>(qh, kh, vh, ctx_h);

    // output projection
    gemm_f16<<<dim3(HID / 128, SEQ / 128), 256, GEMM_SMEM_BYTES>>>(
        ctx_h, wo_h, nullptr, out, SEQ, HID, HID);
}

// round 12
// speedup vs baseline: 8.8438x; 1.0189x over previous
#include <cuda_runtime.h>
#include <cuda_fp16.h>
#include <math.h>
#include <stdint.h>

#define SEQ   2048
#define HID   3584
#define NH    28
#define NKV   4
#define HD    128
#define KVDIM 512   // NKV * HD

// ---------------- scratch (no allocations allowed) ----------------
__device__ float  g_q[SEQ * HID];
__device__ float  g_k[SEQ * KVDIM];
__device__ __half g_qh[SEQ * HID];
__device__ __half g_kh[SEQ * KVDIM];
__device__ __half g_vh[SEQ * KVDIM];
__device__ __half g_ctx_h[SEQ * HID];
__device__ __half g_hs_h[SEQ * HID];
__device__ __half g_wq_h[(size_t)HID * HID];
__device__ __half g_wk_h[(size_t)KVDIM * HID];
__device__ __half g_wv_h[(size_t)KVDIM * HID];
__device__ __half g_wo_h[(size_t)HID * HID];
__device__ float  g_cos[SEQ * 64];
__device__ float  g_sin[SEQ * 64];

// ---------------- helpers ----------------
__device__ __forceinline__ uint32_t smem_u32(const void* p) {
    uint32_t a;
    asm("{ .reg .u64 t; cvta.to.shared.u64 t, %1; cvt.u32.u64 %0, t; }" : "=r"(a) : "l"(p));
    return a;
}

__device__ __forceinline__ uint32_t h2_as_u32(__half2 h) {
    return *reinterpret_cast<uint32_t*>(&h);
}

__device__ __forceinline__ void mma_f16(float* c, const uint32_t* a, const uint32_t* b) {
    asm volatile(
        "mma.sync.aligned.m16n8k16.row.col.f32.f16.f16.f32 "
        "{%0,%1,%2,%3}, {%4,%5,%6,%7}, {%8,%9}, {%0,%1,%2,%3};\n"
        : "+f"(c[0]), "+f"(c[1]), "+f"(c[2]), "+f"(c[3])
        : "r"(a[0]), "r"(a[1]), "r"(a[2]), "r"(a[3]), "r"(b[0]), "r"(b[1]));
}

__device__ __forceinline__ void ldm_x4(uint32_t* r, uint32_t addr) {
    asm volatile("ldmatrix.sync.aligned.m8n8.x4.shared.b16 {%0,%1,%2,%3}, [%4];"
                 : "=r"(r[0]), "=r"(r[1]), "=r"(r[2]), "=r"(r[3]) : "r"(addr));
}

__device__ __forceinline__ void ldm_x4_t(uint32_t* r, uint32_t addr) {
    asm volatile("ldmatrix.sync.aligned.m8n8.x4.trans.shared.b16 {%0,%1,%2,%3}, [%4];"
                 : "=r"(r[0]), "=r"(r[1]), "=r"(r[2]), "=r"(r[3]) : "r"(addr));
}

// ---------------- fp32 -> fp16 conversion, 4 float4/thread (MLP=4) --------
// n4 MUST be a multiple of 1024 (all call sites are).
__global__ void cvt_half(const float* __restrict__ in, __half* __restrict__ out, int n4) {
    const int i0 = blockIdx.x * 1024 + threadIdx.x;
    float4 v[4];
    #pragma unroll
    for (int j = 0; j < 4; j++) v[j] = ((const float4*)in)[i0 + j * 256];
    #pragma unroll
    for (int j = 0; j < 4; j++) {
        const int i = i0 + j * 256;
        ((__half2*)out)[i * 2 + 0] = __floats2half2_rn(v[j].x, v[j].y);
        ((__half2*)out)[i * 2 + 1] = __floats2half2_rn(v[j].z, v[j].w);
    }
}

// ---------------- FP16 GEMM body: 3-stage cp.async, 1 sync/iter ------------
#define GTILE_H 5120        // 128 rows * 40 halves per stage
#define GSTAGES 3
#define GEMM_SMEM_BYTES (2 * GSTAGES * GTILE_H * 2)

__device__ __forceinline__ void gemm_body(
    const __half* __restrict__ A, const __half* __restrict__ W,
    const float* __restrict__ bias, float* __restrict__ Cf, __half* __restrict__ Ch,
    int N, int K, int bm, int bn, __half* As, __half* Bs)
{
    const int tid  = threadIdx.x;
    const int lane = tid & 31;
    const int wid  = tid >> 5;

    const int warp_m = (wid >> 1) * 32;
    const int warp_n = (wid & 1) * 64;

    const uint32_t sbA = smem_u32(As);
    const uint32_t sbB = smem_u32(Bs);

    int lrow[2], lch[2];
    #pragma unroll
    for (int p = 0; p < 2; p++) {
        int f = tid + p * 256;
        lrow[p] = f >> 2;
        lch[p]  = f & 3;
    }

    const int nt = K / 32;

    #pragma unroll
    for (int st = 0; st < 2; st++) {
        const uint32_t ab = sbA + (uint32_t)st * (GTILE_H * 2);
        const uint32_t bb = sbB + (uint32_t)st * (GTILE_H * 2);
        #pragma unroll
        for (int p = 0; p < 2; p++) {
            uint32_t so = (uint32_t)lrow[p] * 80u + (uint32_t)lch[p] * 16u;
            const __half* ga = A + (size_t)(bm + lrow[p]) * K + (size_t)st * 32 + lch[p] * 8;
            const __half* gb = W + (size_t)(bn + lrow[p]) * K + (size_t)st * 32 + lch[p] * 8;
            asm volatile("cp.async.cg.shared.global [%0], [%1], 16;" :: "r"(ab + so), "l"(ga) : "memory");
            asm volatile("cp.async.cg.shared.global [%0], [%1], 16;" :: "r"(bb + so), "l"(gb) : "memory");
        }
        asm volatile("cp.async.commit_group;" ::: "memory");
    }

    float acc[2][8][4];
    #pragma unroll
    for (int mi = 0; mi < 2; mi++)
        #pragma unroll
        for (int ni = 0; ni < 8; ni++)
            #pragma unroll
            for (int j = 0; j < 4; j++) acc[mi][ni][j] = 0.f;

    const int lg = lane >> 3;
    const int lr = lane & 7;

    int cur = 0, nxt = 2;
    for (int i = 0; i < nt; i++) {
        if (i < nt - 1) asm volatile("cp.async.wait_group 1;" ::: "memory");
        else            asm volatile("cp.async.wait_group 0;" ::: "memory");
        __syncthreads();

        if (i + 2 < nt) {
            const uint32_t ab = sbA + (uint32_t)nxt * (GTILE_H * 2);
            const uint32_t bb = sbB + (uint32_t)nxt * (GTILE_H * 2);
            #pragma unroll
            for (int p = 0; p < 2; p++) {
                uint32_t so = (uint32_t)lrow[p] * 80u + (uint32_t)lch[p] * 16u;
                const __half* ga = A + (size_t)(bm + lrow[p]) * K + (size_t)(i + 2) * 32 + lch[p] * 8;
                const __half* gb = W + (size_t)(bn + lrow[p]) * K + (size_t)(i + 2) * 32 + lch[p] * 8;
                asm volatile("cp.async.cg.shared.global [%0], [%1], 16;" :: "r"(ab + so), "l"(ga) : "memory");
                asm volatile("cp.async.cg.shared.global [%0], [%1], 16;" :: "r"(bb + so), "l"(gb) : "memory");
            }
            asm volatile("cp.async.commit_group;" ::: "memory");
        }

        const uint32_t abuf = sbA + (uint32_t)cur * (GTILE_H * 2);
        const uint32_t bbuf = sbB + (uint32_t)cur * (GTILE_H * 2);

        #pragma unroll
        for (int s = 0; s < 2; s++) {
            uint32_t a[2][4], bq[4][4];
            #pragma unroll
            for (int mi = 0; mi < 2; mi++) {
                int row = warp_m + mi * 16 + lr + (lg & 1) * 8;
                int ch  = s * 2 + (lg >> 1);
                ldm_x4(a[mi], abuf + (uint32_t)row * 80u + (uint32_t)ch * 16u);
            }
            #pragma unroll
            for (int pr = 0; pr < 4; pr++) {
                int row = warp_n + pr * 16 + lr + (lg >> 1) * 8;
                int ch  = s * 2 + (lg & 1);
                ldm_x4(bq[pr], bbuf + (uint32_t)row * 80u + (uint32_t)ch * 16u);
            }
            #pragma unroll
            for (int mi = 0; mi < 2; mi++)
                #pragma unroll
                for (int pr = 0; pr < 4; pr++) {
                    mma_f16(acc[mi][pr * 2 + 0], a[mi], &bq[pr][0]);
                    mma_f16(acc[mi][pr * 2 + 1], a[mi], &bq[pr][2]);
                }
        }

        cur = (cur + 1 == GSTAGES) ? 0 : cur + 1;
        nxt = (nxt + 1 == GSTAGES) ? 0 : nxt + 1;
    }

    #pragma unroll
    for (int ni = 0; ni < 8; ni++) {
        const int col = bn + warp_n + ni * 8 + (lane & 3) * 2;
        float b0 = 0.f, b1 = 0.f;
        if (bias) { b0 = bias[col]; b1 = bias[col + 1]; }
        #pragma unroll
        for (int mi = 0; mi < 2; mi++) {
            const int row = bm + warp_m + mi * 16 + (lane >> 2);
            if (Ch) {
                *(__half2*)(Ch + (size_t)row * N + col) =
                    __floats2half2_rn(acc[mi][ni][0] + b0, acc[mi][ni][1] + b1);
                *(__half2*)(Ch + (size_t)(row + 8) * N + col) =
                    __floats2half2_rn(acc[mi][ni][2] + b0, acc[mi][ni][3] + b1);
            } else {
                float2 v0 = make_float2(acc[mi][ni][0] + b0, acc[mi][ni][1] + b1);
                float2 v1 = make_float2(acc[mi][ni][2] + b0, acc[mi][ni][3] + b1);
                *(float2*)(Cf + (size_t)row * N + col) = v0;
                *(float2*)(Cf + (size_t)(row + 8) * N + col) = v1;
            }
        }
    }
}

// generic GEMM (O-projection, fp32 out)
__global__ __launch_bounds__(256, 2) void gemm_f16(
    const __half* __restrict__ A, const __half* __restrict__ W,
    const float* __restrict__ bias, float* __restrict__ C,
    int M, int N, int K)
{
    extern __shared__ __align__(16) __half gsh[];
    gemm_body(A, W, bias, C, (__half*)0, N, K, blockIdx.y * 128, blockIdx.x * 128,
              gsh, gsh + GSTAGES * GTILE_H);
}

// fused Q/K/V projection: 36 block-cols; V written directly as fp16
__global__ __launch_bounds__(256, 2) void gemm_qkv(
    const __half* __restrict__ A,
    const __half* __restrict__ wq, const __half* __restrict__ wk, const __half* __restrict__ wv,
    const float* __restrict__ bq, const float* __restrict__ bk, const float* __restrict__ bv,
    float* __restrict__ q, float* __restrict__ k, __half* __restrict__ vh)
{
    extern __shared__ __align__(16) __half gsh[];
    const int bx = blockIdx.x;
    const __half* W; const float* bias; float* Cf; __half* Ch; int N, bn;
    if (bx < HID / 128) {
        W = wq; bias = bq; Cf = q; Ch = 0; N = HID; bn = bx * 128;
    } else if (bx < HID / 128 + KVDIM / 128) {
        W = wk; bias = bk; Cf = k; Ch = 0; N = KVDIM; bn = (bx - HID / 128) * 128;
    } else {
        W = wv; bias = bv; Cf = 0; Ch = vh; N = KVDIM; bn = (bx - HID / 128 - KVDIM / 128) * 128;
    }
    gemm_body(A, W, bias, Cf, Ch, N, HID, blockIdx.y * 128, bn,
              gsh, gsh + GSTAGES * GTILE_H);
}

// ---------------- RoPE tables + apply (vectorized, 4 dims/thread) ----------
__global__ void rope_tables(float* __restrict__ cosd, float* __restrict__ sind) {
    int i = blockIdx.x * blockDim.x + threadIdx.x;
    int half = i & 63;
    int s = i >> 6;
    double inv = exp(-log(1.0e6) * (double)(2 * half) / 128.0);
    double ang = (double)s * inv;
    cosd[i] = (float)cos(ang);
    sind[i] = (float)sin(ang);
}

// one thread handles 4 consecutive dims of one (s, h) row: float4 in, half2 out
__global__ void rope_apply(const float* __restrict__ x, __half* __restrict__ xh,
                           const float* __restrict__ cosd, const float* __restrict__ sind,
                           int nheads)
{
    int idx = blockIdx.x * blockDim.x + threadIdx.x;   // SEQ*nheads*16 threads
    int d4 = (idx & 15) << 2;           // 0,4,...,60
    int h  = (idx >> 4) % nheads;
    int s  = idx / (16 * nheads);

    float4 c  = *(const float4*)&cosd[s * 64 + d4];
    float4 si = *(const float4*)&sind[s * 64 + d4];

    const float* base = x + (size_t)s * nheads * HD + h * HD;
    __half* baseh = xh + (size_t)s * nheads * HD + h * HD;
    float4 x1 = *(const float4*)&base[d4];
    float4 x2 = *(const float4*)&base[d4 + 64];

    *(__half2*)&baseh[d4]          = __floats2half2_rn(x1.x * c.x - x2.x * si.x,
                                                       x1.y * c.y - x2.y * si.y);
    *(__half2*)&baseh[d4 + 2]      = __floats2half2_rn(x1.z * c.z - x2.z * si.z,
                                                       x1.w * c.w - x2.w * si.w);
    *(__half2*)&baseh[d4 + 64]     = __floats2half2_rn(x2.x * c.x + x1.x * si.x,
                                                       x2.y * c.y + x1.y * si.y);
    *(__half2*)&baseh[d4 + 64 + 2] = __floats2half2_rn(x2.z * c.z + x1.z * si.z,
                                                       x2.w * c.w + x1.w * si.w);
}

// ---------------- Flash attention (FA2): 128q block, warp = 16q x 64k ------
// 1-D grid in strict LPT order. Softmax in log2 domain (exp2f, scale folded).
#define AQ_STR 136
#define ATTN_SMEM_BYTES ((128 * AQ_STR + 4 * 64 * AQ_STR) * 2)

__global__ __launch_bounds__(256, 2) void attn_f16(
    const __half* __restrict__ q, const __half* __restrict__ k,
    const __half* __restrict__ v, __half* __restrict__ ctx)
{
    extern __shared__ __align__(16) char smraw[];
    __half* Qh = (__half*)smraw;                    // [128][136]
    __half* Kh = Qh + 128 * AQ_STR;                 // [2][64][136]
    __half* Vh = Kh + 2 * 64 * AQ_STR;              // [2][64][136]

    const int b   = blockIdx.x;                     // 0..447, LPT order
    const int qt  = (SEQ / 128 - 1) - (b / NH);     // heaviest first across ALL heads
    const int h   = b % NH;
    const int kvh = h / 7;
    const int tid  = threadIdx.x;
    const int lane = tid & 31;
    const int wid  = tid >> 5;

    const int wm = wid * 16;                        // warp's q-row base
    const int lg = lane >> 3;
    const int lr = lane & 7;
    const int qr = lane >> 2;                       // row-in-slab (0..7)
    const int qc = lane & 3;

    const uint32_t sQ = smem_u32(Qh);
    const uint32_t sK = smem_u32(Kh);
    const uint32_t sV = smem_u32(Vh);

    // K/V cp.async mapping: 64 rows x 128 cols = 1024 uint4; 4 per thread
    int trow[4], tcol[4];
    #pragma unroll
    for (int i = 0; i < 4; i++) {
        int f = tid + i * 256;
        trow[i] = f >> 4;
        tcol[i] = (f & 15) * 8;
    }

    const int nkt = 2 * qt + 2;

    // prologue: cp.async tile 0 into stage 0
    {
        const __half* kb = k + kvh * HD;
        const __half* vb = v + kvh * HD;
        #pragma unroll
        for (int i = 0; i < 4; i++) {
            uint32_t so = (uint32_t)trow[i] * (AQ_STR * 2) + (uint32_t)tcol[i] * 2;
            asm volatile("cp.async.cg.shared.global [%0], [%1], 16;"
                         :: "r"(sK + so), "l"(kb + (size_t)trow[i] * KVDIM + tcol[i]) : "memory");
            asm volatile("cp.async.cg.shared.global [%0], [%1], 16;"
                         :: "r"(sV + so), "l"(vb + (size_t)trow[i] * KVDIM + tcol[i]) : "memory");
        }
        asm volatile("cp.async.commit_group;" ::: "memory");
    }

    // load Q tile (128 rows)
    {
        const __half* qbase = q + (size_t)(qt * 128) * HID + h * HD;
        #pragma unroll
        for (int i = 0; i < 8; i++) {
            int f = tid + i * 256;
            int r = f >> 4;
            int c = (f & 15) * 8;
            *(uint4*)&Qh[r * AQ_STR + c] = *(const uint4*)(qbase + (size_t)r * HID + c);
        }
    }

    float out[16][4];
    #pragma unroll
    for (int ni = 0; ni < 16; ni++)
        #pragma unroll
        for (int j = 0; j < 4; j++) out[ni][j] = 0.f;
    float m0 = -INFINITY, m1 = -INFINITY, l0 = 0.f, l1 = 0.f;

    // scale * log2(e): softmax runs in log2 domain, exp2f = bare MUFU.EX2
    const float scale_l2e = 0.12751741958f;         // (1/sqrt(128)) * log2(e)
    const float mask_l2e  = -1.4426950e9f;          // -1e9 * log2(e)

    for (int kt = 0; kt < nkt; kt++) {
        asm volatile("cp.async.wait_group 0;" ::: "memory");
        __syncthreads();

        // issue next tile into the other stage (overlaps compute below)
        if (kt + 1 < nkt) {
            const uint32_t stoff = (uint32_t)((kt + 1) & 1) * (64 * AQ_STR * 2);
            const __half* kb = k + (size_t)((kt + 1) * 64) * KVDIM + kvh * HD;
            const __half* vb = v + (size_t)((kt + 1) * 64) * KVDIM + kvh * HD;
            #pragma unroll
            for (int i = 0; i < 4; i++) {
                uint32_t so = (uint32_t)trow[i] * (AQ_STR * 2) + (uint32_t)tcol[i] * 2 + stoff;
                asm volatile("cp.async.cg.shared.global [%0], [%1], 16;"
                             :: "r"(sK + so), "l"(kb + (size_t)trow[i] * KVDIM + tcol[i]) : "memory");
                asm volatile("cp.async.cg.shared.global [%0], [%1], 16;"
                             :: "r"(sV + so), "l"(vb + (size_t)trow[i] * KVDIM + tcol[i]) : "memory");
            }
            asm volatile("cp.async.commit_group;" ::: "memory");
        }

        const uint32_t kbuf = sK + (uint32_t)(kt & 1) * (64 * AQ_STR * 2);
        const uint32_t vbuf = sV + (uint32_t)(kt & 1) * (64 * AQ_STR * 2);

        // ---- S = Q @ K^T : sfrag[8] covers 64 keys ----
        float sfrag[8][4];
        #pragma unroll
        for (int ni = 0; ni < 8; ni++)
            #pragma unroll
            for (int j = 0; j < 4; j++) sfrag[ni][j] = 0.f;

        #pragma unroll
        for (int s = 0; s < 8; s++) {
            uint32_t a[4];
            {
                int row = wm + lr + (lg & 1) * 8;
                int ch  = s * 2 + (lg >> 1);
                ldm_x4(a, sQ + ((uint32_t)row * AQ_STR + (uint32_t)ch * 8) * 2u);
            }
            #pragma unroll
            for (int pr = 0; pr < 4; pr++) {
                uint32_t bq[4];
                int row = pr * 16 + lr + (lg >> 1) * 8;
                int ch  = s * 2 + (lg & 1);
                ldm_x4(bq, kbuf + ((uint32_t)row * AQ_STR + (uint32_t)ch * 8) * 2u);
                mma_f16(sfrag[pr * 2 + 0], a, &bq[0]);
                mma_f16(sfrag[pr * 2 + 1], a, &bq[2]);
            }
        }

        // ---- scale (log2 domain) + causal mask ----
        const bool diag = (kt >= 2 * qt);
        const int qr0 = qt * 128 + wm + qr;
        #pragma unroll
        for (int ni = 0; ni < 8; ni++) {
            const int kc = kt * 64 + ni * 8 + qc * 2;
            sfrag[ni][0] *= scale_l2e; sfrag[ni][1] *= scale_l2e;
            sfrag[ni][2] *= scale_l2e; sfrag[ni][3] *= scale_l2e;
            if (diag) {
                if (kc > qr0)         sfrag[ni][0] += mask_l2e;
                if (kc + 1 > qr0)     sfrag[ni][1] += mask_l2e;
                if (kc > qr0 + 8)     sfrag[ni][2] += mask_l2e;
                if (kc + 1 > qr0 + 8) sfrag[ni][3] += mask_l2e;
            }
        }

        // ---- row max (quad reduce) + rescale ----
        float mx0 = m0, mx1 = m1;
        #pragma unroll
        for (int ni = 0; ni < 8; ni++) {
            mx0 = fmaxf(mx0, fmaxf(sfrag[ni][0], sfrag[ni][1]));
            mx1 = fmaxf(mx1, fmaxf(sfrag[ni][2], sfrag[ni][3]));
        }
        mx0 = fmaxf(mx0, __shfl_xor_sync(0xffffffffu, mx0, 1));
        mx0 = fmaxf(mx0, __shfl_xor_sync(0xffffffffu, mx0, 2));
        mx1 = fmaxf(mx1, __shfl_xor_sync(0xffffffffu, mx1, 1));
        mx1 = fmaxf(mx1, __shfl_xor_sync(0xffffffffu, mx1, 2));
        const float al0 = exp2f(m0 - mx0);
        const float al1 = exp2f(m1 - mx1);
        m0 = mx0; m1 = mx1;
        #pragma unroll
        for (int ni = 0; ni < 16; ni++) {
            out[ni][0] *= al0; out[ni][1] *= al0;
            out[ni][2] *= al1; out[ni][3] *= al1;
        }

        // ---- exp2 -> P frags; PV interleaved per k16-step ----
        float sum0 = 0.f, sum1 = 0.f;
        #pragma unroll
        for (int s = 0; s < 4; s++) {
            float p00 = exp2f(sfrag[2*s][0]   - mx0), p01 = exp2f(sfrag[2*s][1]   - mx0);
            float p10 = exp2f(sfrag[2*s][2]   - mx1), p11 = exp2f(sfrag[2*s][3]   - mx1);
            float p20 = exp2f(sfrag[2*s+1][0] - mx0), p21 = exp2f(sfrag[2*s+1][1] - mx0);
            float p30 = exp2f(sfrag[2*s+1][2] - mx1), p31 = exp2f(sfrag[2*s+1][3] - mx1);
            sum0 += p00 + p01 + p20 + p21;
            sum1 += p10 + p11 + p30 + p31;
            uint32_t pf[4];
            pf[0] = h2_as_u32(__floats2half2_rn(p00, p01));
            pf[1] = h2_as_u32(__floats2half2_rn(p10, p11));
            pf[2] = h2_as_u32(__floats2half2_rn(p20, p21));
            pf[3] = h2_as_u32(__floats2half2_rn(p30, p31));
            #pragma unroll
            for (int nb = 0; nb < 8; nb++) {
                uint32_t bv[4];
                int row = s * 16 + (lg & 1) * 8 + lr;        // key row
                int col = nb * 16 + (lg >> 1) * 8;           // d col
                ldm_x4_t(bv, vbuf + ((uint32_t)row * AQ_STR + (uint32_t)col) * 2u);
                mma_f16(out[nb * 2 + 0], pf, &bv[0]);
                mma_f16(out[nb * 2 + 1], pf, &bv[2]);
            }
        }
        sum0 += __shfl_xor_sync(0xffffffffu, sum0, 1);
        sum0 += __shfl_xor_sync(0xffffffffu, sum0, 2);
        sum1 += __shfl_xor_sync(0xffffffffu, sum1, 1);
        sum1 += __shfl_xor_sync(0xffffffffu, sum1, 2);
        l0 = l0 * al0 + sum0;
        l1 = l1 * al1 + sum1;
    }

    // ---- epilogue ----
    {
        const float inv0 = 1.f / l0;
        const float inv1 = 1.f / l1;
        const int row0 = qt * 128 + wm + qr;
        #pragma unroll
        for (int ni = 0; ni < 16; ni++) {
            const int col = h * HD + ni * 8 + qc * 2;
            *(__half2*)(ctx + (size_t)row0 * HID + col) =
                __floats2half2_rn(out[ni][0] * inv0, out[ni][1] * inv0);
            *(__half2*)(ctx + (size_t)(row0 + 8) * HID + col) =
                __floats2half2_rn(out[ni][2] * inv1, out[ni][3] * inv1);
        }
    }
}

// ---------------- host launcher ----------------
extern "C" void kernel_launch(void* const* d_in, const int* in_sizes, int n_in,
                              void* d_out, int out_size)
{
    const float* hs = (const float*)d_in[0];
    const float* wq = (const float*)d_in[2];
    const float* bq = (const float*)d_in[3];
    const float* wk = (const float*)d_in[4];
    const float* bk = (const float*)d_in[5];
    const float* wv = (const float*)d_in[6];
    const float* bv = (const float*)d_in[7];
    const float* wo = (const float*)d_in[8];
    float* out = (float*)d_out;

    float *q, *k, *cosd, *sind;
    __half *qh, *kh, *vh, *ctx_h, *hs_h, *wq_h, *wk_h, *wv_h, *wo_h;
    cudaGetSymbolAddress((void**)&q,     g_q);
    cudaGetSymbolAddress((void**)&k,     g_k);
    cudaGetSymbolAddress((void**)&qh,    g_qh);
    cudaGetSymbolAddress((void**)&kh,    g_kh);
    cudaGetSymbolAddress((void**)&vh,    g_vh);
    cudaGetSymbolAddress((void**)&ctx_h, g_ctx_h);
    cudaGetSymbolAddress((void**)&hs_h,  g_hs_h);
    cudaGetSymbolAddress((void**)&wq_h,  g_wq_h);
    cudaGetSymbolAddress((void**)&wk_h,  g_wk_h);
    cudaGetSymbolAddress((void**)&wv_h,  g_wv_h);
    cudaGetSymbolAddress((void**)&wo_h,  g_wo_h);
    cudaGetSymbolAddress((void**)&cosd,  g_cos);
    cudaGetSymbolAddress((void**)&sind,  g_sin);

    // conversions needed by gemm_qkv, then rope tables (launch #6 = gemm_qkv for ncu -s 5)
    cvt_half<<<SEQ * HID / 4 / 1024,   256>>>(hs, hs_h, SEQ * HID / 4);
    cvt_half<<<HID * HID / 4 / 1024,   256>>>(wq, wq_h, HID * HID / 4);
    cvt_half<<<KVDIM * HID / 4 / 1024, 256>>>(wk, wk_h, KVDIM * HID / 4);
    cvt_half<<<KVDIM * HID / 4 / 1024, 256>>>(wv, wv_h, KVDIM * HID / 4);
    rope_tables<<<(SEQ * 64) / 256, 256>>>(cosd, sind);

    cudaFuncSetAttribute(gemm_qkv, cudaFuncAttributeMaxDynamicSharedMemorySize, GEMM_SMEM_BYTES);
    cudaFuncSetAttribute(gemm_f16, cudaFuncAttributeMaxDynamicSharedMemorySize, GEMM_SMEM_BYTES);

    // fused Q/K/V projection (V written directly as fp16)
    gemm_qkv<<<dim3((HID + 2 * KVDIM) / 128, SEQ / 128), 256, GEMM_SMEM_BYTES>>>(
        hs_h, wq_h, wk_h, wv_h, bq, bk, bv, q, k, vh);

    // rope (vectorized; fp32 math, single rounding to half)
    rope_apply<<<(SEQ * NH  * 16) / 256, 256>>>(q, qh, cosd, sind, NH);
    rope_apply<<<(SEQ * NKV * 16) / 256, 256>>>(k, kh, cosd, sind, NKV);

    // wo conversion (only needed before final gemm)
    cvt_half<<<HID * HID / 4 / 1024, 256>>>(wo, wo_h, HID * HID / 4);

    // attention (FA2, in-register log2-domain softmax, LPT block order)
    cudaFuncSetAttribute(attn_f16, cudaFuncAttributeMaxDynamicSharedMemorySize, ATTN_SMEM_BYTES);
    attn_f16<<<(SEQ / 128) * NH, 256, ATTN_SMEM_BYTES>>>(qh, kh, vh, ctx_h);

    // output projection
    gemm_f16<<<dim3(HID / 128, SEQ / 128), 256, GEMM_SMEM_BYTES>>>(
        ctx_h, wo_h, nullptr, out, SEQ, HID, HID);
}

// round 13
// speedup vs baseline: 10.0192x; 1.1329x over previous
#include <cuda_runtime.h>
#include <cuda_fp16.h>
#include <math.h>
#include <stdint.h>

#define SEQ   2048
#define HID   3584
#define NH    28
#define NKV   4
#define HD    128
#define KVDIM 512   // NKV * HD

// ---------------- scratch (no allocations allowed) ----------------
__device__ float  g_q[SEQ * HID];
__device__ float  g_k[SEQ * KVDIM];
__device__ __half g_qh[SEQ * HID];
__device__ __half g_kh[SEQ * KVDIM];
__device__ __half g_vh[SEQ * KVDIM];
__device__ __half g_ctx_h[SEQ * HID];
__device__ __half g_hs_h[SEQ * HID];
__device__ __half g_wq_h[(size_t)HID * HID];
__device__ __half g_wk_h[(size_t)KVDIM * HID];
__device__ __half g_wv_h[(size_t)KVDIM * HID];
__device__ __half g_wo_h[(size_t)HID * HID];
__device__ float  g_cos[SEQ * 64];
__device__ float  g_sin[SEQ * 64];

// ---------------- helpers ----------------
__device__ __forceinline__ uint32_t smem_u32(const void* p) {
    uint32_t a;
    asm("{ .reg .u64 t; cvta.to.shared.u64 t, %1; cvt.u32.u64 %0, t; }" : "=r"(a) : "l"(p));
    return a;
}

__device__ __forceinline__ uint32_t h2_as_u32(__half2 h) {
    return *reinterpret_cast<uint32_t*>(&h);
}

__device__ __forceinline__ void mma_f16(float* c, const uint32_t* a, const uint32_t* b) {
    asm volatile(
        "mma.sync.aligned.m16n8k16.row.col.f32.f16.f16.f32 "
        "{%0,%1,%2,%3}, {%4,%5,%6,%7}, {%8,%9}, {%0,%1,%2,%3};\n"
        : "+f"(c[0]), "+f"(c[1]), "+f"(c[2]), "+f"(c[3])
        : "r"(a[0]), "r"(a[1]), "r"(a[2]), "r"(a[3]), "r"(b[0]), "r"(b[1]));
}

__device__ __forceinline__ void ldm_x4(uint32_t* r, uint32_t addr) {
    asm volatile("ldmatrix.sync.aligned.m8n8.x4.shared.b16 {%0,%1,%2,%3}, [%4];"
                 : "=r"(r[0]), "=r"(r[1]), "=r"(r[2]), "=r"(r[3]) : "r"(addr));
}

__device__ __forceinline__ void ldm_x4_t(uint32_t* r, uint32_t addr) {
    asm volatile("ldmatrix.sync.aligned.m8n8.x4.trans.shared.b16 {%0,%1,%2,%3}, [%4];"
                 : "=r"(r[0]), "=r"(r[1]), "=r"(r[2]), "=r"(r[3]) : "r"(addr));
}

// ---------------- fp32 -> fp16 conversion, 4 float4/thread (MLP=4) --------
// n4 MUST be a multiple of 1024 (all call sites are).
__global__ void cvt_half(const float* __restrict__ in, __half* __restrict__ out, int n4) {
    const int i0 = blockIdx.x * 1024 + threadIdx.x;
    float4 v[4];
    #pragma unroll
    for (int j = 0; j < 4; j++) v[j] = ((const float4*)in)[i0 + j * 256];
    #pragma unroll
    for (int j = 0; j < 4; j++) {
        const int i = i0 + j * 256;
        ((__half2*)out)[i * 2 + 0] = __floats2half2_rn(v[j].x, v[j].y);
        ((__half2*)out)[i * 2 + 1] = __floats2half2_rn(v[j].z, v[j].w);
    }
}

// ---------------- FP16 GEMM body: BK=64, 2-stage cp.async, 1 sync/iter -----
// Row stride 72 halves (144B = 9x16B, odd -> ldmatrix conflict-free).
#define GSTRIDE 72
#define GTILE_H (128 * GSTRIDE)   // 9216 halves per stage
#define GSTAGES 2
#define GEMM_SMEM_BYTES (2 * GSTAGES * GTILE_H * 2)   // 73728 B

__device__ __forceinline__ void gemm_body(
    const __half* __restrict__ A, const __half* __restrict__ W,
    const float* __restrict__ bias, float* __restrict__ Cf, __half* __restrict__ Ch,
    int N, int K, int bm, int bn, __half* As, __half* Bs)
{
    const int tid  = threadIdx.x;
    const int lane = tid & 31;
    const int wid  = tid >> 5;

    const int warp_m = (wid >> 1) * 32;
    const int warp_n = (wid & 1) * 64;

    const uint32_t sbA = smem_u32(As);
    const uint32_t sbB = smem_u32(Bs);

    // cp.async mapping: 128 rows x 8 chunks (16B) per operand per stage; 4/thread
    int lrow[4], lch[4];
    #pragma unroll
    for (int p = 0; p < 4; p++) {
        int f = tid + p * 256;
        lrow[p] = f >> 3;
        lch[p]  = f & 7;
    }

    const int nt = K / 64;

    // prologue: stage 0
    #pragma unroll
    for (int p = 0; p < 4; p++) {
        uint32_t so = (uint32_t)lrow[p] * 144u + (uint32_t)lch[p] * 16u;
        const __half* ga = A + (size_t)(bm + lrow[p]) * K + lch[p] * 8;
        const __half* gb = W + (size_t)(bn + lrow[p]) * K + lch[p] * 8;
        asm volatile("cp.async.cg.shared.global [%0], [%1], 16;" :: "r"(sbA + so), "l"(ga) : "memory");
        asm volatile("cp.async.cg.shared.global [%0], [%1], 16;" :: "r"(sbB + so), "l"(gb) : "memory");
    }
    asm volatile("cp.async.commit_group;" ::: "memory");

    float acc[2][8][4];
    #pragma unroll
    for (int mi = 0; mi < 2; mi++)
        #pragma unroll
        for (int ni = 0; ni < 8; ni++)
            #pragma unroll
            for (int j = 0; j < 4; j++) acc[mi][ni][j] = 0.f;

    const int lg = lane >> 3;
    const int lr = lane & 7;

    for (int i = 0; i < nt; i++) {
        asm volatile("cp.async.wait_group 0;" ::: "memory");   // chunk i resident
        __syncthreads();                                       // prior reads of buf (i+1)&1 done

        // issue chunk i+1 into the other stage (overlaps compute below)
        if (i + 1 < nt) {
            const uint32_t ab = sbA + (uint32_t)((i + 1) & 1) * (GTILE_H * 2);
            const uint32_t bb = sbB + (uint32_t)((i + 1) & 1) * (GTILE_H * 2);
            #pragma unroll
            for (int p = 0; p < 4; p++) {
                uint32_t so = (uint32_t)lrow[p] * 144u + (uint32_t)lch[p] * 16u;
                const __half* ga = A + (size_t)(bm + lrow[p]) * K + (size_t)(i + 1) * 64 + lch[p] * 8;
                const __half* gb = W + (size_t)(bn + lrow[p]) * K + (size_t)(i + 1) * 64 + lch[p] * 8;
                asm volatile("cp.async.cg.shared.global [%0], [%1], 16;" :: "r"(ab + so), "l"(ga) : "memory");
                asm volatile("cp.async.cg.shared.global [%0], [%1], 16;" :: "r"(bb + so), "l"(gb) : "memory");
            }
            asm volatile("cp.async.commit_group;" ::: "memory");
        }

        const uint32_t abuf = sbA + (uint32_t)(i & 1) * (GTILE_H * 2);
        const uint32_t bbuf = sbB + (uint32_t)(i & 1) * (GTILE_H * 2);

        #pragma unroll
        for (int s = 0; s < 4; s++) {          // 4 k16-steps per 64-half chunk
            uint32_t a[2][4], bq[4][4];
            #pragma unroll
            for (int mi = 0; mi < 2; mi++) {
                int row = warp_m + mi * 16 + lr + (lg & 1) * 8;
                int ch  = s * 2 + (lg >> 1);
                ldm_x4(a[mi], abuf + (uint32_t)row * 144u + (uint32_t)ch * 16u);
            }
            #pragma unroll
            for (int pr = 0; pr < 4; pr++) {
                int row = warp_n + pr * 16 + lr + (lg >> 1) * 8;
                int ch  = s * 2 + (lg & 1);
                ldm_x4(bq[pr], bbuf + (uint32_t)row * 144u + (uint32_t)ch * 16u);
            }
            #pragma unroll
            for (int mi = 0; mi < 2; mi++)
                #pragma unroll
                for (int pr = 0; pr < 4; pr++) {
                    mma_f16(acc[mi][pr * 2 + 0], a[mi], &bq[pr][0]);
                    mma_f16(acc[mi][pr * 2 + 1], a[mi], &bq[pr][2]);
                }
        }
    }

    #pragma unroll
    for (int ni = 0; ni < 8; ni++) {
        const int col = bn + warp_n + ni * 8 + (lane & 3) * 2;
        float b0 = 0.f, b1 = 0.f;
        if (bias) { b0 = bias[col]; b1 = bias[col + 1]; }
        #pragma unroll
        for (int mi = 0; mi < 2; mi++) {
            const int row = bm + warp_m + mi * 16 + (lane >> 2);
            if (Ch) {
                *(__half2*)(Ch + (size_t)row * N + col) =
                    __floats2half2_rn(acc[mi][ni][0] + b0, acc[mi][ni][1] + b1);
                *(__half2*)(Ch + (size_t)(row + 8) * N + col) =
                    __floats2half2_rn(acc[mi][ni][2] + b0, acc[mi][ni][3] + b1);
            } else {
                float2 v0 = make_float2(acc[mi][ni][0] + b0, acc[mi][ni][1] + b1);
                float2 v1 = make_float2(acc[mi][ni][2] + b0, acc[mi][ni][3] + b1);
                *(float2*)(Cf + (size_t)row * N + col) = v0;
                *(float2*)(Cf + (size_t)(row + 8) * N + col) = v1;
            }
        }
    }
}

// generic GEMM (O-projection, fp32 out)
__global__ __launch_bounds__(256, 2) void gemm_f16(
    const __half* __restrict__ A, const __half* __restrict__ W,
    const float* __restrict__ bias, float* __restrict__ C,
    int M, int N, int K)
{
    extern __shared__ __align__(16) __half gsh[];
    gemm_body(A, W, bias, C, (__half*)0, N, K, blockIdx.y * 128, blockIdx.x * 128,
              gsh, gsh + GSTAGES * GTILE_H);
}

// fused Q/K/V projection: 36 block-cols; V written directly as fp16
__global__ __launch_bounds__(256, 2) void gemm_qkv(
    const __half* __restrict__ A,
    const __half* __restrict__ wq, const __half* __restrict__ wk, const __half* __restrict__ wv,
    const float* __restrict__ bq, const float* __restrict__ bk, const float* __restrict__ bv,
    float* __restrict__ q, float* __restrict__ k, __half* __restrict__ vh)
{
    extern __shared__ __align__(16) __half gsh[];
    const int bx = blockIdx.x;
    const __half* W; const float* bias; float* Cf; __half* Ch; int N, bn;
    if (bx < HID / 128) {
        W = wq; bias = bq; Cf = q; Ch = 0; N = HID; bn = bx * 128;
    } else if (bx < HID / 128 + KVDIM / 128) {
        W = wk; bias = bk; Cf = k; Ch = 0; N = KVDIM; bn = (bx - HID / 128) * 128;
    } else {
        W = wv; bias = bv; Cf = 0; Ch = vh; N = KVDIM; bn = (bx - HID / 128 - KVDIM / 128) * 128;
    }
    gemm_body(A, W, bias, Cf, Ch, N, HID, blockIdx.y * 128, bn,
              gsh, gsh + GSTAGES * GTILE_H);
}

// ---------------- RoPE tables + apply (vectorized, 4 dims/thread) ----------
__global__ void rope_tables(float* __restrict__ cosd, float* __restrict__ sind) {
    int i = blockIdx.x * blockDim.x + threadIdx.x;
    int half = i & 63;
    int s = i >> 6;
    double inv = exp(-log(1.0e6) * (double)(2 * half) / 128.0);
    double ang = (double)s * inv;
    cosd[i] = (float)cos(ang);
    sind[i] = (float)sin(ang);
}

// one thread handles 4 consecutive dims of one (s, h) row: float4 in, half2 out
__global__ void rope_apply(const float* __restrict__ x, __half* __restrict__ xh,
                           const float* __restrict__ cosd, const float* __restrict__ sind,
                           int nheads)
{
    int idx = blockIdx.x * blockDim.x + threadIdx.x;   // SEQ*nheads*16 threads
    int d4 = (idx & 15) << 2;           // 0,4,...,60
    int h  = (idx >> 4) % nheads;
    int s  = idx / (16 * nheads);

    float4 c  = *(const float4*)&cosd[s * 64 + d4];
    float4 si = *(const float4*)&sind[s * 64 + d4];

    const float* base = x + (size_t)s * nheads * HD + h * HD;
    __half* baseh = xh + (size_t)s * nheads * HD + h * HD;
    float4 x1 = *(const float4*)&base[d4];
    float4 x2 = *(const float4*)&base[d4 + 64];

    *(__half2*)&baseh[d4]          = __floats2half2_rn(x1.x * c.x - x2.x * si.x,
                                                       x1.y * c.y - x2.y * si.y);
    *(__half2*)&baseh[d4 + 2]      = __floats2half2_rn(x1.z * c.z - x2.z * si.z,
                                                       x1.w * c.w - x2.w * si.w);
    *(__half2*)&baseh[d4 + 64]     = __floats2half2_rn(x2.x * c.x + x1.x * si.x,
                                                       x2.y * c.y + x1.y * si.y);
    *(__half2*)&baseh[d4 + 64 + 2] = __floats2half2_rn(x2.z * c.z + x1.z * si.z,
                                                       x2.w * c.w + x1.w * si.w);
}

// ---------------- Flash attention (FA2): 128q block, warp = 16q x 64k ------
// 1-D grid in strict LPT order. Softmax in log2 domain (exp2f, scale folded).
#define AQ_STR 136
#define ATTN_SMEM_BYTES ((128 * AQ_STR + 4 * 64 * AQ_STR) * 2)

__global__ __launch_bounds__(256, 2) void attn_f16(
    const __half* __restrict__ q, const __half* __restrict__ k,
    const __half* __restrict__ v, __half* __restrict__ ctx)
{
    extern __shared__ __align__(16) char smraw[];
    __half* Qh = (__half*)smraw;                    // [128][136]
    __half* Kh = Qh + 128 * AQ_STR;                 // [2][64][136]
    __half* Vh = Kh + 2 * 64 * AQ_STR;              // [2][64][136]

    const int b   = blockIdx.x;                     // 0..447, LPT order
    const int qt  = (SEQ / 128 - 1) - (b / NH);     // heaviest first across ALL heads
    const int h   = b % NH;
    const int kvh = h / 7;
    const int tid  = threadIdx.x;
    const int lane = tid & 31;
    const int wid  = tid >> 5;

    const int wm = wid * 16;                        // warp's q-row base
    const int lg = lane >> 3;
    const int lr = lane & 7;
    const int qr = lane >> 2;                       // row-in-slab (0..7)
    const int qc = lane & 3;

    const uint32_t sQ = smem_u32(Qh);
    const uint32_t sK = smem_u32(Kh);
    const uint32_t sV = smem_u32(Vh);

    // K/V cp.async mapping: 64 rows x 128 cols = 1024 uint4; 4 per thread
    int trow[4], tcol[4];
    #pragma unroll
    for (int i = 0; i < 4; i++) {
        int f = tid + i * 256;
        trow[i] = f >> 4;
        tcol[i] = (f & 15) * 8;
    }

    const int nkt = 2 * qt + 2;

    // prologue: cp.async tile 0 into stage 0
    {
        const __half* kb = k + kvh * HD;
        const __half* vb = v + kvh * HD;
        #pragma unroll
        for (int i = 0; i < 4; i++) {
            uint32_t so = (uint32_t)trow[i] * (AQ_STR * 2) + (uint32_t)tcol[i] * 2;
            asm volatile("cp.async.cg.shared.global [%0], [%1], 16;"
                         :: "r"(sK + so), "l"(kb + (size_t)trow[i] * KVDIM + tcol[i]) : "memory");
            asm volatile("cp.async.cg.shared.global [%0], [%1], 16;"
                         :: "r"(sV + so), "l"(vb + (size_t)trow[i] * KVDIM + tcol[i]) : "memory");
        }
        asm volatile("cp.async.commit_group;" ::: "memory");
    }

    // load Q tile (128 rows)
    {
        const __half* qbase = q + (size_t)(qt * 128) * HID + h * HD;
        #pragma unroll
        for (int i = 0; i < 8; i++) {
            int f = tid + i * 256;
            int r = f >> 4;
            int c = (f & 15) * 8;
            *(uint4*)&Qh[r * AQ_STR + c] = *(const uint4*)(qbase + (size_t)r * HID + c);
        }
    }

    float out[16][4];
    #pragma unroll
    for (int ni = 0; ni < 16; ni++)
        #pragma unroll
        for (int j = 0; j < 4; j++) out[ni][j] = 0.f;
    float m0 = -INFINITY, m1 = -INFINITY, l0 = 0.f, l1 = 0.f;

    // scale * log2(e): softmax runs in log2 domain, exp2f = bare MUFU.EX2
    const float scale_l2e = 0.12751741958f;         // (1/sqrt(128)) * log2(e)
    const float mask_l2e  = -1.4426950e9f;          // -1e9 * log2(e)

    for (int kt = 0; kt < nkt; kt++) {
        asm volatile("cp.async.wait_group 0;" ::: "memory");
        __syncthreads();

        // issue next tile into the other stage (overlaps compute below)
        if (kt + 1 < nkt) {
            const uint32_t stoff = (uint32_t)((kt + 1) & 1) * (64 * AQ_STR * 2);
            const __half* kb = k + (size_t)((kt + 1) * 64) * KVDIM + kvh * HD;
            const __half* vb = v + (size_t)((kt + 1) * 64) * KVDIM + kvh * HD;
            #pragma unroll
            for (int i = 0; i < 4; i++) {
                uint32_t so = (uint32_t)trow[i] * (AQ_STR * 2) + (uint32_t)tcol[i] * 2 + stoff;
                asm volatile("cp.async.cg.shared.global [%0], [%1], 16;"
                             :: "r"(sK + so), "l"(kb + (size_t)trow[i] * KVDIM + tcol[i]) : "memory");
                asm volatile("cp.async.cg.shared.global [%0], [%1], 16;"
                             :: "r"(sV + so), "l"(vb + (size_t)trow[i] * KVDIM + tcol[i]) : "memory");
            }
            asm volatile("cp.async.commit_group;" ::: "memory");
        }

        const uint32_t kbuf = sK + (uint32_t)(kt & 1) * (64 * AQ_STR * 2);
        const uint32_t vbuf = sV + (uint32_t)(kt & 1) * (64 * AQ_STR * 2);

        // ---- S = Q @ K^T : sfrag[8] covers 64 keys ----
        float sfrag[8][4];
        #pragma unroll
        for (int ni = 0; ni < 8; ni++)
            #pragma unroll
            for (int j = 0; j < 4; j++) sfrag[ni][j] = 0.f;

        #pragma unroll
        for (int s = 0; s < 8; s++) {
            uint32_t a[4];
            {
                int row = wm + lr + (lg & 1) * 8;
                int ch  = s * 2 + (lg >> 1);
                ldm_x4(a, sQ + ((uint32_t)row * AQ_STR + (uint32_t)ch * 8) * 2u);
            }
            #pragma unroll
            for (int pr = 0; pr < 4; pr++) {
                uint32_t bq[4];
                int row = pr * 16 + lr + (lg >> 1) * 8;
                int ch  = s * 2 + (lg & 1);
                ldm_x4(bq, kbuf + ((uint32_t)row * AQ_STR + (uint32_t)ch * 8) * 2u);
                mma_f16(sfrag[pr * 2 + 0], a, &bq[0]);
                mma_f16(sfrag[pr * 2 + 1], a, &bq[2]);
            }
        }

        // ---- scale (log2 domain) + causal mask ----
        const bool diag = (kt >= 2 * qt);
        const int qr0 = qt * 128 + wm + qr;
        #pragma unroll
        for (int ni = 0; ni < 8; ni++) {
            const int kc = kt * 64 + ni * 8 + qc * 2;
            sfrag[ni][0] *= scale_l2e; sfrag[ni][1] *= scale_l2e;
            sfrag[ni][2] *= scale_l2e; sfrag[ni][3] *= scale_l2e;
            if (diag) {
                if (kc > qr0)         sfrag[ni][0] += mask_l2e;
                if (kc + 1 > qr0)     sfrag[ni][1] += mask_l2e;
                if (kc > qr0 + 8)     sfrag[ni][2] += mask_l2e;
                if (kc + 1 > qr0 + 8) sfrag[ni][3] += mask_l2e;
            }
        }

        // ---- row max (quad reduce) + rescale ----
        float mx0 = m0, mx1 = m1;
        #pragma unroll
        for (int ni = 0; ni < 8; ni++) {
            mx0 = fmaxf(mx0, fmaxf(sfrag[ni][0], sfrag[ni][1]));
            mx1 = fmaxf(mx1, fmaxf(sfrag[ni][2], sfrag[ni][3]));
        }
        mx0 = fmaxf(mx0, __shfl_xor_sync(0xffffffffu, mx0, 1));
        mx0 = fmaxf(mx0, __shfl_xor_sync(0xffffffffu, mx0, 2));
        mx1 = fmaxf(mx1, __shfl_xor_sync(0xffffffffu, mx1, 1));
        mx1 = fmaxf(mx1, __shfl_xor_sync(0xffffffffu, mx1, 2));
        const float al0 = exp2f(m0 - mx0);
        const float al1 = exp2f(m1 - mx1);
        m0 = mx0; m1 = mx1;
        #pragma unroll
        for (int ni = 0; ni < 16; ni++) {
            out[ni][0] *= al0; out[ni][1] *= al0;
            out[ni][2] *= al1; out[ni][3] *= al1;
        }

        // ---- exp2 -> P frags; PV interleaved per k16-step ----
        float sum0 = 0.f, sum1 = 0.f;
        #pragma unroll
        for (int s = 0; s < 4; s++) {
            float p00 = exp2f(sfrag[2*s][0]   - mx0), p01 = exp2f(sfrag[2*s][1]   - mx0);
            float p10 = exp2f(sfrag[2*s][2]   - mx1), p11 = exp2f(sfrag[2*s][3]   - mx1);
            float p20 = exp2f(sfrag[2*s+1][0] - mx0), p21 = exp2f(sfrag[2*s+1][1] - mx0);
            float p30 = exp2f(sfrag[2*s+1][2] - mx1), p31 = exp2f(sfrag[2*s+1][3] - mx1);
            sum0 += p00 + p01 + p20 + p21;
            sum1 += p10 + p11 + p30 + p31;
            uint32_t pf[4];
            pf[0] = h2_as_u32(__floats2half2_rn(p00, p01));
            pf[1] = h2_as_u32(__floats2half2_rn(p10, p11));
            pf[2] = h2_as_u32(__floats2half2_rn(p20, p21));
            pf[3] = h2_as_u32(__floats2half2_rn(p30, p31));
            #pragma unroll
            for (int nb = 0; nb < 8; nb++) {
                uint32_t bv[4];
                int row = s * 16 + (lg & 1) * 8 + lr;        // key row
                int col = nb * 16 + (lg >> 1) * 8;           // d col
                ldm_x4_t(bv, vbuf + ((uint32_t)row * AQ_STR + (uint32_t)col) * 2u);
                mma_f16(out[nb * 2 + 0], pf, &bv[0]);
                mma_f16(out[nb * 2 + 1], pf, &bv[2]);
            }
        }
        sum0 += __shfl_xor_sync(0xffffffffu, sum0, 1);
        sum0 += __shfl_xor_sync(0xffffffffu, sum0, 2);
        sum1 += __shfl_xor_sync(0xffffffffu, sum1, 1);
        sum1 += __shfl_xor_sync(0xffffffffu, sum1, 2);
        l0 = l0 * al0 + sum0;
        l1 = l1 * al1 + sum1;
    }

    // ---- epilogue ----
    {
        const float inv0 = 1.f / l0;
        const float inv1 = 1.f / l1;
        const int row0 = qt * 128 + wm + qr;
        #pragma unroll
        for (int ni = 0; ni < 16; ni++) {
            const int col = h * HD + ni * 8 + qc * 2;
            *(__half2*)(ctx + (size_t)row0 * HID + col) =
                __floats2half2_rn(out[ni][0] * inv0, out[ni][1] * inv0);
            *(__half2*)(ctx + (size_t)(row0 + 8) * HID + col) =
                __floats2half2_rn(out[ni][2] * inv1, out[ni][3] * inv1);
        }
    }
}

// ---------------- host launcher ----------------
extern "C" void kernel_launch(void* const* d_in, const int* in_sizes, int n_in,
                              void* d_out, int out_size)
{
    const float* hs = (const float*)d_in[0];
    const float* wq = (const float*)d_in[2];
    const float* bq = (const float*)d_in[3];
    const float* wk = (const float*)d_in[4];
    const float* bk = (const float*)d_in[5];
    const float* wv = (const float*)d_in[6];
    const float* bv = (const float*)d_in[7];
    const float* wo = (const float*)d_in[8];
    float* out = (float*)d_out;

    float *q, *k, *cosd, *sind;
    __half *qh, *kh, *vh, *ctx_h, *hs_h, *wq_h, *wk_h, *wv_h, *wo_h;
    cudaGetSymbolAddress((void**)&q,     g_q);
    cudaGetSymbolAddress((void**)&k,     g_k);
    cudaGetSymbolAddress((void**)&qh,    g_qh);
    cudaGetSymbolAddress((void**)&kh,    g_kh);
    cudaGetSymbolAddress((void**)&vh,    g_vh);
    cudaGetSymbolAddress((void**)&ctx_h, g_ctx_h);
    cudaGetSymbolAddress((void**)&hs_h,  g_hs_h);
    cudaGetSymbolAddress((void**)&wq_h,  g_wq_h);
    cudaGetSymbolAddress((void**)&wk_h,  g_wk_h);
    cudaGetSymbolAddress((void**)&wv_h,  g_wv_h);
    cudaGetSymbolAddress((void**)&wo_h,  g_wo_h);
    cudaGetSymbolAddress((void**)&cosd,  g_cos);
    cudaGetSymbolAddress((void**)&sind,  g_sin);

    // conversions needed by gemm_qkv, then rope tables
    cvt_half<<<SEQ * HID / 4 / 1024,   256>>>(hs, hs_h, SEQ * HID / 4);
    cvt_half<<<HID * HID / 4 / 1024,   256>>>(wq, wq_h, HID * HID / 4);
    cvt_half<<<KVDIM * HID / 4 / 1024, 256>>>(wk, wk_h, KVDIM * HID / 4);
    cvt_half<<<KVDIM * HID / 4 / 1024, 256>>>(wv, wv_h, KVDIM * HID / 4);
    rope_tables<<<(SEQ * 64) / 256, 256>>>(cosd, sind);

    cudaFuncSetAttribute(gemm_qkv, cudaFuncAttributeMaxDynamicSharedMemorySize, GEMM_SMEM_BYTES);
    cudaFuncSetAttribute(gemm_f16, cudaFuncAttributeMaxDynamicSharedMemorySize, GEMM_SMEM_BYTES);

    // fused Q/K/V projection (V written directly as fp16)
    gemm_qkv<<<dim3((HID + 2 * KVDIM) / 128, SEQ / 128), 256, GEMM_SMEM_BYTES>>>(
        hs_h, wq_h, wk_h, wv_h, bq, bk, bv, q, k, vh);

    // rope (vectorized; fp32 math, single rounding to half)
    rope_apply<<<(SEQ * NH  * 16) / 256, 256>>>(q, qh, cosd, sind, NH);
    rope_apply<<<(SEQ * NKV * 16) / 256, 256>>>(k, kh, cosd, sind, NKV);

    // wo conversion (only needed before final gemm)
    cvt_half<<<HID * HID / 4 / 1024, 256>>>(wo, wo_h, HID * HID / 4);

    // attention (FA2, in-register log2-domain softmax, LPT block order)
    cudaFuncSetAttribute(attn_f16, cudaFuncAttributeMaxDynamicSharedMemorySize, ATTN_SMEM_BYTES);
    attn_f16<<<(SEQ / 128) * NH, 256, ATTN_SMEM_BYTES>>>(qh, kh, vh, ctx_h);

    // output projection
    gemm_f16<<<dim3(HID / 128, SEQ / 128), 256, GEMM_SMEM_BYTES>>>(
        ctx_h, wo_h, nullptr, out, SEQ, HID, HID);
}